// round 3
// baseline (speedup 1.0000x reference)
#include <cuda_runtime.h>
#include <float.h>
#include <math.h>

#define CN 12288          // CODE_NUM
#define GD 128            // GRAPH
#define HD 128            // HIDDEN
#define AT 64             // ATT
#define KSPLIT 3

// ----------------- scratch (device globals; no allocation allowed) ---------
__device__ float g_Xq[CN * GD];     // gathered query-source rows (m23)
__device__ float g_Xc[CN * GD];     // gathered co_embeddings rows (m23)
__device__ float g_X1[CN * GD];     // gathered co_embeddings rows (m1)
__device__ float g_H1[CN * HD];     // gathered hidden rows (m1)
__device__ float g_GI[CN * 3 * HD]; // x @ W_ih^T + b_ih
__device__ float g_GH[CN * 3 * HD]; // h @ W_hh^T + b_hh
__device__ float g_Q[CN * AT];
__device__ float g_K[CN * AT];
__device__ float g_V[CN * HD];
__device__ float g_O3[KSPLIT * CN * HD];  // per-split O partials
__device__ float g_L3[KSPLIT * CN];       // per-split l partials
__device__ int   g_idx1[CN];
__device__ int   g_idx23[CN];       // row | (m2 << 30)
__device__ int   g_cnt[2];          // [0]=n1, [1]=n23
__device__ unsigned g_outacc[HD];   // ordered-uint float max accumulator
__device__ float g_tf[HD];          // time features

__device__ __forceinline__ unsigned ford(float f) {
    unsigned u = __float_as_uint(f);
    return (u & 0x80000000u) ? ~u : (u | 0x80000000u);
}
__device__ __forceinline__ float funord(unsigned u) {
    return (u & 0x80000000u) ? __uint_as_float(u ^ 0x80000000u)
                             : __uint_as_float(~u);
}

// packed fp32x2 FMA: d = a*b + d (elementwise on 2 packed floats)
__device__ __forceinline__ void ffma2(unsigned long long& d,
                                      unsigned long long a,
                                      unsigned long long b) {
    asm("fma.rn.f32x2 %0, %1, %2, %0;" : "+l"(d) : "l"(a), "l"(b));
}
__device__ __forceinline__ float hadd2(unsigned long long v) {
    float lo, hi;
    asm("mov.b64 {%0,%1}, %2;" : "=f"(lo), "=f"(hi) : "l"(v));
    return lo + hi;
}
__device__ __forceinline__ float2 unpk(unsigned long long v) {
    float2 r;
    asm("mov.b64 {%0,%1}, %2;" : "=f"(r.x), "=f"(r.y) : "l"(v));
    return r;
}

// ----------------- k_init: zero h_new region, init accumulators, tf --------
__global__ void k_init(float* __restrict__ outH, const float* __restrict__ interval,
                       const float* __restrict__ Wt, const float* __restrict__ bt) {
    int i = blockIdx.x * 512 + threadIdx.x;            // 768*512 = 393216 float4
    reinterpret_cast<float4*>(outH)[i] = make_float4(0.f, 0.f, 0.f, 0.f);
    if (blockIdx.x == 0) {
        int t = threadIdx.x;
        if (t < HD) {
            float xt = 1.0f / logf(interval[0] + 2.7182818284590452f);
            g_tf[t] = tanhf(xt * Wt[t] + bt[t]);
            g_outacc[t] = ford(-FLT_MAX);
        }
        if (t == 0) { g_cnt[0] = 0; g_cnt[1] = 0; }
    }
}

// ----------------- k_compact: build m1 / m23 index lists -------------------
__global__ void k_compact(const int* __restrict__ divided) {
    int row = blockIdx.x * 256 + threadIdx.x;
    if (row >= CN) return;
    int d0 = divided[row * 3 + 0];
    int d1 = divided[row * 3 + 1];
    int d2 = divided[row * 3 + 2];
    if (d0 > 0) {
        int pos = atomicAdd(&g_cnt[0], 1);
        g_idx1[pos] = row;
    }
    if (d1 > 0 || d2 > 0) {
        int pos = atomicAdd(&g_cnt[1], 1);
        g_idx23[pos] = row | ((d1 > 0) ? (1 << 30) : 0);
    }
}

// ----------------- k_gather: compact rows into dense scratch ---------------
__global__ void k_gather(const float* __restrict__ co, const float* __restrict__ no_,
                         const float* __restrict__ un, const float* __restrict__ hid) {
    int s = blockIdx.x * 2 + (threadIdx.x >> 7);
    int lane = threadIdx.x & 127;
    int n23 = g_cnt[1], n1 = g_cnt[0];
    if (s < n23) {
        int e = g_idx23[s];
        int row = e & 0x3FFFFFFF;
        const float* src = (e & (1 << 30)) ? no_ : un;
        g_Xq[s * GD + lane] = src[row * GD + lane];
        g_Xc[s * GD + lane] = co[row * GD + lane];
    }
    if (s < n1) {
        int row = g_idx1[s];
        g_X1[s * GD + lane] = co[row * GD + lane];
        g_H1[s * HD + lane] = hid[row * HD + lane];
    }
}

// ----------------- tiled GEMM: C[64,64] = A[64,128] @ W[64,128]^T + b ------
// k-packed FFMA2: A rows and W rows are both k-major, pairs come free.
#define GEMM_SMEM ((64 * 132 + 64 * 128) * 4)
__device__ __forceinline__ void gemm_tile(const float* __restrict__ A,
                                          const float* __restrict__ W,
                                          const float* __restrict__ bias,
                                          float* __restrict__ C,
                                          int M, int N, int row0, int col0,
                                          float* sm) {
    float* As = sm;              // [64 r][132] row-major (k-major rows)
    float* Ws = sm + 64 * 132;   // [64 c][128] rows, quad-XOR-swizzled
    int t = threadIdx.x;
    for (int i4 = t; i4 < 64 * 32; i4 += 256) {
        int r = i4 >> 5, k4 = i4 & 31;
        float4 v = make_float4(0.f, 0.f, 0.f, 0.f);
        if (row0 + r < M)
            v = reinterpret_cast<const float4*>(A + (size_t)(row0 + r) * 128)[k4];
        reinterpret_cast<float4*>(As + r * 132)[k4] = v;
    }
    for (int i4 = t; i4 < 64 * 32; i4 += 256) {
        int c = i4 >> 5, k4 = i4 & 31;
        float4 v = reinterpret_cast<const float4*>(W + (size_t)(col0 + c) * 128)[k4];
        *reinterpret_cast<float4*>(Ws + c * 128 + ((k4 ^ ((c >> 2) & 7)) << 2)) = v;
    }
    __syncthreads();
    int ty = t >> 4, tx = t & 15;
    unsigned long long acc[4][4] = {};
    const float* Ap = As + ty * 4 * 132;
    const float* Wp = Ws + tx * 4 * 128;
    int swz = tx & 7;
#pragma unroll
    for (int c4 = 0; c4 < 32; c4++) {
        ulonglong2 a2[4], w2[4];
#pragma unroll
        for (int i = 0; i < 4; i++)
            a2[i] = *reinterpret_cast<const ulonglong2*>(Ap + i * 132 + c4 * 4);
#pragma unroll
        for (int j = 0; j < 4; j++)
            w2[j] = *reinterpret_cast<const ulonglong2*>(Wp + j * 128 + ((c4 ^ swz) << 2));
#pragma unroll
        for (int i = 0; i < 4; i++)
#pragma unroll
            for (int j = 0; j < 4; j++) {
                ffma2(acc[i][j], a2[i].x, w2[j].x);
                ffma2(acc[i][j], a2[i].y, w2[j].y);
            }
    }
    float4 bz = *reinterpret_cast<const float4*>(bias + col0 + tx * 4);
#pragma unroll
    for (int i = 0; i < 4; i++) {
        int r = row0 + ty * 4 + i;
        if (r < M) {
            float4 o = make_float4(hadd2(acc[i][0]) + bz.x, hadd2(acc[i][1]) + bz.y,
                                   hadd2(acc[i][2]) + bz.z, hadd2(acc[i][3]) + bz.w);
            *reinterpret_cast<float4*>(C + (size_t)r * N + col0 + tx * 4) = o;
        }
    }
}

// GI/GH fused: y<6 -> GI col y, y>=6 -> GH col y-6
__global__ void k_gemm_g(const float* __restrict__ Wih, const float* __restrict__ Whh,
                         const float* __restrict__ bih, const float* __restrict__ bhh) {
    int M = g_cnt[0];
    int row0 = blockIdx.x * 64;
    if (row0 >= M) return;
    int y = blockIdx.y;
    const float* A = (y < 6) ? g_X1 : g_H1;
    const float* W = (y < 6) ? Wih : Whh;
    const float* b = (y < 6) ? bih : bhh;
    float* C       = (y < 6) ? g_GI : g_GH;
    int col0 = (y % 6) * 64;
    extern __shared__ float sm[];
    gemm_tile(A, W, b, C, M, 384, row0, col0, sm);
}

// Q/K/V fused: y=0 Q, y=1 K, y=2,3 V halves
__global__ void k_gemm_qkv(const float* __restrict__ Wq, const float* __restrict__ bq,
                           const float* __restrict__ Wk, const float* __restrict__ bk,
                           const float* __restrict__ Wv, const float* __restrict__ bv) {
    int M = g_cnt[1];
    int row0 = blockIdx.x * 64;
    if (row0 >= M) return;
    int y = blockIdx.y;
    const float *A, *W, *b; float* C; int N, col0;
    if (y == 0)      { A = g_Xq; W = Wq; b = bq; C = g_Q; N = 64;  col0 = 0; }
    else if (y == 1) { A = g_Xc; W = Wk; b = bk; C = g_K; N = 64;  col0 = 0; }
    else             { A = g_Xc; W = Wv; b = bv; C = g_V; N = 128; col0 = (y - 2) * 64; }
    extern __shared__ float sm[];
    gemm_tile(A, W, b, C, M, N, row0, col0, sm);
}

// ----------------- k_gruc: GRU gates + scatter h_new + column max ----------
__global__ void k_gruc(const float* __restrict__ hid, float* __restrict__ outH) {
    int n1 = g_cnt[0];
    int t = threadIdx.x;
    int c = t & 127, sub = t >> 7;
    int s0 = blockIdx.x * 8;
    float mx = -FLT_MAX;
#pragma unroll
    for (int k = 0; k < 4; k++) {
        int s = s0 + sub * 4 + k;
        if (s < n1) {
            int row = g_idx1[s];
            const float* gi = g_GI + (size_t)s * 384;
            const float* gh = g_GH + (size_t)s * 384;
            float r  = 1.f / (1.f + __expf(-(gi[c] + gh[c])));
            float z  = 1.f / (1.f + __expf(-(gi[128 + c] + gh[128 + c])));
            float nn = tanhf(gi[256 + c] + r * gh[256 + c]);
            float h  = hid[(size_t)row * 128 + c];
            float o  = (1.f - z) * nn + z * h;
            outH[(size_t)row * 128 + c] = o;
            mx = fmaxf(mx, o);
        }
    }
    __shared__ float red[2][128];
    red[sub][c] = mx;
    __syncthreads();
    if (t < 128) atomicMax(&g_outacc[t], ford(fmaxf(red[0][t], red[1][t])));
}

// ----------------- k_flash: FFMA2 no-rescale attention partials ------------
// Qs: [64 r][68] row-major (d-major).  Ks: [64 j][68] quad-swizzled by row>>2.
// Ps2: [64 j][128] duplicated P^T (p,p pairs), quad-swizzled by (row>>2)&7.
// Vs: [64 j][128] natural.
#define FLASH_SMEM ((2 * 64 * 68 + 2 * 64 * 128) * 4)
__global__ void __launch_bounds__(256, 2) k_flash() {
    int n23 = g_cnt[1];
    int qb = blockIdx.x / KSPLIT;
    int sp = blockIdx.x % KSPLIT;
    int q0 = qb * 64;
    if (q0 >= n23) return;
    extern __shared__ float sm[];
    float* Qs  = sm;                          // 64*68
    float* Ks  = sm + 64 * 68;                // 64*68
    float* Ps2 = sm + 2 * 64 * 68;            // 64*128
    float* Vs  = sm + 2 * 64 * 68 + 64 * 128; // 64*128
    int t = threadIdx.x;
    int ty = t >> 4, tx = t & 15;
    // load Q tile row-major, fold 1/sqrt(64) scale
    for (int i4 = t; i4 < 64 * 16; i4 += 256) {
        int r = i4 >> 4, d4 = i4 & 15;
        float4 v = make_float4(0.f, 0.f, 0.f, 0.f);
        if (q0 + r < n23)
            v = reinterpret_cast<const float4*>(g_Q + (size_t)(q0 + r) * AT)[d4];
        v.x *= 0.125f; v.y *= 0.125f; v.z *= 0.125f; v.w *= 0.125f;
        *reinterpret_cast<float4*>(Qs + r * 68 + d4 * 4) = v;
    }
    float l[4] = {0.f, 0.f, 0.f, 0.f};
    unsigned long long o2[4][4] = {};   // O packed over c-pairs

    int nkb = (n23 + 63) >> 6;
    int chunk = (nkb + KSPLIT - 1) / KSPLIT;
    int kb0 = sp * chunk;
    int kb1 = min(kb0 + chunk, nkb);
    const float* Qp = Qs + ty * 4 * 68;
    for (int kb = kb0; kb < kb1; kb++) {
        int k0 = kb << 6;
        __syncthreads();
        for (int i4 = t; i4 < 64 * 16; i4 += 256) {
            int j = i4 >> 4, d4 = i4 & 15;
            float4 v = make_float4(0.f, 0.f, 0.f, 0.f);
            if (k0 + j < n23)
                v = reinterpret_cast<const float4*>(g_K + (size_t)(k0 + j) * AT)[d4];
            *reinterpret_cast<float4*>(Ks + j * 68 + ((d4 ^ ((j >> 2) & 15)) << 2)) = v;
        }
        for (int i4 = t; i4 < 64 * 32; i4 += 256) {
            int j = i4 >> 5, d4 = i4 & 31;
            float4 v = make_float4(0.f, 0.f, 0.f, 0.f);
            if (k0 + j < n23)
                v = reinterpret_cast<const float4*>(g_V + (size_t)(k0 + j) * HD)[d4];
            reinterpret_cast<float4*>(Vs + j * 128)[d4] = v;
        }
        __syncthreads();
        // S = Qs K^T, d-packed FFMA2 (4x4 micro-tile)
        unsigned long long acc[4][4] = {};
        const float* Kp = Ks + tx * 4 * 68;
#pragma unroll
        for (int c4 = 0; c4 < 16; c4++) {
            ulonglong2 qa[4], kk[4];
#pragma unroll
            for (int i = 0; i < 4; i++)
                qa[i] = *reinterpret_cast<const ulonglong2*>(Qp + i * 68 + c4 * 4);
#pragma unroll
            for (int j = 0; j < 4; j++)
                kk[j] = *reinterpret_cast<const ulonglong2*>(Kp + j * 68 + (((c4 ^ tx) & 15) << 2));
#pragma unroll
            for (int i = 0; i < 4; i++)
#pragma unroll
                for (int j = 0; j < 4; j++) {
                    ffma2(acc[i][j], qa[i].x, kk[j].x);
                    ffma2(acc[i][j], qa[i].y, kk[j].y);
                }
        }
        // P = exp(S) with tail mask; accumulate l; write duplicated P^T
        int psw = tx & 7;
#pragma unroll
        for (int j = 0; j < 4; j++) {
            bool vj = (k0 + tx * 4 + j) < n23;
            float p0 = vj ? __expf(hadd2(acc[0][j])) : 0.f;
            float p1 = vj ? __expf(hadd2(acc[1][j])) : 0.f;
            float p2 = vj ? __expf(hadd2(acc[2][j])) : 0.f;
            float p3 = vj ? __expf(hadd2(acc[3][j])) : 0.f;
            l[0] += p0; l[1] += p1; l[2] += p2; l[3] += p3;
            float* prow = Ps2 + (tx * 4 + j) * 128;
            *reinterpret_cast<float4*>(prow + (((2 * ty) ^ psw) << 2)) =
                make_float4(p0, p0, p1, p1);
            *reinterpret_cast<float4*>(prow + (((2 * ty + 1) ^ psw) << 2)) =
                make_float4(p2, p2, p3, p3);
        }
        __syncthreads();
        // O += P V, c-packed FFMA2 (pre-duplicated P pairs)
#pragma unroll 4
        for (int j2 = 0; j2 < 64; j2++) {
            int sw = (j2 >> 2) & 7;
            const float* prow = Ps2 + j2 * 128;
            ulonglong2 pq0 = *reinterpret_cast<const ulonglong2*>(prow + (((2 * ty) ^ sw) << 2));
            ulonglong2 pq1 = *reinterpret_cast<const ulonglong2*>(prow + (((2 * ty + 1) ^ sw) << 2));
            ulonglong2 va = *reinterpret_cast<const ulonglong2*>(Vs + j2 * 128 + tx * 8);
            ulonglong2 vb = *reinterpret_cast<const ulonglong2*>(Vs + j2 * 128 + tx * 8 + 4);
            unsigned long long pd[4] = {pq0.x, pq0.y, pq1.x, pq1.y};
#pragma unroll
            for (int i = 0; i < 4; i++) {
                ffma2(o2[i][0], pd[i], va.x);
                ffma2(o2[i][1], pd[i], va.y);
                ffma2(o2[i][2], pd[i], vb.x);
                ffma2(o2[i][3], pd[i], vb.y);
            }
        }
    }
    __syncthreads();
    // epilogue: reduce l across tx, store O/l partials for this split
    float* lr = Ks;   // Ks no longer needed
#pragma unroll
    for (int i = 0; i < 4; i++) lr[(ty * 4 + i) * 16 + tx] = l[i];
    __syncthreads();
#pragma unroll
    for (int i = 0; i < 4; i++) {
        int slot = q0 + ty * 4 + i;
        if (slot >= n23) continue;
        float lt = 0.f;
#pragma unroll
        for (int x = 0; x < 16; x++) lt += lr[(ty * 4 + i) * 16 + x];
        if (tx == 0) g_L3[sp * CN + slot] = lt;
        float2 a0 = unpk(o2[i][0]), a1 = unpk(o2[i][1]);
        float2 a2 = unpk(o2[i][2]), a3 = unpk(o2[i][3]);
        float* dst = g_O3 + ((size_t)sp * CN + slot) * 128 + tx * 8;
        *reinterpret_cast<float4*>(dst)     = make_float4(a0.x, a0.y, a1.x, a1.y);
        *reinterpret_cast<float4*>(dst + 4) = make_float4(a2.x, a2.y, a3.x, a3.y);
    }
}

// ----------------- k_combine: sum splits, tanh, scatter, column max --------
__global__ void k_combine(float* __restrict__ outH) {
    int n23 = g_cnt[1];
    int t = threadIdx.x;
    int c = t & 127, sub = t >> 7;
    int s0 = blockIdx.x * 8;
    float mx = -FLT_MAX;
#pragma unroll
    for (int k = 0; k < 4; k++) {
        int sl = s0 + sub * 4 + k;
        if (sl < n23) {
            float lt = g_L3[sl] + g_L3[CN + sl] + g_L3[2 * CN + sl];
            float ov = g_O3[(size_t)sl * 128 + c]
                     + g_O3[((size_t)CN + sl) * 128 + c]
                     + g_O3[((size_t)2 * CN + sl) * 128 + c];
            float h = tanhf(ov / lt);
            int row = g_idx23[sl] & 0x3FFFFFFF;
            outH[(size_t)row * 128 + c] = h;
            mx = fmaxf(mx, h);
        }
    }
    __shared__ float red[2][128];
    red[sub][c] = mx;
    __syncthreads();
    if (t < 128) atomicMax(&g_outacc[t], ford(fmaxf(red[0][t], red[1][t])));
}

// ----------------- k_final: output vector --------------------------------
__global__ void k_final(float* __restrict__ out) {
    int t = threadIdx.x;
    out[t] = funord(g_outacc[t]) + g_tf[t];
}

// ---------------------------------------------------------------------------
extern "C" void kernel_launch(void* const* d_in, const int* in_sizes, int n_in,
                              void* d_out, int out_size) {
    const float* interval = (const float*)d_in[0];
    const float* co   = (const float*)d_in[1];
    const float* no_  = (const float*)d_in[2];
    const float* un   = (const float*)d_in[3];
    const float* hid  = (const float*)d_in[4];
    const int*   divided = (const int*)d_in[5];
    const float* W_ih = (const float*)d_in[6];
    const float* W_hh = (const float*)d_in[7];
    const float* b_ih = (const float*)d_in[8];
    const float* b_hh = (const float*)d_in[9];
    const float* Wq = (const float*)d_in[10];
    const float* bq = (const float*)d_in[11];
    const float* Wk = (const float*)d_in[12];
    const float* bk = (const float*)d_in[13];
    const float* Wv = (const float*)d_in[14];
    const float* bv = (const float*)d_in[15];
    const float* Wt = (const float*)d_in[16];
    const float* bt = (const float*)d_in[17];
    float* out  = (float*)d_out;
    float* outH = out + HD;   // h_new region: [12288, 128] after the 128-vec

    cudaFuncSetAttribute(k_gemm_g,   cudaFuncAttributeMaxDynamicSharedMemorySize, GEMM_SMEM);
    cudaFuncSetAttribute(k_gemm_qkv, cudaFuncAttributeMaxDynamicSharedMemorySize, GEMM_SMEM);
    cudaFuncSetAttribute(k_flash,    cudaFuncAttributeMaxDynamicSharedMemorySize, FLASH_SMEM);

    k_init<<<768, 512>>>(outH, interval, Wt, bt);
    k_compact<<<48, 256>>>(divided);
    k_gather<<<CN / 2, 256>>>(co, no_, un, hid);
    k_gemm_g<<<dim3(192, 12), 256, GEMM_SMEM>>>(W_ih, W_hh, b_ih, b_hh);
    k_gemm_qkv<<<dim3(192, 4), 256, GEMM_SMEM>>>(Wq, bq, Wk, bk, Wv, bv);
    k_gruc<<<CN / 8, 256>>>(hid, outH);
    k_flash<<<192 * KSPLIT, 256, FLASH_SMEM>>>();
    k_combine<<<CN / 8, 256>>>(outH);
    k_final<<<1, 128>>>(out);
}

// round 4
// speedup vs baseline: 1.2652x; 1.2652x over previous
#include <cuda_runtime.h>
#include <float.h>
#include <math.h>

#define CN 12288          // CODE_NUM
#define GD 128            // GRAPH
#define HD 128            // HIDDEN
#define AT 64             // ATT
#define KSPLIT 3

// ----------------- scratch (device globals; no allocation allowed) ---------
__device__ float g_Xq[CN * GD];     // gathered query-source rows (m23)
__device__ float g_Xc[CN * GD];     // gathered co_embeddings rows (m23)
__device__ float g_X1[CN * GD];     // gathered co_embeddings rows (m1)
__device__ float g_H1[CN * HD];     // gathered hidden rows (m1)
__device__ float g_GI[CN * 3 * HD]; // x @ W_ih^T + b_ih
__device__ float g_GH[CN * 3 * HD]; // h @ W_hh^T + b_hh
__device__ float g_Q[CN * AT];
__device__ float g_K[CN * AT];
__device__ float g_V[CN * HD];
__device__ float g_O3[KSPLIT * CN * HD];  // per-split O partials
__device__ float g_L3[KSPLIT * CN];       // per-split l partials
__device__ int   g_idx1[CN];
__device__ int   g_idx23[CN];       // row | (m2 << 30)
__device__ int   g_cnt[2];          // [0]=n1, [1]=n23
__device__ unsigned g_outacc[HD];   // ordered-uint float max accumulator
__device__ float g_tf[HD];          // time features

__device__ __forceinline__ unsigned ford(float f) {
    unsigned u = __float_as_uint(f);
    return (u & 0x80000000u) ? ~u : (u | 0x80000000u);
}
__device__ __forceinline__ float funord(unsigned u) {
    return (u & 0x80000000u) ? __uint_as_float(u ^ 0x80000000u)
                             : __uint_as_float(~u);
}

// FMA-pipe exp: exp(x) = 2^n * 2^f, n=rint(x*log2e), f in [-0.5,0.5].
// Degree-5 Taylor of 2^f (|f*ln2| <= 0.347 -> rel err ~3e-6).
// Avoids MUFU entirely (MUFU is the binding pipe in the flash loop).
__device__ __forceinline__ float exp_fast(float x) {
    float y = fmaf(x, 1.44269504f, 12582912.0f);      // y+magic (rounds)
    int   bz = __float_as_int(y);
    float n = y - 12582912.0f;                        // rint(x*log2e)
    float f = fmaf(x, 1.44269504f, -n);               // frac in [-0.5,0.5]
    float p = 0.0013333558f;
    p = fmaf(p, f, 0.0096181291f);
    p = fmaf(p, f, 0.0555041087f);
    p = fmaf(p, f, 0.2402265069f);
    p = fmaf(p, f, 0.6931471806f);
    p = fmaf(p, f, 1.0f);
    float sc = __int_as_float((bz + (127 - 0x4B400000)) << 23);  // 2^n
    return p * sc;
}

// ----------------- k_init: zero h_new region, init accumulators, tf --------
__global__ void k_init(float* __restrict__ outH, const float* __restrict__ interval,
                       const float* __restrict__ Wt, const float* __restrict__ bt) {
    int i = blockIdx.x * 512 + threadIdx.x;            // 768*512 = 393216 float4
    reinterpret_cast<float4*>(outH)[i] = make_float4(0.f, 0.f, 0.f, 0.f);
    if (blockIdx.x == 0) {
        int t = threadIdx.x;
        if (t < HD) {
            float xt = 1.0f / logf(interval[0] + 2.7182818284590452f);
            g_tf[t] = tanhf(xt * Wt[t] + bt[t]);
            g_outacc[t] = ford(-FLT_MAX);
        }
        if (t == 0) { g_cnt[0] = 0; g_cnt[1] = 0; }
    }
}

// ----------------- k_compact: build m1 / m23 index lists -------------------
__global__ void k_compact(const int* __restrict__ divided) {
    int row = blockIdx.x * 256 + threadIdx.x;
    if (row >= CN) return;
    int d0 = divided[row * 3 + 0];
    int d1 = divided[row * 3 + 1];
    int d2 = divided[row * 3 + 2];
    if (d0 > 0) {
        int pos = atomicAdd(&g_cnt[0], 1);
        g_idx1[pos] = row;
    }
    if (d1 > 0 || d2 > 0) {
        int pos = atomicAdd(&g_cnt[1], 1);
        g_idx23[pos] = row | ((d1 > 0) ? (1 << 30) : 0);
    }
}

// ----------------- k_gather: compact rows into dense scratch ---------------
__global__ void k_gather(const float* __restrict__ co, const float* __restrict__ no_,
                         const float* __restrict__ un, const float* __restrict__ hid) {
    int s = blockIdx.x * 2 + (threadIdx.x >> 7);
    int lane = threadIdx.x & 127;
    int n23 = g_cnt[1], n1 = g_cnt[0];
    if (s < n23) {
        int e = g_idx23[s];
        int row = e & 0x3FFFFFFF;
        const float* src = (e & (1 << 30)) ? no_ : un;
        g_Xq[s * GD + lane] = src[row * GD + lane];
        g_Xc[s * GD + lane] = co[row * GD + lane];
    }
    if (s < n1) {
        int row = g_idx1[s];
        g_X1[s * GD + lane] = co[row * GD + lane];
        g_H1[s * HD + lane] = hid[row * HD + lane];
    }
}

// ----------------- tiled GEMM body: C[64,64] = A[64,128] @ W[64,128]^T + b -
#define GEMM_SMEM ((64 * 132 + 128 * 68) * 4)
__device__ __forceinline__ void gemm_tile(const float* __restrict__ A,
                                          const float* __restrict__ W,
                                          const float* __restrict__ bias,
                                          float* __restrict__ C,
                                          int M, int N, int row0, int col0,
                                          float* sm) {
    float* As = sm;              // [64][132] row-major, padded
    float* Ws = sm + 64 * 132;   // [128][68]  Ws[k][c]
    int t = threadIdx.x;
    for (int i4 = t; i4 < 64 * 32; i4 += 256) {
        int r = i4 >> 5, k4 = i4 & 31;
        float4 v = make_float4(0.f, 0.f, 0.f, 0.f);
        if (row0 + r < M)
            v = reinterpret_cast<const float4*>(A + (size_t)(row0 + r) * 128)[k4];
        reinterpret_cast<float4*>(As + r * 132)[k4] = v;
    }
    for (int i4 = t; i4 < 64 * 32; i4 += 256) {
        int c = i4 >> 5, k4 = i4 & 31;
        float4 v = reinterpret_cast<const float4*>(W + (size_t)(col0 + c) * 128)[k4];
        Ws[(k4 * 4 + 0) * 68 + c] = v.x;
        Ws[(k4 * 4 + 1) * 68 + c] = v.y;
        Ws[(k4 * 4 + 2) * 68 + c] = v.z;
        Ws[(k4 * 4 + 3) * 68 + c] = v.w;
    }
    __syncthreads();
    int ty = t >> 4, tx = t & 15;
    float acc[4][4] = {};
    const float* Ap = As + ty * 4 * 132;
#pragma unroll 8
    for (int k = 0; k < 128; k++) {
        float a[4];
        a[0] = Ap[k]; a[1] = Ap[132 + k]; a[2] = Ap[264 + k]; a[3] = Ap[396 + k];
        float4 b4 = *reinterpret_cast<const float4*>(Ws + k * 68 + tx * 4);
        float b[4] = {b4.x, b4.y, b4.z, b4.w};
#pragma unroll
        for (int i = 0; i < 4; i++)
#pragma unroll
            for (int j = 0; j < 4; j++) acc[i][j] += a[i] * b[j];
    }
    float4 bz = *reinterpret_cast<const float4*>(bias + col0 + tx * 4);
#pragma unroll
    for (int i = 0; i < 4; i++) {
        int r = row0 + ty * 4 + i;
        if (r < M) {
            float4 o = make_float4(acc[i][0] + bz.x, acc[i][1] + bz.y,
                                   acc[i][2] + bz.z, acc[i][3] + bz.w);
            *reinterpret_cast<float4*>(C + (size_t)r * N + col0 + tx * 4) = o;
        }
    }
}

// GI/GH fused: y<6 -> GI col y, y>=6 -> GH col y-6
__global__ void k_gemm_g(const float* __restrict__ Wih, const float* __restrict__ Whh,
                         const float* __restrict__ bih, const float* __restrict__ bhh) {
    int M = g_cnt[0];
    int row0 = blockIdx.x * 64;
    if (row0 >= M) return;
    int y = blockIdx.y;
    const float* A = (y < 6) ? g_X1 : g_H1;
    const float* W = (y < 6) ? Wih : Whh;
    const float* b = (y < 6) ? bih : bhh;
    float* C       = (y < 6) ? g_GI : g_GH;
    int col0 = (y % 6) * 64;
    extern __shared__ float sm[];
    gemm_tile(A, W, b, C, M, 384, row0, col0, sm);
}

// Q/K/V fused: y=0 Q, y=1 K, y=2,3 V halves
__global__ void k_gemm_qkv(const float* __restrict__ Wq, const float* __restrict__ bq,
                           const float* __restrict__ Wk, const float* __restrict__ bk,
                           const float* __restrict__ Wv, const float* __restrict__ bv) {
    int M = g_cnt[1];
    int row0 = blockIdx.x * 64;
    if (row0 >= M) return;
    int y = blockIdx.y;
    const float *A, *W, *b; float* C; int N, col0;
    if (y == 0)      { A = g_Xq; W = Wq; b = bq; C = g_Q; N = 64;  col0 = 0; }
    else if (y == 1) { A = g_Xc; W = Wk; b = bk; C = g_K; N = 64;  col0 = 0; }
    else             { A = g_Xc; W = Wv; b = bv; C = g_V; N = 128; col0 = (y - 2) * 64; }
    extern __shared__ float sm[];
    gemm_tile(A, W, b, C, M, N, row0, col0, sm);
}

// ----------------- k_gruc: GRU gates + scatter h_new + column max ----------
__global__ void k_gruc(const float* __restrict__ hid, float* __restrict__ outH) {
    int n1 = g_cnt[0];
    int t = threadIdx.x;
    int c = t & 127, sub = t >> 7;
    int s0 = blockIdx.x * 8;
    float mx = -FLT_MAX;
#pragma unroll
    for (int k = 0; k < 4; k++) {
        int s = s0 + sub * 4 + k;
        if (s < n1) {
            int row = g_idx1[s];
            const float* gi = g_GI + (size_t)s * 384;
            const float* gh = g_GH + (size_t)s * 384;
            float r  = 1.f / (1.f + __expf(-(gi[c] + gh[c])));
            float z  = 1.f / (1.f + __expf(-(gi[128 + c] + gh[128 + c])));
            float nn = tanhf(gi[256 + c] + r * gh[256 + c]);
            float h  = hid[(size_t)row * 128 + c];
            float o  = (1.f - z) * nn + z * h;
            outH[(size_t)row * 128 + c] = o;
            mx = fmaxf(mx, o);
        }
    }
    __shared__ float red[2][128];
    red[sub][c] = mx;
    __syncthreads();
    if (t < 128) atomicMax(&g_outacc[t], ford(fmaxf(red[0][t], red[1][t])));
}

// ----------------- k_flash: no-rescale attention partials over m23 ---------
// Scores are provably bounded (|s|<~3), so exp needs no max subtraction and
// key-split partials (O, l) are exactly additive. exp runs on the FMA pipe.
#define FLASH_SMEM ((3 * 64 * 68 + 64 * 128) * 4)
__global__ void __launch_bounds__(256, 2) k_flash() {
    int n23 = g_cnt[1];
    int qb = blockIdx.x / KSPLIT;
    int sp = blockIdx.x % KSPLIT;
    int q0 = qb * 64;
    if (q0 >= n23) return;
    extern __shared__ float sm[];
    float* QT = sm;                 // [64 d][68]  (scaled by 1/8)
    float* KT = sm + 64 * 68;       // [64 d][68]
    float* Ps = sm + 2 * 64 * 68;   // [64 j][68]  i-contiguous
    float* Vs = sm + 3 * 64 * 68;   // [64 j][128]
    int t = threadIdx.x;
    int ty = t >> 4, tx = t & 15;
    // load Q tile transposed, fold 1/sqrt(64) scale
    for (int i4 = t; i4 < 64 * 16; i4 += 256) {
        int r = i4 >> 4, d4 = i4 & 15;
        float4 v = make_float4(0.f, 0.f, 0.f, 0.f);
        if (q0 + r < n23)
            v = reinterpret_cast<const float4*>(g_Q + (size_t)(q0 + r) * AT)[d4];
        QT[(d4 * 4 + 0) * 68 + r] = v.x * 0.125f;
        QT[(d4 * 4 + 1) * 68 + r] = v.y * 0.125f;
        QT[(d4 * 4 + 2) * 68 + r] = v.z * 0.125f;
        QT[(d4 * 4 + 3) * 68 + r] = v.w * 0.125f;
    }
    float l[4] = {0.f, 0.f, 0.f, 0.f};
    float o[4][8];
#pragma unroll
    for (int i = 0; i < 4; i++)
#pragma unroll
        for (int c = 0; c < 8; c++) o[i][c] = 0.f;

    int nkb = (n23 + 63) >> 6;
    int chunk = (nkb + KSPLIT - 1) / KSPLIT;
    int kb0 = sp * chunk;
    int kb1 = min(kb0 + chunk, nkb);
    for (int kb = kb0; kb < kb1; kb++) {
        int k0 = kb << 6;
        __syncthreads();
        for (int i4 = t; i4 < 64 * 16; i4 += 256) {
            int j = i4 >> 4, d4 = i4 & 15;
            float4 v = make_float4(0.f, 0.f, 0.f, 0.f);
            if (k0 + j < n23)
                v = reinterpret_cast<const float4*>(g_K + (size_t)(k0 + j) * AT)[d4];
            KT[(d4 * 4 + 0) * 68 + j] = v.x;
            KT[(d4 * 4 + 1) * 68 + j] = v.y;
            KT[(d4 * 4 + 2) * 68 + j] = v.z;
            KT[(d4 * 4 + 3) * 68 + j] = v.w;
        }
        for (int i4 = t; i4 < 64 * 32; i4 += 256) {
            int j = i4 >> 5, d4 = i4 & 31;
            float4 v = make_float4(0.f, 0.f, 0.f, 0.f);
            if (k0 + j < n23)
                v = reinterpret_cast<const float4*>(g_V + (size_t)(k0 + j) * HD)[d4];
            reinterpret_cast<float4*>(Vs + j * 128)[d4] = v;
        }
        __syncthreads();
        // S = Qs K^T (4x4 micro)
        float s[4][4] = {};
#pragma unroll 8
        for (int d = 0; d < 64; d++) {
            float4 qa4 = *reinterpret_cast<const float4*>(QT + d * 68 + ty * 4);
            float4 kb4 = *reinterpret_cast<const float4*>(KT + d * 68 + tx * 4);
            float qa[4] = {qa4.x, qa4.y, qa4.z, qa4.w};
            float kk[4] = {kb4.x, kb4.y, kb4.z, kb4.w};
#pragma unroll
            for (int i = 0; i < 4; i++)
#pragma unroll
                for (int j = 0; j < 4; j++) s[i][j] += qa[i] * kk[j];
        }
        // P = exp(S) with tail mask; accumulate l; write P^T (i-contiguous)
#pragma unroll
        for (int j = 0; j < 4; j++) {
            bool vj = (k0 + tx * 4 + j) < n23;
            float p0 = vj ? exp_fast(s[0][j]) : 0.f;
            float p1 = vj ? exp_fast(s[1][j]) : 0.f;
            float p2 = vj ? exp_fast(s[2][j]) : 0.f;
            float p3 = vj ? exp_fast(s[3][j]) : 0.f;
            l[0] += p0; l[1] += p1; l[2] += p2; l[3] += p3;
            *reinterpret_cast<float4*>(Ps + (tx * 4 + j) * 68 + ty * 4) =
                make_float4(p0, p1, p2, p3);
        }
        __syncthreads();
        // O += P V  (4 rows x 8 cols micro; cols split into two tx*4 halves)
#pragma unroll 4
        for (int j2 = 0; j2 < 64; j2++) {
            float4 p4 = *reinterpret_cast<const float4*>(Ps + j2 * 68 + ty * 4);
            float4 va = *reinterpret_cast<const float4*>(Vs + j2 * 128 + tx * 4);
            float4 vb = *reinterpret_cast<const float4*>(Vs + j2 * 128 + 64 + tx * 4);
            float pr[4] = {p4.x, p4.y, p4.z, p4.w};
            float vv[8] = {va.x, va.y, va.z, va.w, vb.x, vb.y, vb.z, vb.w};
#pragma unroll
            for (int i = 0; i < 4; i++)
#pragma unroll
                for (int c = 0; c < 8; c++) o[i][c] += pr[i] * vv[c];
        }
    }
    // epilogue: reduce l across tx, store partials for this split
    __syncthreads();
    float* lr = KT;   // KT no longer needed
#pragma unroll
    for (int i = 0; i < 4; i++) lr[(ty * 4 + i) * 16 + tx] = l[i];
    __syncthreads();
#pragma unroll
    for (int i = 0; i < 4; i++) {
        int slot = q0 + ty * 4 + i;
        if (slot >= n23) continue;
        float lt = 0.f;
#pragma unroll
        for (int x = 0; x < 16; x++) lt += lr[(ty * 4 + i) * 16 + x];
        if (tx == 0) g_L3[sp * CN + slot] = lt;
        float* dst = g_O3 + ((size_t)sp * CN + slot) * 128;
        *reinterpret_cast<float4*>(dst + tx * 4) =
            make_float4(o[i][0], o[i][1], o[i][2], o[i][3]);
        *reinterpret_cast<float4*>(dst + 64 + tx * 4) =
            make_float4(o[i][4], o[i][5], o[i][6], o[i][7]);
    }
}

// ----------------- k_combine: sum splits, tanh, scatter, column max --------
__global__ void k_combine(float* __restrict__ outH) {
    int n23 = g_cnt[1];
    int t = threadIdx.x;
    int c = t & 127, sub = t >> 7;
    int s0 = blockIdx.x * 8;
    float mx = -FLT_MAX;
#pragma unroll
    for (int k = 0; k < 4; k++) {
        int sl = s0 + sub * 4 + k;
        if (sl < n23) {
            float lt = g_L3[sl] + g_L3[CN + sl] + g_L3[2 * CN + sl];
            float ov = g_O3[(size_t)sl * 128 + c]
                     + g_O3[((size_t)CN + sl) * 128 + c]
                     + g_O3[((size_t)2 * CN + sl) * 128 + c];
            float h = tanhf(ov / lt);
            int row = g_idx23[sl] & 0x3FFFFFFF;
            outH[(size_t)row * 128 + c] = h;
            mx = fmaxf(mx, h);
        }
    }
    __shared__ float red[2][128];
    red[sub][c] = mx;
    __syncthreads();
    if (t < 128) atomicMax(&g_outacc[t], ford(fmaxf(red[0][t], red[1][t])));
}

// ----------------- k_final: output vector --------------------------------
__global__ void k_final(float* __restrict__ out) {
    int t = threadIdx.x;
    out[t] = funord(g_outacc[t]) + g_tf[t];
}

// ---------------------------------------------------------------------------
extern "C" void kernel_launch(void* const* d_in, const int* in_sizes, int n_in,
                              void* d_out, int out_size) {
    const float* interval = (const float*)d_in[0];
    const float* co   = (const float*)d_in[1];
    const float* no_  = (const float*)d_in[2];
    const float* un   = (const float*)d_in[3];
    const float* hid  = (const float*)d_in[4];
    const int*   divided = (const int*)d_in[5];
    const float* W_ih = (const float*)d_in[6];
    const float* W_hh = (const float*)d_in[7];
    const float* b_ih = (const float*)d_in[8];
    const float* b_hh = (const float*)d_in[9];
    const float* Wq = (const float*)d_in[10];
    const float* bq = (const float*)d_in[11];
    const float* Wk = (const float*)d_in[12];
    const float* bk = (const float*)d_in[13];
    const float* Wv = (const float*)d_in[14];
    const float* bv = (const float*)d_in[15];
    const float* Wt = (const float*)d_in[16];
    const float* bt = (const float*)d_in[17];
    float* out  = (float*)d_out;
    float* outH = out + HD;   // h_new region: [12288, 128] after the 128-vec

    cudaFuncSetAttribute(k_gemm_g,   cudaFuncAttributeMaxDynamicSharedMemorySize, GEMM_SMEM);
    cudaFuncSetAttribute(k_gemm_qkv, cudaFuncAttributeMaxDynamicSharedMemorySize, GEMM_SMEM);
    cudaFuncSetAttribute(k_flash,    cudaFuncAttributeMaxDynamicSharedMemorySize, FLASH_SMEM);

    k_init<<<768, 512>>>(outH, interval, Wt, bt);
    k_compact<<<48, 256>>>(divided);
    k_gather<<<CN / 2, 256>>>(co, no_, un, hid);
    k_gemm_g<<<dim3(192, 12), 256, GEMM_SMEM>>>(W_ih, W_hh, b_ih, b_hh);
    k_gemm_qkv<<<dim3(192, 4), 256, GEMM_SMEM>>>(Wq, bq, Wk, bk, Wv, bv);
    k_gruc<<<CN / 8, 256>>>(hid, outH);
    k_flash<<<192 * KSPLIT, 256, FLASH_SMEM>>>();
    k_combine<<<CN / 8, 256>>>(outH);
    k_final<<<1, 128>>>(out);
}

// round 5
// speedup vs baseline: 2.5137x; 1.9868x over previous
#include <cuda_runtime.h>
#include <float.h>
#include <math.h>

#define CN 12288          // CODE_NUM
#define GD 128            // GRAPH
#define HD 128            // HIDDEN
#define AT 64             // ATT
#define KSPLIT 3

// ----------------- scratch (device globals; no allocation allowed) ---------
__device__ float g_Xq[CN * GD];     // gathered query-source rows (m23)
__device__ float g_Xc[CN * GD];     // gathered co_embeddings rows (m23)
__device__ float g_X1[CN * GD];     // gathered co_embeddings rows (m1)
__device__ float g_H1[CN * HD];     // gathered hidden rows (m1)
__device__ float g_GI[CN * 3 * HD]; // x @ W_ih^T + b_ih
__device__ float g_GH[CN * 3 * HD]; // h @ W_hh^T + b_hh
__device__ float g_Q[CN * AT];      // tf32-truncated
__device__ float g_K[CN * AT];      // tf32-truncated
__device__ float g_V[CN * HD];      // tf32-truncated
__device__ float g_O3[KSPLIT * CN * HD];  // per-split O partials
__device__ float g_L3[KSPLIT * CN];       // per-split l partials
__device__ int   g_idx1[CN];
__device__ int   g_idx23[CN];       // row | (m2 << 30)
__device__ int   g_cnt[2];          // [0]=n1, [1]=n23
__device__ unsigned g_outacc[HD];   // ordered-uint float max accumulator
__device__ float g_tf[HD];          // time features

__device__ __forceinline__ unsigned ford(float f) {
    unsigned u = __float_as_uint(f);
    return (u & 0x80000000u) ? ~u : (u | 0x80000000u);
}
__device__ __forceinline__ float funord(unsigned u) {
    return (u & 0x80000000u) ? __uint_as_float(u ^ 0x80000000u)
                             : __uint_as_float(~u);
}

// round-to-nearest tf32 (10-bit mantissa), returned as fp32 bit pattern
__device__ __forceinline__ float tf32r(float x) {
    unsigned u;
    asm("cvt.rna.tf32.f32 %0, %1;" : "=r"(u) : "f"(x));
    return __uint_as_float(u);
}

// m16n8k8 tf32 MMA, fp32 accumulate (in place)
__device__ __forceinline__ void mma_tf32(float* c, const unsigned* a,
                                         unsigned b0, unsigned b1) {
    asm volatile(
        "mma.sync.aligned.m16n8k8.row.col.f32.tf32.tf32.f32 "
        "{%0,%1,%2,%3}, {%4,%5,%6,%7}, {%8,%9}, {%0,%1,%2,%3};"
        : "+f"(c[0]), "+f"(c[1]), "+f"(c[2]), "+f"(c[3])
        : "r"(a[0]), "r"(a[1]), "r"(a[2]), "r"(a[3]), "r"(b0), "r"(b1));
}

// FMA-pipe exp (scores bounded, no range clamp needed)
__device__ __forceinline__ float exp_fast(float x) {
    float y = fmaf(x, 1.44269504f, 12582912.0f);
    int   bz = __float_as_int(y);
    float n = y - 12582912.0f;
    float f = fmaf(x, 1.44269504f, -n);
    float p = 0.0013333558f;
    p = fmaf(p, f, 0.0096181291f);
    p = fmaf(p, f, 0.0555041087f);
    p = fmaf(p, f, 0.2402265069f);
    p = fmaf(p, f, 0.6931471806f);
    p = fmaf(p, f, 1.0f);
    float sc = __int_as_float((bz + (127 - 0x4B400000)) << 23);
    return p * sc;
}

// ----------------- k_init: zero h_new region, init accumulators, tf --------
__global__ void k_init(float* __restrict__ outH, const float* __restrict__ interval,
                       const float* __restrict__ Wt, const float* __restrict__ bt) {
    int i = blockIdx.x * 512 + threadIdx.x;            // 768*512 = 393216 float4
    reinterpret_cast<float4*>(outH)[i] = make_float4(0.f, 0.f, 0.f, 0.f);
    if (blockIdx.x == 0) {
        int t = threadIdx.x;
        if (t < HD) {
            float xt = 1.0f / logf(interval[0] + 2.7182818284590452f);
            g_tf[t] = tanhf(xt * Wt[t] + bt[t]);
            g_outacc[t] = ford(-FLT_MAX);
        }
        if (t == 0) { g_cnt[0] = 0; g_cnt[1] = 0; }
    }
}

// ----------------- k_compact: build m1 / m23 index lists -------------------
__global__ void k_compact(const int* __restrict__ divided) {
    int row = blockIdx.x * 256 + threadIdx.x;
    if (row >= CN) return;
    int d0 = divided[row * 3 + 0];
    int d1 = divided[row * 3 + 1];
    int d2 = divided[row * 3 + 2];
    if (d0 > 0) {
        int pos = atomicAdd(&g_cnt[0], 1);
        g_idx1[pos] = row;
    }
    if (d1 > 0 || d2 > 0) {
        int pos = atomicAdd(&g_cnt[1], 1);
        g_idx23[pos] = row | ((d1 > 0) ? (1 << 30) : 0);
    }
}

// ----------------- k_gather: compact rows into dense scratch ---------------
__global__ void k_gather(const float* __restrict__ co, const float* __restrict__ no_,
                         const float* __restrict__ un, const float* __restrict__ hid) {
    int s = blockIdx.x * 2 + (threadIdx.x >> 7);
    int lane = threadIdx.x & 127;
    int n23 = g_cnt[1], n1 = g_cnt[0];
    if (s < n23) {
        int e = g_idx23[s];
        int row = e & 0x3FFFFFFF;
        const float* src = (e & (1 << 30)) ? no_ : un;
        g_Xq[s * GD + lane] = src[row * GD + lane];
        g_Xc[s * GD + lane] = co[row * GD + lane];
    }
    if (s < n1) {
        int row = g_idx1[s];
        g_X1[s * GD + lane] = co[row * GD + lane];
        g_H1[s * HD + lane] = hid[row * HD + lane];
    }
}

// ----------------- tiled GEMM body: C[64,64] = A[64,128] @ W[64,128]^T + b -
#define GEMM_SMEM ((64 * 132 + 128 * 68) * 4)
__device__ __forceinline__ void gemm_tile(const float* __restrict__ A,
                                          const float* __restrict__ W,
                                          const float* __restrict__ bias,
                                          float* __restrict__ C,
                                          int M, int N, int row0, int col0,
                                          float* sm, bool trunc) {
    float* As = sm;              // [64][132] row-major, padded
    float* Ws = sm + 64 * 132;   // [128][68]  Ws[k][c]
    int t = threadIdx.x;
    for (int i4 = t; i4 < 64 * 32; i4 += 256) {
        int r = i4 >> 5, k4 = i4 & 31;
        float4 v = make_float4(0.f, 0.f, 0.f, 0.f);
        if (row0 + r < M)
            v = reinterpret_cast<const float4*>(A + (size_t)(row0 + r) * 128)[k4];
        reinterpret_cast<float4*>(As + r * 132)[k4] = v;
    }
    for (int i4 = t; i4 < 64 * 32; i4 += 256) {
        int c = i4 >> 5, k4 = i4 & 31;
        float4 v = reinterpret_cast<const float4*>(W + (size_t)(col0 + c) * 128)[k4];
        Ws[(k4 * 4 + 0) * 68 + c] = v.x;
        Ws[(k4 * 4 + 1) * 68 + c] = v.y;
        Ws[(k4 * 4 + 2) * 68 + c] = v.z;
        Ws[(k4 * 4 + 3) * 68 + c] = v.w;
    }
    __syncthreads();
    int ty = t >> 4, tx = t & 15;
    float acc[4][4] = {};
    const float* Ap = As + ty * 4 * 132;
#pragma unroll 8
    for (int k = 0; k < 128; k++) {
        float a[4];
        a[0] = Ap[k]; a[1] = Ap[132 + k]; a[2] = Ap[264 + k]; a[3] = Ap[396 + k];
        float4 b4 = *reinterpret_cast<const float4*>(Ws + k * 68 + tx * 4);
        float b[4] = {b4.x, b4.y, b4.z, b4.w};
#pragma unroll
        for (int i = 0; i < 4; i++)
#pragma unroll
            for (int j = 0; j < 4; j++) acc[i][j] += a[i] * b[j];
    }
    float4 bz = *reinterpret_cast<const float4*>(bias + col0 + tx * 4);
#pragma unroll
    for (int i = 0; i < 4; i++) {
        int r = row0 + ty * 4 + i;
        if (r < M) {
            float4 o = make_float4(acc[i][0] + bz.x, acc[i][1] + bz.y,
                                   acc[i][2] + bz.z, acc[i][3] + bz.w);
            if (trunc) {
                o.x = tf32r(o.x); o.y = tf32r(o.y);
                o.z = tf32r(o.z); o.w = tf32r(o.w);
            }
            *reinterpret_cast<float4*>(C + (size_t)r * N + col0 + tx * 4) = o;
        }
    }
}

// GI/GH fused: y<6 -> GI col y, y>=6 -> GH col y-6
__global__ void k_gemm_g(const float* __restrict__ Wih, const float* __restrict__ Whh,
                         const float* __restrict__ bih, const float* __restrict__ bhh) {
    int M = g_cnt[0];
    int row0 = blockIdx.x * 64;
    if (row0 >= M) return;
    int y = blockIdx.y;
    const float* A = (y < 6) ? g_X1 : g_H1;
    const float* W = (y < 6) ? Wih : Whh;
    const float* b = (y < 6) ? bih : bhh;
    float* C       = (y < 6) ? g_GI : g_GH;
    int col0 = (y % 6) * 64;
    extern __shared__ float sm[];
    gemm_tile(A, W, b, C, M, 384, row0, col0, sm, false);
}

// Q/K/V fused: y=0 Q, y=1 K, y=2,3 V halves (outputs tf32-truncated)
__global__ void k_gemm_qkv(const float* __restrict__ Wq, const float* __restrict__ bq,
                           const float* __restrict__ Wk, const float* __restrict__ bk,
                           const float* __restrict__ Wv, const float* __restrict__ bv) {
    int M = g_cnt[1];
    int row0 = blockIdx.x * 64;
    if (row0 >= M) return;
    int y = blockIdx.y;
    const float *A, *W, *b; float* C; int N, col0;
    if (y == 0)      { A = g_Xq; W = Wq; b = bq; C = g_Q; N = 64;  col0 = 0; }
    else if (y == 1) { A = g_Xc; W = Wk; b = bk; C = g_K; N = 64;  col0 = 0; }
    else             { A = g_Xc; W = Wv; b = bv; C = g_V; N = 128; col0 = (y - 2) * 64; }
    extern __shared__ float sm[];
    gemm_tile(A, W, b, C, M, N, row0, col0, sm, true);
}

// ----------------- k_gruc: GRU gates + scatter h_new + column max ----------
__global__ void k_gruc(const float* __restrict__ hid, float* __restrict__ outH) {
    int n1 = g_cnt[0];
    int t = threadIdx.x;
    int c = t & 127, sub = t >> 7;
    int s0 = blockIdx.x * 8;
    float mx = -FLT_MAX;
#pragma unroll
    for (int k = 0; k < 4; k++) {
        int s = s0 + sub * 4 + k;
        if (s < n1) {
            int row = g_idx1[s];
            const float* gi = g_GI + (size_t)s * 384;
            const float* gh = g_GH + (size_t)s * 384;
            float r  = 1.f / (1.f + __expf(-(gi[c] + gh[c])));
            float z  = 1.f / (1.f + __expf(-(gi[128 + c] + gh[128 + c])));
            float nn = tanhf(gi[256 + c] + r * gh[256 + c]);
            float h  = hid[(size_t)row * 128 + c];
            float o  = (1.f - z) * nn + z * h;
            outH[(size_t)row * 128 + c] = o;
            mx = fmaxf(mx, o);
        }
    }
    __shared__ float red[2][128];
    red[sub][c] = mx;
    __syncthreads();
    if (t < 128) atomicMax(&g_outacc[t], ford(fmaxf(red[0][t], red[1][t])));
}

// ----------------- k_flash: tf32 MMA no-rescale attention partials ---------
// 8 warps: warp w -> mw=w>>1 (16 q-rows), nw=w&1 (key-half for S, d-half for PV).
// Ps [64][68] (aliased Q staging), Ks [64][68], Vs [64][136]: all fragment
// LDS patterns conflict-free by construction (banks 4g+tid / 8tid+g).
#define FLASH_SMEM ((2 * 64 * 68 + 64 * 136) * 4)
__global__ void __launch_bounds__(256, 2) k_flash() {
    int n23 = g_cnt[1];
    int qb = blockIdx.x / KSPLIT;
    int sp = blockIdx.x % KSPLIT;
    int q0 = qb * 64;
    if (q0 >= n23) return;
    extern __shared__ float sm[];
    float* Ps = sm;                       // [64][68], first used as Q staging
    float* Ks = sm + 64 * 68;             // [64][68]
    float* Vs = sm + 2 * 64 * 68;         // [64][136]
    int t = threadIdx.x;
    int w = t >> 5, lane = t & 31;
    int g = lane >> 2, tid = lane & 3;
    int mw = w >> 1, nw = w & 1;

    // stage Q (x 1/8 — exact exponent shift on tf32 values) into Ps
    for (int i4 = t; i4 < 64 * 16; i4 += 256) {
        int r = i4 >> 4, d4 = i4 & 15;
        float4 v = make_float4(0.f, 0.f, 0.f, 0.f);
        if (q0 + r < n23)
            v = reinterpret_cast<const float4*>(g_Q + (size_t)(q0 + r) * AT)[d4];
        v.x *= 0.125f; v.y *= 0.125f; v.z *= 0.125f; v.w *= 0.125f;
        *reinterpret_cast<float4*>(Ps + r * 68 + d4 * 4) = v;
    }
    __syncthreads();
    // preload Q fragments: qa[ks][0..3]
    unsigned qa[8][4];
    {
        const float* r0 = Ps + (16 * mw + g) * 68;
        const float* r8 = Ps + (16 * mw + g + 8) * 68;
#pragma unroll
        for (int ks = 0; ks < 8; ks++) {
            qa[ks][0] = __float_as_uint(r0[8 * ks + tid]);
            qa[ks][1] = __float_as_uint(r8[8 * ks + tid]);
            qa[ks][2] = __float_as_uint(r0[8 * ks + tid + 4]);
            qa[ks][3] = __float_as_uint(r8[8 * ks + tid + 4]);
        }
    }
    float o[8][4];
#pragma unroll
    for (int nt = 0; nt < 8; nt++)
#pragma unroll
        for (int i = 0; i < 4; i++) o[nt][i] = 0.f;
    float l0 = 0.f, l1 = 0.f;

    int nkb = (n23 + 63) >> 6;
    int chunk = (nkb + KSPLIT - 1) / KSPLIT;
    int kb0 = sp * chunk;
    int kb1 = min(kb0 + chunk, nkb);
    for (int kb = kb0; kb < kb1; kb++) {
        int k0 = kb << 6;
        __syncthreads();
        // load K tile [64][68]
        for (int i4 = t; i4 < 64 * 16; i4 += 256) {
            int r = i4 >> 4, d4 = i4 & 15;
            float4 v = make_float4(0.f, 0.f, 0.f, 0.f);
            if (k0 + r < n23)
                v = reinterpret_cast<const float4*>(g_K + (size_t)(k0 + r) * AT)[d4];
            *reinterpret_cast<float4*>(Ks + r * 68 + d4 * 4) = v;
        }
        // load V tile [64][136]
        for (int i4 = t; i4 < 64 * 32; i4 += 256) {
            int j = i4 >> 5, d4 = i4 & 31;
            float4 v = make_float4(0.f, 0.f, 0.f, 0.f);
            if (k0 + j < n23)
                v = reinterpret_cast<const float4*>(g_V + (size_t)(k0 + j) * HD)[d4];
            *reinterpret_cast<float4*>(Vs + j * 136 + d4 * 4) = v;
        }
        __syncthreads();
        // S = Qs K^T over this warp's 32-key half: 4 n-tiles x 8 k-steps
        float c[4][4];
#pragma unroll
        for (int nt = 0; nt < 4; nt++)
#pragma unroll
            for (int i = 0; i < 4; i++) c[nt][i] = 0.f;
#pragma unroll
        for (int nt = 0; nt < 4; nt++) {
            const float* kr = Ks + (nw * 32 + 8 * nt + g) * 68;
#pragma unroll
            for (int ks = 0; ks < 8; ks++) {
                unsigned b0 = __float_as_uint(kr[8 * ks + tid]);
                unsigned b1 = __float_as_uint(kr[8 * ks + tid + 4]);
                mma_tf32(c[nt], qa[ks], b0, b1);
            }
        }
        // P = exp(S), tail-masked; accumulate l; write tf32 P to Ps
#pragma unroll
        for (int nt = 0; nt < 4; nt++) {
            int key0 = k0 + nw * 32 + 8 * nt + 2 * tid;
            float p0 = (key0     < n23) ? exp_fast(c[nt][0]) : 0.f;
            float p1 = (key0 + 1 < n23) ? exp_fast(c[nt][1]) : 0.f;
            float p2 = (key0     < n23) ? exp_fast(c[nt][2]) : 0.f;
            float p3 = (key0 + 1 < n23) ? exp_fast(c[nt][3]) : 0.f;
            l0 += p0 + p1;
            l1 += p2 + p3;
            int col = nw * 32 + 8 * nt + 2 * tid;
            *reinterpret_cast<float2*>(Ps + (16 * mw + g) * 68 + col) =
                make_float2(tf32r(p0), tf32r(p1));
            *reinterpret_cast<float2*>(Ps + (16 * mw + g + 8) * 68 + col) =
                make_float2(tf32r(p2), tf32r(p3));
        }
        __syncthreads();
        // O += P V over this warp's 64-d half: 8 n-tiles x 8 k-steps
#pragma unroll
        for (int ks = 0; ks < 8; ks++) {
            unsigned pa[4];
            pa[0] = __float_as_uint(Ps[(16 * mw + g) * 68 + 8 * ks + tid]);
            pa[1] = __float_as_uint(Ps[(16 * mw + g + 8) * 68 + 8 * ks + tid]);
            pa[2] = __float_as_uint(Ps[(16 * mw + g) * 68 + 8 * ks + tid + 4]);
            pa[3] = __float_as_uint(Ps[(16 * mw + g + 8) * 68 + 8 * ks + tid + 4]);
            const float* vr0 = Vs + (8 * ks + tid) * 136 + nw * 64 + g;
            const float* vr1 = Vs + (8 * ks + tid + 4) * 136 + nw * 64 + g;
#pragma unroll
            for (int nt = 0; nt < 8; nt++) {
                unsigned b0 = __float_as_uint(vr0[8 * nt]);
                unsigned b1 = __float_as_uint(vr1[8 * nt]);
                mma_tf32(o[nt], pa, b0, b1);
            }
        }
    }
    // ---- epilogue ----
    // reduce l over the quad (tid dimension)
    l0 += __shfl_xor_sync(0xffffffffu, l0, 1);
    l0 += __shfl_xor_sync(0xffffffffu, l0, 2);
    l1 += __shfl_xor_sync(0xffffffffu, l1, 1);
    l1 += __shfl_xor_sync(0xffffffffu, l1, 2);
    // lr[row][nw] in Ks region (Ks reads all complete before last PV)
    float* lr = Ks;
    if (tid == 0) {
        lr[(16 * mw + g) * 2 + nw] = l0;
        lr[(16 * mw + g + 8) * 2 + nw] = l1;
    }
    __syncthreads();
    if (t < 64 && q0 + t < n23)
        g_L3[sp * CN + q0 + t] = lr[t * 2] + lr[t * 2 + 1];
    // store O partials: rows 16mw+g(+8), cols nw*64 + 8nt + 2tid
    int r0 = q0 + 16 * mw + g;
    int r8 = r0 + 8;
    float* base0 = g_O3 + ((size_t)sp * CN + r0) * 128 + nw * 64 + 2 * tid;
    float* base8 = g_O3 + ((size_t)sp * CN + r8) * 128 + nw * 64 + 2 * tid;
#pragma unroll
    for (int nt = 0; nt < 8; nt++) {
        if (r0 < n23)
            *reinterpret_cast<float2*>(base0 + 8 * nt) = make_float2(o[nt][0], o[nt][1]);
        if (r8 < n23)
            *reinterpret_cast<float2*>(base8 + 8 * nt) = make_float2(o[nt][2], o[nt][3]);
    }
}

// ----------------- k_combine: sum splits, tanh, scatter, column max --------
__global__ void k_combine(float* __restrict__ outH) {
    int n23 = g_cnt[1];
    int t = threadIdx.x;
    int c = t & 127, sub = t >> 7;
    int s0 = blockIdx.x * 8;
    float mx = -FLT_MAX;
#pragma unroll
    for (int k = 0; k < 4; k++) {
        int sl = s0 + sub * 4 + k;
        if (sl < n23) {
            float lt = g_L3[sl] + g_L3[CN + sl] + g_L3[2 * CN + sl];
            float ov = g_O3[(size_t)sl * 128 + c]
                     + g_O3[((size_t)CN + sl) * 128 + c]
                     + g_O3[((size_t)2 * CN + sl) * 128 + c];
            float h = tanhf(ov / lt);
            int row = g_idx23[sl] & 0x3FFFFFFF;
            outH[(size_t)row * 128 + c] = h;
            mx = fmaxf(mx, h);
        }
    }
    __shared__ float red[2][128];
    red[sub][c] = mx;
    __syncthreads();
    if (t < 128) atomicMax(&g_outacc[t], ford(fmaxf(red[0][t], red[1][t])));
}

// ----------------- k_final: output vector --------------------------------
__global__ void k_final(float* __restrict__ out) {
    int t = threadIdx.x;
    out[t] = funord(g_outacc[t]) + g_tf[t];
}

// ---------------------------------------------------------------------------
extern "C" void kernel_launch(void* const* d_in, const int* in_sizes, int n_in,
                              void* d_out, int out_size) {
    const float* interval = (const float*)d_in[0];
    const float* co   = (const float*)d_in[1];
    const float* no_  = (const float*)d_in[2];
    const float* un   = (const float*)d_in[3];
    const float* hid  = (const float*)d_in[4];
    const int*   divided = (const int*)d_in[5];
    const float* W_ih = (const float*)d_in[6];
    const float* W_hh = (const float*)d_in[7];
    const float* b_ih = (const float*)d_in[8];
    const float* b_hh = (const float*)d_in[9];
    const float* Wq = (const float*)d_in[10];
    const float* bq = (const float*)d_in[11];
    const float* Wk = (const float*)d_in[12];
    const float* bk = (const float*)d_in[13];
    const float* Wv = (const float*)d_in[14];
    const float* bv = (const float*)d_in[15];
    const float* Wt = (const float*)d_in[16];
    const float* bt = (const float*)d_in[17];
    float* out  = (float*)d_out;
    float* outH = out + HD;   // h_new region: [12288, 128] after the 128-vec

    cudaFuncSetAttribute(k_gemm_g,   cudaFuncAttributeMaxDynamicSharedMemorySize, GEMM_SMEM);
    cudaFuncSetAttribute(k_gemm_qkv, cudaFuncAttributeMaxDynamicSharedMemorySize, GEMM_SMEM);
    cudaFuncSetAttribute(k_flash,    cudaFuncAttributeMaxDynamicSharedMemorySize, FLASH_SMEM);

    k_init<<<768, 512>>>(outH, interval, Wt, bt);
    k_compact<<<48, 256>>>(divided);
    k_gather<<<CN / 2, 256>>>(co, no_, un, hid);
    k_gemm_g<<<dim3(192, 12), 256, GEMM_SMEM>>>(W_ih, W_hh, b_ih, b_hh);
    k_gemm_qkv<<<dim3(192, 4), 256, GEMM_SMEM>>>(Wq, bq, Wk, bk, Wv, bv);
    k_gruc<<<CN / 8, 256>>>(hid, outH);
    k_flash<<<192 * KSPLIT, 256, FLASH_SMEM>>>();
    k_combine<<<CN / 8, 256>>>(outH);
    k_final<<<1, 128>>>(out);
}

// round 6
// speedup vs baseline: 2.9200x; 1.1616x over previous
#include <cuda_runtime.h>
#include <float.h>
#include <math.h>

#define CN 12288          // CODE_NUM
#define GD 128            // GRAPH
#define HD 128            // HIDDEN
#define AT 64             // ATT
#define KSPLIT 3

// ----------------- scratch (device globals; no allocation allowed) ---------
__device__ float g_Xq[CN * GD];     // gathered query-source rows (m23)
__device__ float g_Xc[CN * GD];     // gathered co_embeddings rows (m23)
__device__ float g_X1[CN * GD];     // gathered co_embeddings rows (m1)
__device__ float g_H1[CN * HD];     // gathered hidden rows (m1)
__device__ float g_GI[CN * 3 * HD]; // x @ W_ih^T + b_ih
__device__ float g_GH[CN * 3 * HD]; // h @ W_hh^T + b_hh
__device__ float g_Q[CN * AT];      // tf32-truncated
__device__ float g_K[CN * AT];      // tf32-truncated
__device__ float g_V[CN * HD];      // tf32-truncated
__device__ float g_O3[KSPLIT * CN * HD];  // per-split O partials
__device__ float g_L3[KSPLIT * CN];       // per-split l partials
__device__ int   g_idx1[CN];
__device__ int   g_idx23[CN];       // row | (m2 << 30)
__device__ int   g_cnt[2];          // [0]=n1, [1]=n23
__device__ unsigned g_outacc[HD];   // ordered-uint float max accumulator
__device__ float g_tf[HD];          // time features

__device__ __forceinline__ unsigned ford(float f) {
    unsigned u = __float_as_uint(f);
    return (u & 0x80000000u) ? ~u : (u | 0x80000000u);
}
__device__ __forceinline__ float funord(unsigned u) {
    return (u & 0x80000000u) ? __uint_as_float(u ^ 0x80000000u)
                             : __uint_as_float(~u);
}

// round-to-nearest tf32 (10-bit mantissa), returned as fp32 bit pattern
__device__ __forceinline__ float tf32r(float x) {
    unsigned u;
    asm("cvt.rna.tf32.f32 %0, %1;" : "=r"(u) : "f"(x));
    return __uint_as_float(u);
}

// m16n8k8 tf32 MMA, fp32 accumulate (in place)
__device__ __forceinline__ void mma_tf32(float* c, const unsigned* a,
                                         unsigned b0, unsigned b1) {
    asm volatile(
        "mma.sync.aligned.m16n8k8.row.col.f32.tf32.tf32.f32 "
        "{%0,%1,%2,%3}, {%4,%5,%6,%7}, {%8,%9}, {%0,%1,%2,%3};"
        : "+f"(c[0]), "+f"(c[1]), "+f"(c[2]), "+f"(c[3])
        : "r"(a[0]), "r"(a[1]), "r"(a[2]), "r"(a[3]), "r"(b0), "r"(b1));
}

// FMA-pipe exp (scores bounded, no range clamp needed)
__device__ __forceinline__ float exp_fast(float x) {
    float y = fmaf(x, 1.44269504f, 12582912.0f);
    int   bz = __float_as_int(y);
    float n = y - 12582912.0f;
    float f = fmaf(x, 1.44269504f, -n);
    float p = 0.0013333558f;
    p = fmaf(p, f, 0.0096181291f);
    p = fmaf(p, f, 0.0555041087f);
    p = fmaf(p, f, 0.2402265069f);
    p = fmaf(p, f, 0.6931471806f);
    p = fmaf(p, f, 1.0f);
    float sc = __int_as_float((bz + (127 - 0x4B400000)) << 23);
    return p * sc;
}

// ----------------- k_init: zero h_new region, init accumulators, tf --------
__global__ void k_init(float* __restrict__ outH, const float* __restrict__ interval,
                       const float* __restrict__ Wt, const float* __restrict__ bt) {
    int i = blockIdx.x * 512 + threadIdx.x;            // 768*512 = 393216 float4
    reinterpret_cast<float4*>(outH)[i] = make_float4(0.f, 0.f, 0.f, 0.f);
    if (blockIdx.x == 0) {
        int t = threadIdx.x;
        if (t < HD) {
            float xt = 1.0f / logf(interval[0] + 2.7182818284590452f);
            g_tf[t] = tanhf(xt * Wt[t] + bt[t]);
            g_outacc[t] = ford(-FLT_MAX);
        }
        if (t == 0) { g_cnt[0] = 0; g_cnt[1] = 0; }
    }
}

// ----------------- k_compact: build m1 / m23 index lists -------------------
__global__ void k_compact(const int* __restrict__ divided) {
    int row = blockIdx.x * 256 + threadIdx.x;
    if (row >= CN) return;
    int d0 = divided[row * 3 + 0];
    int d1 = divided[row * 3 + 1];
    int d2 = divided[row * 3 + 2];
    if (d0 > 0) {
        int pos = atomicAdd(&g_cnt[0], 1);
        g_idx1[pos] = row;
    }
    if (d1 > 0 || d2 > 0) {
        int pos = atomicAdd(&g_cnt[1], 1);
        g_idx23[pos] = row | ((d1 > 0) ? (1 << 30) : 0);
    }
}

// ----------------- k_gather: compact rows into dense scratch ---------------
__global__ void k_gather(const float* __restrict__ co, const float* __restrict__ no_,
                         const float* __restrict__ un, const float* __restrict__ hid) {
    int s = blockIdx.x * 2 + (threadIdx.x >> 7);
    int lane = threadIdx.x & 127;
    int n23 = g_cnt[1], n1 = g_cnt[0];
    if (s < n23) {
        int e = g_idx23[s];
        int row = e & 0x3FFFFFFF;
        const float* src = (e & (1 << 30)) ? no_ : un;
        g_Xq[s * GD + lane] = src[row * GD + lane];
        g_Xc[s * GD + lane] = co[row * GD + lane];
    }
    if (s < n1) {
        int row = g_idx1[s];
        g_X1[s * GD + lane] = co[row * GD + lane];
        g_H1[s * HD + lane] = hid[row * HD + lane];
    }
}

// ----------------- tf32 MMA GEMM tile: C[64,64] = A[64,128] @ W[64,128]^T + b
// 8 warps: mw=w>>1 (16 rows), nw=w&1 (32 cols). K=128 in one smem tile.
// As/Ws [64][132]: fragment reads land on banks 4g+tid (+8ks const) -> conflict-free.
#define GEMM_SMEM (2 * 64 * 132 * 4)
__device__ __forceinline__ void gemm_tile_mma(const float* __restrict__ A,
                                              const float* __restrict__ W,
                                              const float* __restrict__ bias,
                                              float* __restrict__ C,
                                              int M, int N, int row0, int col0,
                                              float* sm, bool trunc) {
    float* As = sm;              // [64][132] row-major (k-major rows), tf32
    float* Ws = sm + 64 * 132;   // [64][132] W rows (= C cols), tf32
    int t = threadIdx.x;
    for (int i4 = t; i4 < 64 * 32; i4 += 256) {
        int r = i4 >> 5, k4 = i4 & 31;
        float4 v = make_float4(0.f, 0.f, 0.f, 0.f);
        if (row0 + r < M)
            v = reinterpret_cast<const float4*>(A + (size_t)(row0 + r) * 128)[k4];
        v.x = tf32r(v.x); v.y = tf32r(v.y); v.z = tf32r(v.z); v.w = tf32r(v.w);
        *reinterpret_cast<float4*>(As + r * 132 + k4 * 4) = v;
    }
    for (int i4 = t; i4 < 64 * 32; i4 += 256) {
        int c = i4 >> 5, k4 = i4 & 31;
        float4 v = reinterpret_cast<const float4*>(W + (size_t)(col0 + c) * 128)[k4];
        v.x = tf32r(v.x); v.y = tf32r(v.y); v.z = tf32r(v.z); v.w = tf32r(v.w);
        *reinterpret_cast<float4*>(Ws + c * 132 + k4 * 4) = v;
    }
    __syncthreads();
    int w = t >> 5, lane = t & 31;
    int g = lane >> 2, tid = lane & 3;
    int mw = w >> 1, nw = w & 1;
    float c[4][4];
#pragma unroll
    for (int nt = 0; nt < 4; nt++)
#pragma unroll
        for (int i = 0; i < 4; i++) c[nt][i] = 0.f;
    const float* r0 = As + (16 * mw + g) * 132;
    const float* r8 = r0 + 8 * 132;
#pragma unroll
    for (int ks = 0; ks < 16; ks++) {
        unsigned a[4];
        a[0] = __float_as_uint(r0[8 * ks + tid]);
        a[1] = __float_as_uint(r8[8 * ks + tid]);
        a[2] = __float_as_uint(r0[8 * ks + tid + 4]);
        a[3] = __float_as_uint(r8[8 * ks + tid + 4]);
#pragma unroll
        for (int nt = 0; nt < 4; nt++) {
            const float* kr = Ws + (nw * 32 + 8 * nt + g) * 132;
            unsigned b0 = __float_as_uint(kr[8 * ks + tid]);
            unsigned b1 = __float_as_uint(kr[8 * ks + tid + 4]);
            mma_tf32(c[nt], a, b0, b1);
        }
    }
    int ra = row0 + 16 * mw + g;
    int rb = ra + 8;
#pragma unroll
    for (int nt = 0; nt < 4; nt++) {
        int cb = col0 + nw * 32 + 8 * nt + 2 * tid;
        float2 bz = *reinterpret_cast<const float2*>(bias + cb);
        if (ra < M) {
            float2 v = make_float2(c[nt][0] + bz.x, c[nt][1] + bz.y);
            if (trunc) { v.x = tf32r(v.x); v.y = tf32r(v.y); }
            *reinterpret_cast<float2*>(C + (size_t)ra * N + cb) = v;
        }
        if (rb < M) {
            float2 v = make_float2(c[nt][2] + bz.x, c[nt][3] + bz.y);
            if (trunc) { v.x = tf32r(v.x); v.y = tf32r(v.y); }
            *reinterpret_cast<float2*>(C + (size_t)rb * N + cb) = v;
        }
    }
}

// GI/GH fused: y<6 -> GI col y, y>=6 -> GH col y-6
__global__ void __launch_bounds__(256, 2) k_gemm_g(
        const float* __restrict__ Wih, const float* __restrict__ Whh,
        const float* __restrict__ bih, const float* __restrict__ bhh) {
    int M = g_cnt[0];
    int row0 = blockIdx.x * 64;
    if (row0 >= M) return;
    int y = blockIdx.y;
    const float* A = (y < 6) ? g_X1 : g_H1;
    const float* W = (y < 6) ? Wih : Whh;
    const float* b = (y < 6) ? bih : bhh;
    float* C       = (y < 6) ? g_GI : g_GH;
    int col0 = (y % 6) * 64;
    extern __shared__ float sm[];
    gemm_tile_mma(A, W, b, C, M, 384, row0, col0, sm, false);
}

// Q/K/V fused: y=0 Q, y=1 K, y=2,3 V halves (outputs tf32-truncated)
__global__ void __launch_bounds__(256, 2) k_gemm_qkv(
        const float* __restrict__ Wq, const float* __restrict__ bq,
        const float* __restrict__ Wk, const float* __restrict__ bk,
        const float* __restrict__ Wv, const float* __restrict__ bv) {
    int M = g_cnt[1];
    int row0 = blockIdx.x * 64;
    if (row0 >= M) return;
    int y = blockIdx.y;
    const float *A, *W, *b; float* C; int N, col0;
    if (y == 0)      { A = g_Xq; W = Wq; b = bq; C = g_Q; N = 64;  col0 = 0; }
    else if (y == 1) { A = g_Xc; W = Wk; b = bk; C = g_K; N = 64;  col0 = 0; }
    else             { A = g_Xc; W = Wv; b = bv; C = g_V; N = 128; col0 = (y - 2) * 64; }
    extern __shared__ float sm[];
    gemm_tile_mma(A, W, b, C, M, N, row0, col0, sm, true);
}

// ----------------- k_gruc: GRU gates + scatter h_new + column max ----------
__global__ void k_gruc(const float* __restrict__ hid, float* __restrict__ outH) {
    int n1 = g_cnt[0];
    int t = threadIdx.x;
    int c = t & 127, sub = t >> 7;
    int s0 = blockIdx.x * 8;
    float mx = -FLT_MAX;
#pragma unroll
    for (int k = 0; k < 4; k++) {
        int s = s0 + sub * 4 + k;
        if (s < n1) {
            int row = g_idx1[s];
            const float* gi = g_GI + (size_t)s * 384;
            const float* gh = g_GH + (size_t)s * 384;
            float r  = 1.f / (1.f + __expf(-(gi[c] + gh[c])));
            float z  = 1.f / (1.f + __expf(-(gi[128 + c] + gh[128 + c])));
            float nn = tanhf(gi[256 + c] + r * gh[256 + c]);
            float h  = hid[(size_t)row * 128 + c];
            float o  = (1.f - z) * nn + z * h;
            outH[(size_t)row * 128 + c] = o;
            mx = fmaxf(mx, o);
        }
    }
    __shared__ float red[2][128];
    red[sub][c] = mx;
    __syncthreads();
    if (t < 128) atomicMax(&g_outacc[t], ford(fmaxf(red[0][t], red[1][t])));
}

// ----------------- k_flash: tf32 MMA no-rescale attention partials ---------
// 8 warps: warp w -> mw=w>>1 (16 q-rows), nw=w&1 (key-half for S, d-half for PV).
#define FLASH_SMEM ((2 * 64 * 68 + 64 * 136) * 4)
__global__ void __launch_bounds__(256, 2) k_flash() {
    int n23 = g_cnt[1];
    int qb = blockIdx.x / KSPLIT;
    int sp = blockIdx.x % KSPLIT;
    int q0 = qb * 64;
    if (q0 >= n23) return;
    extern __shared__ float sm[];
    float* Ps = sm;                       // [64][68], first used as Q staging
    float* Ks = sm + 64 * 68;             // [64][68]
    float* Vs = sm + 2 * 64 * 68;         // [64][136]
    int t = threadIdx.x;
    int w = t >> 5, lane = t & 31;
    int g = lane >> 2, tid = lane & 3;
    int mw = w >> 1, nw = w & 1;

    // stage Q (x 1/8 — exact exponent shift on tf32 values) into Ps
    for (int i4 = t; i4 < 64 * 16; i4 += 256) {
        int r = i4 >> 4, d4 = i4 & 15;
        float4 v = make_float4(0.f, 0.f, 0.f, 0.f);
        if (q0 + r < n23)
            v = reinterpret_cast<const float4*>(g_Q + (size_t)(q0 + r) * AT)[d4];
        v.x *= 0.125f; v.y *= 0.125f; v.z *= 0.125f; v.w *= 0.125f;
        *reinterpret_cast<float4*>(Ps + r * 68 + d4 * 4) = v;
    }
    __syncthreads();
    // preload Q fragments: qa[ks][0..3]
    unsigned qa[8][4];
    {
        const float* r0 = Ps + (16 * mw + g) * 68;
        const float* r8 = Ps + (16 * mw + g + 8) * 68;
#pragma unroll
        for (int ks = 0; ks < 8; ks++) {
            qa[ks][0] = __float_as_uint(r0[8 * ks + tid]);
            qa[ks][1] = __float_as_uint(r8[8 * ks + tid]);
            qa[ks][2] = __float_as_uint(r0[8 * ks + tid + 4]);
            qa[ks][3] = __float_as_uint(r8[8 * ks + tid + 4]);
        }
    }
    float o[8][4];
#pragma unroll
    for (int nt = 0; nt < 8; nt++)
#pragma unroll
        for (int i = 0; i < 4; i++) o[nt][i] = 0.f;
    float l0 = 0.f, l1 = 0.f;

    int nkb = (n23 + 63) >> 6;
    int chunk = (nkb + KSPLIT - 1) / KSPLIT;
    int kb0 = sp * chunk;
    int kb1 = min(kb0 + chunk, nkb);
    for (int kb = kb0; kb < kb1; kb++) {
        int k0 = kb << 6;
        __syncthreads();
        // load K tile [64][68]
        for (int i4 = t; i4 < 64 * 16; i4 += 256) {
            int r = i4 >> 4, d4 = i4 & 15;
            float4 v = make_float4(0.f, 0.f, 0.f, 0.f);
            if (k0 + r < n23)
                v = reinterpret_cast<const float4*>(g_K + (size_t)(k0 + r) * AT)[d4];
            *reinterpret_cast<float4*>(Ks + r * 68 + d4 * 4) = v;
        }
        // load V tile [64][136]
        for (int i4 = t; i4 < 64 * 32; i4 += 256) {
            int j = i4 >> 5, d4 = i4 & 31;
            float4 v = make_float4(0.f, 0.f, 0.f, 0.f);
            if (k0 + j < n23)
                v = reinterpret_cast<const float4*>(g_V + (size_t)(k0 + j) * HD)[d4];
            *reinterpret_cast<float4*>(Vs + j * 136 + d4 * 4) = v;
        }
        __syncthreads();
        // S = Qs K^T over this warp's 32-key half: 4 n-tiles x 8 k-steps
        float c[4][4];
#pragma unroll
        for (int nt = 0; nt < 4; nt++)
#pragma unroll
            for (int i = 0; i < 4; i++) c[nt][i] = 0.f;
#pragma unroll
        for (int nt = 0; nt < 4; nt++) {
            const float* kr = Ks + (nw * 32 + 8 * nt + g) * 68;
#pragma unroll
            for (int ks = 0; ks < 8; ks++) {
                unsigned b0 = __float_as_uint(kr[8 * ks + tid]);
                unsigned b1 = __float_as_uint(kr[8 * ks + tid + 4]);
                mma_tf32(c[nt], qa[ks], b0, b1);
            }
        }
        // P = exp(S), tail-masked; accumulate l; write tf32 P to Ps
#pragma unroll
        for (int nt = 0; nt < 4; nt++) {
            int key0 = k0 + nw * 32 + 8 * nt + 2 * tid;
            float p0 = (key0     < n23) ? exp_fast(c[nt][0]) : 0.f;
            float p1 = (key0 + 1 < n23) ? exp_fast(c[nt][1]) : 0.f;
            float p2 = (key0     < n23) ? exp_fast(c[nt][2]) : 0.f;
            float p3 = (key0 + 1 < n23) ? exp_fast(c[nt][3]) : 0.f;
            l0 += p0 + p1;
            l1 += p2 + p3;
            int col = nw * 32 + 8 * nt + 2 * tid;
            *reinterpret_cast<float2*>(Ps + (16 * mw + g) * 68 + col) =
                make_float2(tf32r(p0), tf32r(p1));
            *reinterpret_cast<float2*>(Ps + (16 * mw + g + 8) * 68 + col) =
                make_float2(tf32r(p2), tf32r(p3));
        }
        __syncthreads();
        // O += P V over this warp's 64-d half: 8 n-tiles x 8 k-steps
#pragma unroll
        for (int ks = 0; ks < 8; ks++) {
            unsigned pa[4];
            pa[0] = __float_as_uint(Ps[(16 * mw + g) * 68 + 8 * ks + tid]);
            pa[1] = __float_as_uint(Ps[(16 * mw + g + 8) * 68 + 8 * ks + tid]);
            pa[2] = __float_as_uint(Ps[(16 * mw + g) * 68 + 8 * ks + tid + 4]);
            pa[3] = __float_as_uint(Ps[(16 * mw + g + 8) * 68 + 8 * ks + tid + 4]);
            const float* vr0 = Vs + (8 * ks + tid) * 136 + nw * 64 + g;
            const float* vr1 = Vs + (8 * ks + tid + 4) * 136 + nw * 64 + g;
#pragma unroll
            for (int nt = 0; nt < 8; nt++) {
                unsigned b0 = __float_as_uint(vr0[8 * nt]);
                unsigned b1 = __float_as_uint(vr1[8 * nt]);
                mma_tf32(o[nt], pa, b0, b1);
            }
        }
    }
    // ---- epilogue ----
    l0 += __shfl_xor_sync(0xffffffffu, l0, 1);
    l0 += __shfl_xor_sync(0xffffffffu, l0, 2);
    l1 += __shfl_xor_sync(0xffffffffu, l1, 1);
    l1 += __shfl_xor_sync(0xffffffffu, l1, 2);
    float* lr = Ks;
    if (tid == 0) {
        lr[(16 * mw + g) * 2 + nw] = l0;
        lr[(16 * mw + g + 8) * 2 + nw] = l1;
    }
    __syncthreads();
    if (t < 64 && q0 + t < n23)
        g_L3[sp * CN + q0 + t] = lr[t * 2] + lr[t * 2 + 1];
    int r0 = q0 + 16 * mw + g;
    int r8 = r0 + 8;
    float* base0 = g_O3 + ((size_t)sp * CN + r0) * 128 + nw * 64 + 2 * tid;
    float* base8 = g_O3 + ((size_t)sp * CN + r8) * 128 + nw * 64 + 2 * tid;
#pragma unroll
    for (int nt = 0; nt < 8; nt++) {
        if (r0 < n23)
            *reinterpret_cast<float2*>(base0 + 8 * nt) = make_float2(o[nt][0], o[nt][1]);
        if (r8 < n23)
            *reinterpret_cast<float2*>(base8 + 8 * nt) = make_float2(o[nt][2], o[nt][3]);
    }
}

// ----------------- k_combine: sum splits, tanh, scatter, column max --------
__global__ void k_combine(float* __restrict__ outH) {
    int n23 = g_cnt[1];
    int t = threadIdx.x;
    int c = t & 127, sub = t >> 7;
    int s0 = blockIdx.x * 8;
    float mx = -FLT_MAX;
#pragma unroll
    for (int k = 0; k < 4; k++) {
        int sl = s0 + sub * 4 + k;
        if (sl < n23) {
            float lt = g_L3[sl] + g_L3[CN + sl] + g_L3[2 * CN + sl];
            float ov = g_O3[(size_t)sl * 128 + c]
                     + g_O3[((size_t)CN + sl) * 128 + c]
                     + g_O3[((size_t)2 * CN + sl) * 128 + c];
            float h = tanhf(ov / lt);
            int row = g_idx23[sl] & 0x3FFFFFFF;
            outH[(size_t)row * 128 + c] = h;
            mx = fmaxf(mx, h);
        }
    }
    __shared__ float red[2][128];
    red[sub][c] = mx;
    __syncthreads();
    if (t < 128) atomicMax(&g_outacc[t], ford(fmaxf(red[0][t], red[1][t])));
}

// ----------------- k_final: output vector --------------------------------
__global__ void k_final(float* __restrict__ out) {
    int t = threadIdx.x;
    out[t] = funord(g_outacc[t]) + g_tf[t];
}

// ---------------------------------------------------------------------------
extern "C" void kernel_launch(void* const* d_in, const int* in_sizes, int n_in,
                              void* d_out, int out_size) {
    const float* interval = (const float*)d_in[0];
    const float* co   = (const float*)d_in[1];
    const float* no_  = (const float*)d_in[2];
    const float* un   = (const float*)d_in[3];
    const float* hid  = (const float*)d_in[4];
    const int*   divided = (const int*)d_in[5];
    const float* W_ih = (const float*)d_in[6];
    const float* W_hh = (const float*)d_in[7];
    const float* b_ih = (const float*)d_in[8];
    const float* b_hh = (const float*)d_in[9];
    const float* Wq = (const float*)d_in[10];
    const float* bq = (const float*)d_in[11];
    const float* Wk = (const float*)d_in[12];
    const float* bk = (const float*)d_in[13];
    const float* Wv = (const float*)d_in[14];
    const float* bv = (const float*)d_in[15];
    const float* Wt = (const float*)d_in[16];
    const float* bt = (const float*)d_in[17];
    float* out  = (float*)d_out;
    float* outH = out + HD;   // h_new region: [12288, 128] after the 128-vec

    cudaFuncSetAttribute(k_gemm_g,   cudaFuncAttributeMaxDynamicSharedMemorySize, GEMM_SMEM);
    cudaFuncSetAttribute(k_gemm_qkv, cudaFuncAttributeMaxDynamicSharedMemorySize, GEMM_SMEM);
    cudaFuncSetAttribute(k_flash,    cudaFuncAttributeMaxDynamicSharedMemorySize, FLASH_SMEM);

    k_init<<<768, 512>>>(outH, interval, Wt, bt);
    k_compact<<<48, 256>>>(divided);
    k_gather<<<CN / 2, 256>>>(co, no_, un, hid);
    k_gemm_g<<<dim3(192, 12), 256, GEMM_SMEM>>>(W_ih, W_hh, b_ih, b_hh);
    k_gemm_qkv<<<dim3(192, 4), 256, GEMM_SMEM>>>(Wq, bq, Wk, bk, Wv, bv);
    k_gruc<<<CN / 8, 256>>>(hid, outH);
    k_flash<<<192 * KSPLIT, 256, FLASH_SMEM>>>();
    k_combine<<<CN / 8, 256>>>(outH);
    k_final<<<1, 128>>>(out);
}

// round 7
// speedup vs baseline: 2.9813x; 1.0210x over previous
#include <cuda_runtime.h>
#include <cuda_fp16.h>
#include <float.h>
#include <math.h>

#define CN 12288          // CODE_NUM
#define GD 128            // GRAPH
#define HD 128            // HIDDEN
#define AT 64             // ATT
#define KSPLIT 3

// ----------------- scratch (device globals; no allocation allowed) ---------
__device__ float g_Xq[CN * GD];     // gathered query-source rows (m23)
__device__ float g_Xc[CN * GD];     // gathered co_embeddings rows (m23)
__device__ float g_X1[CN * GD];     // gathered co_embeddings rows (m1)
__device__ float g_H1[CN * HD];     // gathered hidden rows (m1)
__device__ float g_GI[CN * 3 * HD]; // x @ W_ih^T + b_ih
__device__ float g_GH[CN * 3 * HD]; // h @ W_hh^T + b_hh
__device__ __half g_Qh[CN * AT];    // Q/8, fp16
__device__ __half g_Kh[CN * AT];    // K, fp16
__device__ __half g_VT[HD * CN];    // V transposed [d][slot], fp16
__device__ float g_O3[KSPLIT * CN * HD];  // per-split O partials
__device__ float g_L3[KSPLIT * CN];       // per-split l partials
__device__ int   g_idx1[CN];
__device__ int   g_idx23[CN];       // row | (m2 << 30)
__device__ int   g_cnt[2] = {0, 0}; // [0]=n1, [1]=n23 (reset by k_final)
__device__ unsigned g_outacc[HD];   // ordered-uint float max accumulator
__device__ float g_tf[HD];          // time features

__device__ __forceinline__ unsigned ford(float f) {
    unsigned u = __float_as_uint(f);
    return (u & 0x80000000u) ? ~u : (u | 0x80000000u);
}
__device__ __forceinline__ float funord(unsigned u) {
    return (u & 0x80000000u) ? __uint_as_float(u ^ 0x80000000u)
                             : __uint_as_float(~u);
}

// round-to-nearest tf32 (for MMA operand staging)
__device__ __forceinline__ float tf32r(float x) {
    unsigned u;
    asm("cvt.rna.tf32.f32 %0, %1;" : "=r"(u) : "f"(x));
    return __uint_as_float(u);
}

// m16n8k8 tf32 MMA, fp32 accumulate (projection GEMMs)
__device__ __forceinline__ void mma_tf32(float* c, const unsigned* a,
                                         unsigned b0, unsigned b1) {
    asm volatile(
        "mma.sync.aligned.m16n8k8.row.col.f32.tf32.tf32.f32 "
        "{%0,%1,%2,%3}, {%4,%5,%6,%7}, {%8,%9}, {%0,%1,%2,%3};"
        : "+f"(c[0]), "+f"(c[1]), "+f"(c[2]), "+f"(c[3])
        : "r"(a[0]), "r"(a[1]), "r"(a[2]), "r"(a[3]), "r"(b0), "r"(b1));
}

// m16n8k16 fp16 MMA, fp32 accumulate (flash)
__device__ __forceinline__ void mma_f16(float* c, const unsigned* a,
                                        unsigned b0, unsigned b1) {
    asm volatile(
        "mma.sync.aligned.m16n8k16.row.col.f32.f16.f16.f32 "
        "{%0,%1,%2,%3}, {%4,%5,%6,%7}, {%8,%9}, {%0,%1,%2,%3};"
        : "+f"(c[0]), "+f"(c[1]), "+f"(c[2]), "+f"(c[3])
        : "r"(a[0]), "r"(a[1]), "r"(a[2]), "r"(a[3]), "r"(b0), "r"(b1));
}

__device__ __forceinline__ unsigned pack_h2(float a, float b) {
    __half2 h = __floats2half2_rn(a, b);
    return *reinterpret_cast<unsigned*>(&h);
}

// FMA-pipe exp (scores bounded)
__device__ __forceinline__ float exp_fast(float x) {
    float y = fmaf(x, 1.44269504f, 12582912.0f);
    int   bz = __float_as_int(y);
    float n = y - 12582912.0f;
    float f = fmaf(x, 1.44269504f, -n);
    float p = 0.0013333558f;
    p = fmaf(p, f, 0.0096181291f);
    p = fmaf(p, f, 0.0555041087f);
    p = fmaf(p, f, 0.2402265069f);
    p = fmaf(p, f, 0.6931471806f);
    p = fmaf(p, f, 1.0f);
    float sc = __int_as_float((bz + (127 - 0x4B400000)) << 23);
    return p * sc;
}

// ----------------- k_init: zero h_new, init accumulators, tf, compact ------
// g_cnt is {0,0} at entry (static init on run 1, k_final reset afterwards),
// so the compact atomics here are safe in the same launch.
__global__ void k_init(float* __restrict__ outH, const float* __restrict__ interval,
                       const float* __restrict__ Wt, const float* __restrict__ bt,
                       const int* __restrict__ divided) {
    int i = blockIdx.x * 512 + threadIdx.x;            // 768*512 = 393216 float4
    reinterpret_cast<float4*>(outH)[i] = make_float4(0.f, 0.f, 0.f, 0.f);
    if (blockIdx.x == 0) {
        int t = threadIdx.x;
        if (t < HD) {
            float xt = 1.0f / logf(interval[0] + 2.7182818284590452f);
            g_tf[t] = tanhf(xt * Wt[t] + bt[t]);
            g_outacc[t] = ford(-FLT_MAX);
        }
    }
    if (blockIdx.x < 24) {
        int row = blockIdx.x * 512 + threadIdx.x;      // 24*512 = 12288
        int d0 = divided[row * 3 + 0];
        int d1 = divided[row * 3 + 1];
        int d2 = divided[row * 3 + 2];
        if (d0 > 0) {
            int pos = atomicAdd(&g_cnt[0], 1);
            g_idx1[pos] = row;
        }
        if (d1 > 0 || d2 > 0) {
            int pos = atomicAdd(&g_cnt[1], 1);
            g_idx23[pos] = row | ((d1 > 0) ? (1 << 30) : 0);
        }
    }
}

// ----------------- k_gather: compact rows into dense scratch ---------------
__global__ void k_gather(const float* __restrict__ co, const float* __restrict__ no_,
                         const float* __restrict__ un, const float* __restrict__ hid) {
    int s = blockIdx.x * 2 + (threadIdx.x >> 7);
    int lane = threadIdx.x & 127;
    int n23 = g_cnt[1], n1 = g_cnt[0];
    if (s < n23) {
        int e = g_idx23[s];
        int row = e & 0x3FFFFFFF;
        const float* src = (e & (1 << 30)) ? no_ : un;
        g_Xq[s * GD + lane] = src[row * GD + lane];
        g_Xc[s * GD + lane] = co[row * GD + lane];
    }
    if (s < n1) {
        int row = g_idx1[s];
        g_X1[s * GD + lane] = co[row * GD + lane];
        g_H1[s * HD + lane] = hid[row * HD + lane];
    }
}

// ----------------- k_gemm: all projections in one launch -------------------
// y 0..5:  GI col y      (A=X1, W=Wih)  fp32 out
// y 6..11: GH col y-6    (A=H1, W=Whh)  fp32 out
// y 12: Q (A=Xq, W=Wq) -> g_Qh half (x 1/8)
// y 13: K (A=Xc, W=Wk) -> g_Kh half
// y 14,15: V halves (A=Xc, W=Wv) -> g_VT half transposed
#define GEMM_SMEM (2 * 64 * 132 * 4)
__global__ void __launch_bounds__(256, 2) k_gemm(
        const float* __restrict__ Wih, const float* __restrict__ Whh,
        const float* __restrict__ bih, const float* __restrict__ bhh,
        const float* __restrict__ Wq,  const float* __restrict__ bq,
        const float* __restrict__ Wk,  const float* __restrict__ bk,
        const float* __restrict__ Wv,  const float* __restrict__ bv) {
    int y = blockIdx.y;
    const float *A, *W, *bias;
    int M, col0;
    if (y < 6)       { A = g_X1; W = Wih; bias = bih; M = g_cnt[0]; col0 = y * 64; }
    else if (y < 12) { A = g_H1; W = Whh; bias = bhh; M = g_cnt[0]; col0 = (y - 6) * 64; }
    else if (y == 12){ A = g_Xq; W = Wq;  bias = bq;  M = g_cnt[1]; col0 = 0; }
    else if (y == 13){ A = g_Xc; W = Wk;  bias = bk;  M = g_cnt[1]; col0 = 0; }
    else             { A = g_Xc; W = Wv;  bias = bv;  M = g_cnt[1]; col0 = (y - 14) * 64; }
    int row0 = blockIdx.x * 64;
    if (row0 >= M) return;

    extern __shared__ float sm[];
    float* As = sm;              // [64][132]
    float* Ws = sm + 64 * 132;   // [64][132]
    int t = threadIdx.x;
    for (int i4 = t; i4 < 64 * 32; i4 += 256) {
        int r = i4 >> 5, k4 = i4 & 31;
        float4 v = make_float4(0.f, 0.f, 0.f, 0.f);
        if (row0 + r < M)
            v = reinterpret_cast<const float4*>(A + (size_t)(row0 + r) * 128)[k4];
        v.x = tf32r(v.x); v.y = tf32r(v.y); v.z = tf32r(v.z); v.w = tf32r(v.w);
        *reinterpret_cast<float4*>(As + r * 132 + k4 * 4) = v;
    }
    for (int i4 = t; i4 < 64 * 32; i4 += 256) {
        int c = i4 >> 5, k4 = i4 & 31;
        float4 v = reinterpret_cast<const float4*>(W + (size_t)(col0 + c) * 128)[k4];
        v.x = tf32r(v.x); v.y = tf32r(v.y); v.z = tf32r(v.z); v.w = tf32r(v.w);
        *reinterpret_cast<float4*>(Ws + c * 132 + k4 * 4) = v;
    }
    __syncthreads();
    int w = t >> 5, lane = t & 31;
    int g = lane >> 2, tid = lane & 3;
    int mw = w >> 1, nw = w & 1;
    float c[4][4];
#pragma unroll
    for (int nt = 0; nt < 4; nt++)
#pragma unroll
        for (int i = 0; i < 4; i++) c[nt][i] = 0.f;
    const float* r0p = As + (16 * mw + g) * 132;
    const float* r8p = r0p + 8 * 132;
#pragma unroll
    for (int ks = 0; ks < 16; ks++) {
        unsigned a[4];
        a[0] = __float_as_uint(r0p[8 * ks + tid]);
        a[1] = __float_as_uint(r8p[8 * ks + tid]);
        a[2] = __float_as_uint(r0p[8 * ks + tid + 4]);
        a[3] = __float_as_uint(r8p[8 * ks + tid + 4]);
#pragma unroll
        for (int nt = 0; nt < 4; nt++) {
            const float* kr = Ws + (nw * 32 + 8 * nt + g) * 132;
            unsigned b0 = __float_as_uint(kr[8 * ks + tid]);
            unsigned b1 = __float_as_uint(kr[8 * ks + tid + 4]);
            mma_tf32(c[nt], a, b0, b1);
        }
    }
    int ra = row0 + 16 * mw + g;
    int rb = ra + 8;
    if (y < 12) {
        float* C = (y < 6) ? g_GI : g_GH;
#pragma unroll
        for (int nt = 0; nt < 4; nt++) {
            int cb = col0 + nw * 32 + 8 * nt + 2 * tid;
            float2 bz = *reinterpret_cast<const float2*>(bias + cb);
            if (ra < M)
                *reinterpret_cast<float2*>(C + (size_t)ra * 384 + cb) =
                    make_float2(c[nt][0] + bz.x, c[nt][1] + bz.y);
            if (rb < M)
                *reinterpret_cast<float2*>(C + (size_t)rb * 384 + cb) =
                    make_float2(c[nt][2] + bz.x, c[nt][3] + bz.y);
        }
    } else if (y <= 13) {
        __half* dst = (y == 12) ? g_Qh : g_Kh;
        float s = (y == 12) ? 0.125f : 1.0f;
#pragma unroll
        for (int nt = 0; nt < 4; nt++) {
            int cb = nw * 32 + 8 * nt + 2 * tid;
            float2 bz = *reinterpret_cast<const float2*>(bias + cb);
            if (ra < M) {
                __half2 h = __floats2half2_rn((c[nt][0] + bz.x) * s, (c[nt][1] + bz.y) * s);
                *reinterpret_cast<__half2*>(dst + (size_t)ra * 64 + cb) = h;
            }
            if (rb < M) {
                __half2 h = __floats2half2_rn((c[nt][2] + bz.x) * s, (c[nt][3] + bz.y) * s);
                *reinterpret_cast<__half2*>(dst + (size_t)rb * 64 + cb) = h;
            }
        }
    } else {
        // V -> g_VT transposed [d][slot]
#pragma unroll
        for (int nt = 0; nt < 4; nt++) {
            int cb = col0 + nw * 32 + 8 * nt + 2 * tid;
            float2 bz = *reinterpret_cast<const float2*>(bias + cb);
            if (ra < M) {
                g_VT[(size_t)cb * CN + ra]       = __float2half(c[nt][0] + bz.x);
                g_VT[(size_t)(cb + 1) * CN + ra] = __float2half(c[nt][1] + bz.y);
            }
            if (rb < M) {
                g_VT[(size_t)cb * CN + rb]       = __float2half(c[nt][2] + bz.x);
                g_VT[(size_t)(cb + 1) * CN + rb] = __float2half(c[nt][3] + bz.y);
            }
        }
    }
}

// ----------------- k_gruc: GRU gates + scatter h_new + column max ----------
__global__ void k_gruc(const float* __restrict__ hid, float* __restrict__ outH) {
    int n1 = g_cnt[0];
    int t = threadIdx.x;
    int c = t & 127, sub = t >> 7;
    int s0 = blockIdx.x * 8;
    float mx = -FLT_MAX;
#pragma unroll
    for (int k = 0; k < 4; k++) {
        int s = s0 + sub * 4 + k;
        if (s < n1) {
            int row = g_idx1[s];
            const float* gi = g_GI + (size_t)s * 384;
            const float* gh = g_GH + (size_t)s * 384;
            float r  = 1.f / (1.f + __expf(-(gi[c] + gh[c])));
            float z  = 1.f / (1.f + __expf(-(gi[128 + c] + gh[128 + c])));
            float nn = tanhf(gi[256 + c] + r * gh[256 + c]);
            float h  = hid[(size_t)row * 128 + c];
            float o  = (1.f - z) * nn + z * h;
            outH[(size_t)row * 128 + c] = o;
            mx = fmaxf(mx, o);
        }
    }
    __shared__ float red[2][128];
    red[sub][c] = mx;
    __syncthreads();
    if (t < 128) atomicMax(&g_outacc[t], ford(fmaxf(red[0][t], red[1][t])));
}

// ----------------- k_flash: fp16 MMA, BM=128, P kept in registers ----------
// 8 warps; warp w owns q-rows 16w..16w+15, computes S over all 64 keys of the
// tile, exps in registers, packs accumulator pairs directly into m16n8k16
// A-fragments (layouts match exactly), then PV over all 128 d.
#define FLASH_SMEM ((128 * 72 + 64 * 72 + 128 * 72) * 2)
__global__ void __launch_bounds__(256, 1) k_flash() {
    int n23 = g_cnt[1];
    int qb = blockIdx.x / KSPLIT;
    int sp = blockIdx.x % KSPLIT;
    int q0 = qb * 128;
    if (q0 >= n23) return;
    extern __shared__ __half smh[];
    __half* Qs  = smh;                       // [128][72]
    __half* Ks  = smh + 128 * 72;            // [64][72]
    __half* VTs = smh + 128 * 72 + 64 * 72;  // [128][72]
    int t = threadIdx.x;
    int w = t >> 5, lane = t & 31;
    int g = lane >> 2, tid = lane & 3;

    // stage Q tile (zero-padded tail rows)
    for (int i = t; i < 128 * 8; i += 256) {
        int r = i >> 3, c8 = i & 7;
        uint4 v = make_uint4(0u, 0u, 0u, 0u);
        if (q0 + r < n23)
            v = *reinterpret_cast<const uint4*>(g_Qh + (size_t)(q0 + r) * AT + 8 * c8);
        *reinterpret_cast<uint4*>(Qs + r * 72 + 8 * c8) = v;
    }
    __syncthreads();
    // preload Q A-fragments (4 k-chunks of 16)
    unsigned qa[4][4];
    {
        const __half* r0 = Qs + (16 * w + g) * 72;
        const __half* r8 = Qs + (16 * w + g + 8) * 72;
#pragma unroll
        for (int ks = 0; ks < 4; ks++) {
            qa[ks][0] = *reinterpret_cast<const unsigned*>(r0 + 16 * ks + 2 * tid);
            qa[ks][1] = *reinterpret_cast<const unsigned*>(r8 + 16 * ks + 2 * tid);
            qa[ks][2] = *reinterpret_cast<const unsigned*>(r0 + 16 * ks + 2 * tid + 8);
            qa[ks][3] = *reinterpret_cast<const unsigned*>(r8 + 16 * ks + 2 * tid + 8);
        }
    }
    float o[16][4];
#pragma unroll
    for (int nt = 0; nt < 16; nt++)
#pragma unroll
        for (int i = 0; i < 4; i++) o[nt][i] = 0.f;
    float l0 = 0.f, l1 = 0.f;

    int nkb = (n23 + 63) >> 6;
    int chunk = (nkb + KSPLIT - 1) / KSPLIT;
    int kb0 = sp * chunk;
    int kb1 = min(kb0 + chunk, nkb);
    for (int kb = kb0; kb < kb1; kb++) {
        int k0 = kb << 6;
        __syncthreads();
        // K tile [64][72]
        for (int i = t; i < 64 * 8; i += 256) {
            int r = i >> 3, c8 = i & 7;
            uint4 v = make_uint4(0u, 0u, 0u, 0u);
            if (k0 + r < n23)
                v = *reinterpret_cast<const uint4*>(g_Kh + (size_t)(k0 + r) * AT + 8 * c8);
            *reinterpret_cast<uint4*>(Ks + r * 72 + 8 * c8) = v;
        }
        // V^T tile [128][72] (zero any key >= n23: garbage*0 would still NaN)
        for (int i = t; i < 128 * 8; i += 256) {
            int d = i >> 3, j8 = i & 7;
            int col = k0 + 8 * j8;
            uint4 v = make_uint4(0u, 0u, 0u, 0u);
            if (col + 8 <= n23) {
                v = *reinterpret_cast<const uint4*>(g_VT + (size_t)d * CN + col);
            } else if (col < n23) {
                v = *reinterpret_cast<const uint4*>(g_VT + (size_t)d * CN + col);
                __half* hv = reinterpret_cast<__half*>(&v);
#pragma unroll
                for (int e = 0; e < 8; e++)
                    if (col + e >= n23) hv[e] = __float2half(0.f);
            }
            *reinterpret_cast<uint4*>(VTs + d * 72 + 8 * j8) = v;
        }
        __syncthreads();
        // S = Q K^T : 8 key-tiles x 4 k-chunks
        float c[8][4];
#pragma unroll
        for (int nt = 0; nt < 8; nt++)
#pragma unroll
            for (int i = 0; i < 4; i++) c[nt][i] = 0.f;
#pragma unroll
        for (int nt = 0; nt < 8; nt++) {
            const __half* kr = Ks + (8 * nt + g) * 72;
#pragma unroll
            for (int ks = 0; ks < 4; ks++) {
                unsigned b0 = *reinterpret_cast<const unsigned*>(kr + 16 * ks + 2 * tid);
                unsigned b1 = *reinterpret_cast<const unsigned*>(kr + 16 * ks + 2 * tid + 8);
                mma_f16(c[nt], qa[ks], b0, b1);
            }
        }
        // P = exp(S) in registers, packed straight into PV A-fragments
        unsigned pa[4][4];
#pragma unroll
        for (int nt = 0; nt < 8; nt++) {
            int key0 = k0 + 8 * nt + 2 * tid;
            float p0 = (key0     < n23) ? exp_fast(c[nt][0]) : 0.f;
            float p1 = (key0 + 1 < n23) ? exp_fast(c[nt][1]) : 0.f;
            float p2 = (key0     < n23) ? exp_fast(c[nt][2]) : 0.f;
            float p3 = (key0 + 1 < n23) ? exp_fast(c[nt][3]) : 0.f;
            l0 += p0 + p1;
            l1 += p2 + p3;
            int kc = nt >> 1, h = (nt & 1) * 2;
            pa[kc][h]     = pack_h2(p0, p1);
            pa[kc][h + 1] = pack_h2(p2, p3);
        }
        // O += P V : 16 d-tiles x 4 k-chunks
#pragma unroll
        for (int kc = 0; kc < 4; kc++) {
#pragma unroll
            for (int nt = 0; nt < 16; nt++) {
                const __half* vr = VTs + (8 * nt + g) * 72;
                unsigned b0 = *reinterpret_cast<const unsigned*>(vr + 16 * kc + 2 * tid);
                unsigned b1 = *reinterpret_cast<const unsigned*>(vr + 16 * kc + 2 * tid + 8);
                mma_f16(o[nt], pa[kc], b0, b1);
            }
        }
    }
    // ---- epilogue ----
    l0 += __shfl_xor_sync(0xffffffffu, l0, 1);
    l0 += __shfl_xor_sync(0xffffffffu, l0, 2);
    l1 += __shfl_xor_sync(0xffffffffu, l1, 1);
    l1 += __shfl_xor_sync(0xffffffffu, l1, 2);
    __syncthreads();                   // all S reads of Ks done before alias
    float* lr = reinterpret_cast<float*>(Ks);
    if (tid == 0) {
        lr[16 * w + g] = l0;
        lr[16 * w + g + 8] = l1;
    }
    __syncthreads();
    if (t < 128 && q0 + t < n23)
        g_L3[sp * CN + q0 + t] = lr[t];
    int r0 = q0 + 16 * w + g;
    int r8 = r0 + 8;
    float* base0 = g_O3 + ((size_t)sp * CN + r0) * 128 + 2 * tid;
    float* base8 = g_O3 + ((size_t)sp * CN + r8) * 128 + 2 * tid;
#pragma unroll
    for (int nt = 0; nt < 16; nt++) {
        if (r0 < n23)
            *reinterpret_cast<float2*>(base0 + 8 * nt) = make_float2(o[nt][0], o[nt][1]);
        if (r8 < n23)
            *reinterpret_cast<float2*>(base8 + 8 * nt) = make_float2(o[nt][2], o[nt][3]);
    }
}

// ----------------- k_combine: sum splits, tanh, scatter, column max --------
__global__ void k_combine(float* __restrict__ outH) {
    int n23 = g_cnt[1];
    int t = threadIdx.x;
    int c = t & 127, sub = t >> 7;
    int s0 = blockIdx.x * 8;
    float mx = -FLT_MAX;
#pragma unroll
    for (int k = 0; k < 4; k++) {
        int sl = s0 + sub * 4 + k;
        if (sl < n23) {
            float lt = g_L3[sl] + g_L3[CN + sl] + g_L3[2 * CN + sl];
            float ov = g_O3[(size_t)sl * 128 + c]
                     + g_O3[((size_t)CN + sl) * 128 + c]
                     + g_O3[((size_t)2 * CN + sl) * 128 + c];
            float h = tanhf(ov / lt);
            int row = g_idx23[sl] & 0x3FFFFFFF;
            outH[(size_t)row * 128 + c] = h;
            mx = fmaxf(mx, h);
        }
    }
    __shared__ float red[2][128];
    red[sub][c] = mx;
    __syncthreads();
    if (t < 128) atomicMax(&g_outacc[t], ford(fmaxf(red[0][t], red[1][t])));
}

// ----------------- k_final: output vector + reset counters for next run ----
__global__ void k_final(float* __restrict__ out) {
    int t = threadIdx.x;
    out[t] = funord(g_outacc[t]) + g_tf[t];
    if (t == 0) { g_cnt[0] = 0; g_cnt[1] = 0; }
}

// ---------------------------------------------------------------------------
extern "C" void kernel_launch(void* const* d_in, const int* in_sizes, int n_in,
                              void* d_out, int out_size) {
    const float* interval = (const float*)d_in[0];
    const float* co   = (const float*)d_in[1];
    const float* no_  = (const float*)d_in[2];
    const float* un   = (const float*)d_in[3];
    const float* hid  = (const float*)d_in[4];
    const int*   divided = (const int*)d_in[5];
    const float* W_ih = (const float*)d_in[6];
    const float* W_hh = (const float*)d_in[7];
    const float* b_ih = (const float*)d_in[8];
    const float* b_hh = (const float*)d_in[9];
    const float* Wq = (const float*)d_in[10];
    const float* bq = (const float*)d_in[11];
    const float* Wk = (const float*)d_in[12];
    const float* bk = (const float*)d_in[13];
    const float* Wv = (const float*)d_in[14];
    const float* bv = (const float*)d_in[15];
    const float* Wt = (const float*)d_in[16];
    const float* bt = (const float*)d_in[17];
    float* out  = (float*)d_out;
    float* outH = out + HD;   // h_new region: [12288, 128] after the 128-vec

    cudaFuncSetAttribute(k_gemm,  cudaFuncAttributeMaxDynamicSharedMemorySize, GEMM_SMEM);
    cudaFuncSetAttribute(k_flash, cudaFuncAttributeMaxDynamicSharedMemorySize, FLASH_SMEM);

    k_init<<<768, 512>>>(outH, interval, Wt, bt, divided);
    k_gather<<<CN / 2, 256>>>(co, no_, un, hid);
    k_gemm<<<dim3(192, 16), 256, GEMM_SMEM>>>(W_ih, W_hh, b_ih, b_hh,
                                              Wq, bq, Wk, bk, Wv, bv);
    k_flash<<<(CN / 128) * KSPLIT, 256, FLASH_SMEM>>>();
    k_gruc<<<CN / 8, 256>>>(hid, outH);
    k_combine<<<CN / 8, 256>>>(outH);
    k_final<<<1, 128>>>(out);
}

// round 8
// speedup vs baseline: 3.6684x; 1.2305x over previous
#include <cuda_runtime.h>
#include <cuda_fp16.h>
#include <float.h>
#include <math.h>

#define CN 12288          // CODE_NUM
#define GD 128            // GRAPH
#define HD 128            // HIDDEN
#define AT 64             // ATT
#define KSPLIT 4

// ----------------- scratch (device globals; no allocation allowed) ---------
__device__ float g_Xq[CN * GD];     // gathered query-source rows (m23)
__device__ float g_Xc[CN * GD];     // gathered co_embeddings rows (m23)
__device__ float g_X1[CN * GD];     // gathered co_embeddings rows (m1)
__device__ float g_H1[CN * HD];     // gathered hidden rows (m1)
__device__ float g_GI[CN * 3 * HD]; // x @ W_ih^T + b_ih
__device__ float g_GH[CN * 3 * HD]; // h @ W_hh^T + b_hh
__device__ __half g_Qh[CN * AT];    // Q/8, fp16 (slots >= n23 stay zero)
__device__ __half g_Kh[CN * AT];    // K, fp16  (slots >= n23 stay zero)
__device__ __half g_VT[HD * CN];    // V transposed [d][slot], fp16 (tail zero)
__device__ float g_O3[KSPLIT * CN * HD];  // per-split O partials
__device__ float g_L3[KSPLIT * CN];       // per-split l partials
__device__ int   g_idx1[CN];
__device__ int   g_idx23[CN];       // row | (m2 << 30)
__device__ int   g_cnt[2] = {0, 0}; // [0]=n1, [1]=n23 (reset by k_final)
__device__ unsigned g_outacc[HD];   // ordered-uint float max accumulator
__device__ float g_tf[HD];          // time features

__device__ __forceinline__ unsigned ford(float f) {
    unsigned u = __float_as_uint(f);
    return (u & 0x80000000u) ? ~u : (u | 0x80000000u);
}
__device__ __forceinline__ float funord(unsigned u) {
    return (u & 0x80000000u) ? __uint_as_float(u ^ 0x80000000u)
                             : __uint_as_float(~u);
}

// round-to-nearest tf32 (for MMA operand staging)
__device__ __forceinline__ float tf32r(float x) {
    unsigned u;
    asm("cvt.rna.tf32.f32 %0, %1;" : "=r"(u) : "f"(x));
    return __uint_as_float(u);
}

// m16n8k8 tf32 MMA, fp32 accumulate (projection GEMMs)
__device__ __forceinline__ void mma_tf32(float* c, const unsigned* a,
                                         unsigned b0, unsigned b1) {
    asm volatile(
        "mma.sync.aligned.m16n8k8.row.col.f32.tf32.tf32.f32 "
        "{%0,%1,%2,%3}, {%4,%5,%6,%7}, {%8,%9}, {%0,%1,%2,%3};"
        : "+f"(c[0]), "+f"(c[1]), "+f"(c[2]), "+f"(c[3])
        : "r"(a[0]), "r"(a[1]), "r"(a[2]), "r"(a[3]), "r"(b0), "r"(b1));
}

// m16n8k16 fp16 MMA, fp32 accumulate (flash)
__device__ __forceinline__ void mma_f16(float* c, const unsigned* a,
                                        unsigned b0, unsigned b1) {
    asm volatile(
        "mma.sync.aligned.m16n8k16.row.col.f32.f16.f16.f32 "
        "{%0,%1,%2,%3}, {%4,%5,%6,%7}, {%8,%9}, {%0,%1,%2,%3};"
        : "+f"(c[0]), "+f"(c[1]), "+f"(c[2]), "+f"(c[3])
        : "r"(a[0]), "r"(a[1]), "r"(a[2]), "r"(a[3]), "r"(b0), "r"(b1));
}

__device__ __forceinline__ unsigned pack_h2(float a, float b) {
    __half2 h = __floats2half2_rn(a, b);
    return *reinterpret_cast<unsigned*>(&h);
}

// FMA-pipe exp (scores bounded)
__device__ __forceinline__ float exp_fast(float x) {
    float y = fmaf(x, 1.44269504f, 12582912.0f);
    int   bz = __float_as_int(y);
    float n = y - 12582912.0f;
    float f = fmaf(x, 1.44269504f, -n);
    float p = 0.0013333558f;
    p = fmaf(p, f, 0.0096181291f);
    p = fmaf(p, f, 0.0555041087f);
    p = fmaf(p, f, 0.2402265069f);
    p = fmaf(p, f, 0.6931471806f);
    p = fmaf(p, f, 1.0f);
    float sc = __int_as_float((bz + (127 - 0x4B400000)) << 23);
    return p * sc;
}

// ----------------- k_init: zero h_new, init accumulators, tf, compact ------
__global__ void k_init(float* __restrict__ outH, const float* __restrict__ interval,
                       const float* __restrict__ Wt, const float* __restrict__ bt,
                       const int* __restrict__ divided) {
    int i = blockIdx.x * 512 + threadIdx.x;            // 768*512 = 393216 float4
    reinterpret_cast<float4*>(outH)[i] = make_float4(0.f, 0.f, 0.f, 0.f);
    if (blockIdx.x == 0) {
        int t = threadIdx.x;
        if (t < HD) {
            float xt = 1.0f / logf(interval[0] + 2.7182818284590452f);
            g_tf[t] = tanhf(xt * Wt[t] + bt[t]);
            g_outacc[t] = ford(-FLT_MAX);
        }
    }
    if (blockIdx.x < 24) {
        int row = blockIdx.x * 512 + threadIdx.x;      // 24*512 = 12288
        int d0 = divided[row * 3 + 0];
        int d1 = divided[row * 3 + 1];
        int d2 = divided[row * 3 + 2];
        if (d0 > 0) {
            int pos = atomicAdd(&g_cnt[0], 1);
            g_idx1[pos] = row;
        }
        if (d1 > 0 || d2 > 0) {
            int pos = atomicAdd(&g_cnt[1], 1);
            g_idx23[pos] = row | ((d1 > 0) ? (1 << 30) : 0);
        }
    }
}

// ----------------- k_gather: compact rows into dense scratch ---------------
__global__ void k_gather(const float* __restrict__ co, const float* __restrict__ no_,
                         const float* __restrict__ un, const float* __restrict__ hid) {
    int s = blockIdx.x * 2 + (threadIdx.x >> 7);
    int lane = threadIdx.x & 127;
    int n23 = g_cnt[1], n1 = g_cnt[0];
    if (s < n23) {
        int e = g_idx23[s];
        int row = e & 0x3FFFFFFF;
        const float* src = (e & (1 << 30)) ? no_ : un;
        g_Xq[s * GD + lane] = src[row * GD + lane];
        g_Xc[s * GD + lane] = co[row * GD + lane];
    }
    if (s < n1) {
        int row = g_idx1[s];
        g_X1[s * GD + lane] = co[row * GD + lane];
        g_H1[s * HD + lane] = hid[row * HD + lane];
    }
}

// ----------------- k_gemm: all projections in one launch -------------------
// y 0..5:  GI col y      (A=X1, W=Wih)  fp32 out
// y 6..11: GH col y-6    (A=H1, W=Whh)  fp32 out
// y 12: Q (A=Xq, W=Wq) -> g_Qh half (x 1/8)
// y 13: K (A=Xc, W=Wk) -> g_Kh half
// y 14,15: V halves (A=Xc, W=Wv) -> g_VT half transposed
#define GEMM_SMEM (2 * 64 * 132 * 4)
__global__ void __launch_bounds__(256, 2) k_gemm(
        const float* __restrict__ Wih, const float* __restrict__ Whh,
        const float* __restrict__ bih, const float* __restrict__ bhh,
        const float* __restrict__ Wq,  const float* __restrict__ bq,
        const float* __restrict__ Wk,  const float* __restrict__ bk,
        const float* __restrict__ Wv,  const float* __restrict__ bv) {
    int y = blockIdx.y;
    const float *A, *W, *bias;
    int M, col0;
    if (y < 6)       { A = g_X1; W = Wih; bias = bih; M = g_cnt[0]; col0 = y * 64; }
    else if (y < 12) { A = g_H1; W = Whh; bias = bhh; M = g_cnt[0]; col0 = (y - 6) * 64; }
    else if (y == 12){ A = g_Xq; W = Wq;  bias = bq;  M = g_cnt[1]; col0 = 0; }
    else if (y == 13){ A = g_Xc; W = Wk;  bias = bk;  M = g_cnt[1]; col0 = 0; }
    else             { A = g_Xc; W = Wv;  bias = bv;  M = g_cnt[1]; col0 = (y - 14) * 64; }
    int row0 = blockIdx.x * 64;
    if (row0 >= M) return;

    extern __shared__ float sm[];
    float* As = sm;              // [64][132]
    float* Ws = sm + 64 * 132;   // [64][132]
    int t = threadIdx.x;
    for (int i4 = t; i4 < 64 * 32; i4 += 256) {
        int r = i4 >> 5, k4 = i4 & 31;
        float4 v = make_float4(0.f, 0.f, 0.f, 0.f);
        if (row0 + r < M)
            v = reinterpret_cast<const float4*>(A + (size_t)(row0 + r) * 128)[k4];
        v.x = tf32r(v.x); v.y = tf32r(v.y); v.z = tf32r(v.z); v.w = tf32r(v.w);
        *reinterpret_cast<float4*>(As + r * 132 + k4 * 4) = v;
    }
    for (int i4 = t; i4 < 64 * 32; i4 += 256) {
        int c = i4 >> 5, k4 = i4 & 31;
        float4 v = reinterpret_cast<const float4*>(W + (size_t)(col0 + c) * 128)[k4];
        v.x = tf32r(v.x); v.y = tf32r(v.y); v.z = tf32r(v.z); v.w = tf32r(v.w);
        *reinterpret_cast<float4*>(Ws + c * 132 + k4 * 4) = v;
    }
    __syncthreads();
    int w = t >> 5, lane = t & 31;
    int g = lane >> 2, tid = lane & 3;
    int mw = w >> 1, nw = w & 1;
    float c[4][4];
#pragma unroll
    for (int nt = 0; nt < 4; nt++)
#pragma unroll
        for (int i = 0; i < 4; i++) c[nt][i] = 0.f;
    const float* r0p = As + (16 * mw + g) * 132;
    const float* r8p = r0p + 8 * 132;
#pragma unroll
    for (int ks = 0; ks < 16; ks++) {
        unsigned a[4];
        a[0] = __float_as_uint(r0p[8 * ks + tid]);
        a[1] = __float_as_uint(r8p[8 * ks + tid]);
        a[2] = __float_as_uint(r0p[8 * ks + tid + 4]);
        a[3] = __float_as_uint(r8p[8 * ks + tid + 4]);
#pragma unroll
        for (int nt = 0; nt < 4; nt++) {
            const float* kr = Ws + (nw * 32 + 8 * nt + g) * 132;
            unsigned b0 = __float_as_uint(kr[8 * ks + tid]);
            unsigned b1 = __float_as_uint(kr[8 * ks + tid + 4]);
            mma_tf32(c[nt], a, b0, b1);
        }
    }
    int ra = row0 + 16 * mw + g;
    int rb = ra + 8;
    if (y < 12) {
        float* C = (y < 6) ? g_GI : g_GH;
#pragma unroll
        for (int nt = 0; nt < 4; nt++) {
            int cb = col0 + nw * 32 + 8 * nt + 2 * tid;
            float2 bz = *reinterpret_cast<const float2*>(bias + cb);
            if (ra < M)
                *reinterpret_cast<float2*>(C + (size_t)ra * 384 + cb) =
                    make_float2(c[nt][0] + bz.x, c[nt][1] + bz.y);
            if (rb < M)
                *reinterpret_cast<float2*>(C + (size_t)rb * 384 + cb) =
                    make_float2(c[nt][2] + bz.x, c[nt][3] + bz.y);
        }
    } else if (y <= 13) {
        __half* dst = (y == 12) ? g_Qh : g_Kh;
        float s = (y == 12) ? 0.125f : 1.0f;
#pragma unroll
        for (int nt = 0; nt < 4; nt++) {
            int cb = nw * 32 + 8 * nt + 2 * tid;
            float2 bz = *reinterpret_cast<const float2*>(bias + cb);
            if (ra < M) {
                __half2 h = __floats2half2_rn((c[nt][0] + bz.x) * s, (c[nt][1] + bz.y) * s);
                *reinterpret_cast<__half2*>(dst + (size_t)ra * 64 + cb) = h;
            }
            if (rb < M) {
                __half2 h = __floats2half2_rn((c[nt][2] + bz.x) * s, (c[nt][3] + bz.y) * s);
                *reinterpret_cast<__half2*>(dst + (size_t)rb * 64 + cb) = h;
            }
        }
    } else {
        // V -> g_VT transposed [d][slot]
#pragma unroll
        for (int nt = 0; nt < 4; nt++) {
            int cb = col0 + nw * 32 + 8 * nt + 2 * tid;
            float2 bz = *reinterpret_cast<const float2*>(bias + cb);
            if (ra < M) {
                g_VT[(size_t)cb * CN + ra]       = __float2half(c[nt][0] + bz.x);
                g_VT[(size_t)(cb + 1) * CN + ra] = __float2half(c[nt][1] + bz.y);
            }
            if (rb < M) {
                g_VT[(size_t)cb * CN + rb]       = __float2half(c[nt][2] + bz.x);
                g_VT[(size_t)(cb + 1) * CN + rb] = __float2half(c[nt][3] + bz.y);
            }
        }
    }
}

// ----------------- k_gruc: GRU gates + scatter h_new + column max ----------
__global__ void k_gruc(const float* __restrict__ hid, float* __restrict__ outH) {
    int n1 = g_cnt[0];
    int t = threadIdx.x;
    int c = t & 127, sub = t >> 7;
    int s0 = blockIdx.x * 8;
    float mx = -FLT_MAX;
#pragma unroll
    for (int k = 0; k < 4; k++) {
        int s = s0 + sub * 4 + k;
        if (s < n1) {
            int row = g_idx1[s];
            const float* gi = g_GI + (size_t)s * 384;
            const float* gh = g_GH + (size_t)s * 384;
            float r  = 1.f / (1.f + __expf(-(gi[c] + gh[c])));
            float z  = 1.f / (1.f + __expf(-(gi[128 + c] + gh[128 + c])));
            float nn = tanhf(gi[256 + c] + r * gh[256 + c]);
            float h  = hid[(size_t)row * 128 + c];
            float o  = (1.f - z) * nn + z * h;
            outH[(size_t)row * 128 + c] = o;
            mx = fmaxf(mx, o);
        }
    }
    __shared__ float red[2][128];
    red[sub][c] = mx;
    __syncthreads();
    if (t < 128) atomicMax(&g_outacc[t], ford(fmaxf(red[0][t], red[1][t])));
}

// ----------------- k_flash: fp16 MMA, BM=64, 4 warps, 3 CTAs/SM ------------
// Warp w owns q-rows 16w..16w+15, all 64 keys of the tile, all 128 d.
// P lives in registers (S-accumulator layout == m16n8k16 A-fragment layout).
// Tile loads are unconditional: g_Qh/g_Kh/g_VT tails are zero by construction.
#define FLASH_SMEM ((64 * 72 + 64 * 72 + 128 * 72) * 2)
__global__ void __launch_bounds__(128, 3) k_flash() {
    int n23 = g_cnt[1];
    int qb = blockIdx.x / KSPLIT;
    int sp = blockIdx.x % KSPLIT;
    int q0 = qb * 64;
    if (q0 >= n23) return;
    extern __shared__ __half smh[];
    __half* Qs  = smh;                      // [64][72]
    __half* Ks  = smh + 64 * 72;            // [64][72]
    __half* VTs = smh + 2 * 64 * 72;        // [128][72]
    int t = threadIdx.x;
    int w = t >> 5, lane = t & 31;
    int g = lane >> 2, tid = lane & 3;

    // stage Q tile (rows always in-bounds of the array; tail rows are zero)
    for (int i = t; i < 64 * 8; i += 128) {
        int r = i >> 3, c8 = i & 7;
        *reinterpret_cast<uint4*>(Qs + r * 72 + 8 * c8) =
            *reinterpret_cast<const uint4*>(g_Qh + (size_t)(q0 + r) * AT + 8 * c8);
    }
    __syncthreads();
    // preload Q A-fragments (4 k-chunks of 16)
    unsigned qa[4][4];
    {
        const __half* r0 = Qs + (16 * w + g) * 72;
        const __half* r8 = Qs + (16 * w + g + 8) * 72;
#pragma unroll
        for (int ks = 0; ks < 4; ks++) {
            qa[ks][0] = *reinterpret_cast<const unsigned*>(r0 + 16 * ks + 2 * tid);
            qa[ks][1] = *reinterpret_cast<const unsigned*>(r8 + 16 * ks + 2 * tid);
            qa[ks][2] = *reinterpret_cast<const unsigned*>(r0 + 16 * ks + 2 * tid + 8);
            qa[ks][3] = *reinterpret_cast<const unsigned*>(r8 + 16 * ks + 2 * tid + 8);
        }
    }
    float o[16][4];
#pragma unroll
    for (int nt = 0; nt < 16; nt++)
#pragma unroll
        for (int i = 0; i < 4; i++) o[nt][i] = 0.f;
    float l0 = 0.f, l1 = 0.f;

    int nkb = (n23 + 63) >> 6;
    int chunk = (nkb + KSPLIT - 1) / KSPLIT;
    int kb0 = sp * chunk;
    int kb1 = min(kb0 + chunk, nkb);
    for (int kb = kb0; kb < kb1; kb++) {
        int k0 = kb << 6;
        __syncthreads();
        // K tile [64][72] — unconditional (tail rows zero in gmem)
        for (int i = t; i < 64 * 8; i += 128) {
            int r = i >> 3, c8 = i & 7;
            *reinterpret_cast<uint4*>(Ks + r * 72 + 8 * c8) =
                *reinterpret_cast<const uint4*>(g_Kh + (size_t)(k0 + r) * AT + 8 * c8);
        }
        // V^T tile [128][72] — unconditional (tail cols zero in gmem)
        for (int i = t; i < 128 * 8; i += 128) {
            int d = i >> 3, j8 = i & 7;
            *reinterpret_cast<uint4*>(VTs + d * 72 + 8 * j8) =
                *reinterpret_cast<const uint4*>(g_VT + (size_t)d * CN + k0 + 8 * j8);
        }
        __syncthreads();
        // S = Q K^T : 8 key-tiles x 4 k-chunks
        float c[8][4];
#pragma unroll
        for (int nt = 0; nt < 8; nt++)
#pragma unroll
            for (int i = 0; i < 4; i++) c[nt][i] = 0.f;
#pragma unroll
        for (int nt = 0; nt < 8; nt++) {
            const __half* kr = Ks + (8 * nt + g) * 72;
#pragma unroll
            for (int ks = 0; ks < 4; ks++) {
                unsigned b0 = *reinterpret_cast<const unsigned*>(kr + 16 * ks + 2 * tid);
                unsigned b1 = *reinterpret_cast<const unsigned*>(kr + 16 * ks + 2 * tid + 8);
                mma_f16(c[nt], qa[ks], b0, b1);
            }
        }
        // P = exp(S) in registers, packed straight into PV A-fragments
        unsigned pa[4][4];
#pragma unroll
        for (int nt = 0; nt < 8; nt++) {
            int key0 = k0 + 8 * nt + 2 * tid;
            float p0 = (key0     < n23) ? exp_fast(c[nt][0]) : 0.f;
            float p1 = (key0 + 1 < n23) ? exp_fast(c[nt][1]) : 0.f;
            float p2 = (key0     < n23) ? exp_fast(c[nt][2]) : 0.f;
            float p3 = (key0 + 1 < n23) ? exp_fast(c[nt][3]) : 0.f;
            l0 += p0 + p1;
            l1 += p2 + p3;
            int kc = nt >> 1, h = (nt & 1) * 2;
            pa[kc][h]     = pack_h2(p0, p1);
            pa[kc][h + 1] = pack_h2(p2, p3);
        }
        // O += P V : 16 d-tiles x 4 k-chunks
#pragma unroll
        for (int kc = 0; kc < 4; kc++) {
#pragma unroll
            for (int nt = 0; nt < 16; nt++) {
                const __half* vr = VTs + (8 * nt + g) * 72;
                unsigned b0 = *reinterpret_cast<const unsigned*>(vr + 16 * kc + 2 * tid);
                unsigned b1 = *reinterpret_cast<const unsigned*>(vr + 16 * kc + 2 * tid + 8);
                mma_f16(o[nt], pa[kc], b0, b1);
            }
        }
    }
    // ---- epilogue ----
    l0 += __shfl_xor_sync(0xffffffffu, l0, 1);
    l0 += __shfl_xor_sync(0xffffffffu, l0, 2);
    l1 += __shfl_xor_sync(0xffffffffu, l1, 1);
    l1 += __shfl_xor_sync(0xffffffffu, l1, 2);
    __syncthreads();                   // all S reads of Ks done before alias
    float* lr = reinterpret_cast<float*>(Ks);
    if (tid == 0) {
        lr[16 * w + g] = l0;
        lr[16 * w + g + 8] = l1;
    }
    __syncthreads();
    if (t < 64 && q0 + t < n23)
        g_L3[sp * CN + q0 + t] = lr[t];
    int r0 = q0 + 16 * w + g;
    int r8 = r0 + 8;
    float* base0 = g_O3 + ((size_t)sp * CN + r0) * 128 + 2 * tid;
    float* base8 = g_O3 + ((size_t)sp * CN + r8) * 128 + 2 * tid;
#pragma unroll
    for (int nt = 0; nt < 16; nt++) {
        if (r0 < n23)
            *reinterpret_cast<float2*>(base0 + 8 * nt) = make_float2(o[nt][0], o[nt][1]);
        if (r8 < n23)
            *reinterpret_cast<float2*>(base8 + 8 * nt) = make_float2(o[nt][2], o[nt][3]);
    }
}

// ----------------- k_combine: sum splits, tanh, scatter, column max --------
__global__ void k_combine(float* __restrict__ outH) {
    int n23 = g_cnt[1];
    int t = threadIdx.x;
    int c = t & 127, sub = t >> 7;
    int s0 = blockIdx.x * 8;
    float mx = -FLT_MAX;
#pragma unroll
    for (int k = 0; k < 4; k++) {
        int sl = s0 + sub * 4 + k;
        if (sl < n23) {
            float lt = 0.f, ov = 0.f;
#pragma unroll
            for (int sp = 0; sp < KSPLIT; sp++) {
                lt += g_L3[sp * CN + sl];
                ov += g_O3[((size_t)sp * CN + sl) * 128 + c];
            }
            float h = tanhf(ov / lt);
            int row = g_idx23[sl] & 0x3FFFFFFF;
            outH[(size_t)row * 128 + c] = h;
            mx = fmaxf(mx, h);
        }
    }
    __shared__ float red[2][128];
    red[sub][c] = mx;
    __syncthreads();
    if (t < 128) atomicMax(&g_outacc[t], ford(fmaxf(red[0][t], red[1][t])));
}

// ----------------- k_final: output vector + reset counters for next run ----
__global__ void k_final(float* __restrict__ out) {
    int t = threadIdx.x;
    out[t] = funord(g_outacc[t]) + g_tf[t];
    if (t == 0) { g_cnt[0] = 0; g_cnt[1] = 0; }
}

// ---------------------------------------------------------------------------
extern "C" void kernel_launch(void* const* d_in, const int* in_sizes, int n_in,
                              void* d_out, int out_size) {
    const float* interval = (const float*)d_in[0];
    const float* co   = (const float*)d_in[1];
    const float* no_  = (const float*)d_in[2];
    const float* un   = (const float*)d_in[3];
    const float* hid  = (const float*)d_in[4];
    const int*   divided = (const int*)d_in[5];
    const float* W_ih = (const float*)d_in[6];
    const float* W_hh = (const float*)d_in[7];
    const float* b_ih = (const float*)d_in[8];
    const float* b_hh = (const float*)d_in[9];
    const float* Wq = (const float*)d_in[10];
    const float* bq = (const float*)d_in[11];
    const float* Wk = (const float*)d_in[12];
    const float* bk = (const float*)d_in[13];
    const float* Wv = (const float*)d_in[14];
    const float* bv = (const float*)d_in[15];
    const float* Wt = (const float*)d_in[16];
    const float* bt = (const float*)d_in[17];
    float* out  = (float*)d_out;
    float* outH = out + HD;   // h_new region: [12288, 128] after the 128-vec

    cudaFuncSetAttribute(k_gemm,  cudaFuncAttributeMaxDynamicSharedMemorySize, GEMM_SMEM);
    cudaFuncSetAttribute(k_flash, cudaFuncAttributeMaxDynamicSharedMemorySize, FLASH_SMEM);

    k_init<<<768, 512>>>(outH, interval, Wt, bt, divided);
    k_gather<<<CN / 2, 256>>>(co, no_, un, hid);
    k_gemm<<<dim3(192, 16), 256, GEMM_SMEM>>>(W_ih, W_hh, b_ih, b_hh,
                                              Wq, bq, Wk, bk, Wv, bv);
    k_flash<<<(CN / 64) * KSPLIT, 128, FLASH_SMEM>>>();
    k_gruc<<<CN / 8, 256>>>(hid, outH);
    k_combine<<<CN / 8, 256>>>(outH);
    k_final<<<1, 128>>>(out);
}

// round 9
// speedup vs baseline: 5.0776x; 1.3841x over previous
#include <cuda_runtime.h>
#include <cuda_fp16.h>
#include <float.h>
#include <math.h>

#define CN 12288          // CODE_NUM
#define GD 128            // GRAPH
#define HD 128            // HIDDEN
#define AT 64             // ATT
#define KSPLIT 4

// ----------------- scratch (device globals; no allocation allowed) ---------
__device__ float g_Xq[CN * GD];     // gathered query-source rows (m23)
__device__ float g_Xc[CN * GD];     // gathered co_embeddings rows (m23)
__device__ float g_X1[CN * GD];     // gathered co_embeddings rows (m1)
__device__ float g_H1[CN * HD];     // gathered hidden rows (m1)
__device__ float g_GI[CN * 3 * HD]; // x @ W_ih^T + b_ih
__device__ float g_GH[CN * 3 * HD]; // h @ W_hh^T + b_hh
__device__ __half g_Qh[CN * AT];    // Q/8, fp16 (slots >= n23 stay zero)
__device__ __half g_Kh[CN * AT];    // K, fp16  (slots >= n23 stay zero)
__device__ __half g_VT[HD * CN];    // V transposed [d][slot], fp16 (tail zero)
__device__ float g_O3[KSPLIT * CN * HD];  // per-split O partials
__device__ float g_L3[KSPLIT * CN];       // per-split l partials
__device__ int   g_idx1[CN];
__device__ int   g_idx23[CN];       // row | (m2 << 30)
__device__ int   g_cnt[2] = {0, 0}; // [0]=n1, [1]=n23 (reset by k_final)
__device__ unsigned g_outacc[HD];   // ordered-uint float max accumulator
__device__ float g_tf[HD];          // time features

__device__ __forceinline__ unsigned ford(float f) {
    unsigned u = __float_as_uint(f);
    return (u & 0x80000000u) ? ~u : (u | 0x80000000u);
}
__device__ __forceinline__ float funord(unsigned u) {
    return (u & 0x80000000u) ? __uint_as_float(u ^ 0x80000000u)
                             : __uint_as_float(~u);
}

// round-to-nearest tf32 (for MMA operand staging)
__device__ __forceinline__ float tf32r(float x) {
    unsigned u;
    asm("cvt.rna.tf32.f32 %0, %1;" : "=r"(u) : "f"(x));
    return __uint_as_float(u);
}

// m16n8k8 tf32 MMA, fp32 accumulate (projection GEMMs)
__device__ __forceinline__ void mma_tf32(float* c, const unsigned* a,
                                         unsigned b0, unsigned b1) {
    asm volatile(
        "mma.sync.aligned.m16n8k8.row.col.f32.tf32.tf32.f32 "
        "{%0,%1,%2,%3}, {%4,%5,%6,%7}, {%8,%9}, {%0,%1,%2,%3};"
        : "+f"(c[0]), "+f"(c[1]), "+f"(c[2]), "+f"(c[3])
        : "r"(a[0]), "r"(a[1]), "r"(a[2]), "r"(a[3]), "r"(b0), "r"(b1));
}

// m16n8k16 fp16 MMA, fp32 accumulate (flash)
__device__ __forceinline__ void mma_f16(float* c, const unsigned* a,
                                        unsigned b0, unsigned b1) {
    asm volatile(
        "mma.sync.aligned.m16n8k16.row.col.f32.f16.f16.f32 "
        "{%0,%1,%2,%3}, {%4,%5,%6,%7}, {%8,%9}, {%0,%1,%2,%3};"
        : "+f"(c[0]), "+f"(c[1]), "+f"(c[2]), "+f"(c[3])
        : "r"(a[0]), "r"(a[1]), "r"(a[2]), "r"(a[3]), "r"(b0), "r"(b1));
}

__device__ __forceinline__ unsigned pack_h2(float a, float b) {
    __half2 h = __floats2half2_rn(a, b);
    return *reinterpret_cast<unsigned*>(&h);
}

// 16B global->shared async copy
__device__ __forceinline__ void cp16(unsigned dst, const void* src) {
    asm volatile("cp.async.cg.shared.global [%0], [%1], 16;"
                 :: "r"(dst), "l"(src));
}

// ----------------- k_init: zero h_new, init accumulators, tf, compact ------
__global__ void k_init(float* __restrict__ outH, const float* __restrict__ interval,
                       const float* __restrict__ Wt, const float* __restrict__ bt,
                       const int* __restrict__ divided) {
    int i = blockIdx.x * 512 + threadIdx.x;            // 768*512 = 393216 float4
    reinterpret_cast<float4*>(outH)[i] = make_float4(0.f, 0.f, 0.f, 0.f);
    if (blockIdx.x == 0) {
        int t = threadIdx.x;
        if (t < HD) {
            float xt = 1.0f / logf(interval[0] + 2.7182818284590452f);
            g_tf[t] = tanhf(xt * Wt[t] + bt[t]);
            g_outacc[t] = ford(-FLT_MAX);
        }
    }
    if (blockIdx.x < 24) {
        int row = blockIdx.x * 512 + threadIdx.x;      // 24*512 = 12288
        int d0 = divided[row * 3 + 0];
        int d1 = divided[row * 3 + 1];
        int d2 = divided[row * 3 + 2];
        if (d0 > 0) {
            int pos = atomicAdd(&g_cnt[0], 1);
            g_idx1[pos] = row;
        }
        if (d1 > 0 || d2 > 0) {
            int pos = atomicAdd(&g_cnt[1], 1);
            g_idx23[pos] = row | ((d1 > 0) ? (1 << 30) : 0);
        }
    }
}

// ----------------- k_gather: compact rows into dense scratch ---------------
__global__ void k_gather(const float* __restrict__ co, const float* __restrict__ no_,
                         const float* __restrict__ un, const float* __restrict__ hid) {
    int s = blockIdx.x * 2 + (threadIdx.x >> 7);
    int lane = threadIdx.x & 127;
    int n23 = g_cnt[1], n1 = g_cnt[0];
    if (s < n23) {
        int e = g_idx23[s];
        int row = e & 0x3FFFFFFF;
        const float* src = (e & (1 << 30)) ? no_ : un;
        g_Xq[s * GD + lane] = src[row * GD + lane];
        g_Xc[s * GD + lane] = co[row * GD + lane];
    }
    if (s < n1) {
        int row = g_idx1[s];
        g_X1[s * GD + lane] = co[row * GD + lane];
        g_H1[s * HD + lane] = hid[row * HD + lane];
    }
}

// ----------------- k_gemm: all projections in one launch -------------------
// y 0..5:  GI col y      (A=X1, W=Wih)  fp32 out
// y 6..11: GH col y-6    (A=H1, W=Whh)  fp32 out
// y 12: Q (A=Xq, W=Wq) -> g_Qh half (x 1/8)
// y 13: K (A=Xc, W=Wk) -> g_Kh half
// y 14,15: V halves (A=Xc, W=Wv) -> g_VT half transposed
#define GEMM_SMEM (2 * 64 * 132 * 4)
__global__ void __launch_bounds__(256, 2) k_gemm(
        const float* __restrict__ Wih, const float* __restrict__ Whh,
        const float* __restrict__ bih, const float* __restrict__ bhh,
        const float* __restrict__ Wq,  const float* __restrict__ bq,
        const float* __restrict__ Wk,  const float* __restrict__ bk,
        const float* __restrict__ Wv,  const float* __restrict__ bv) {
    int y = blockIdx.y;
    const float *A, *W, *bias;
    int M, col0;
    if (y < 6)       { A = g_X1; W = Wih; bias = bih; M = g_cnt[0]; col0 = y * 64; }
    else if (y < 12) { A = g_H1; W = Whh; bias = bhh; M = g_cnt[0]; col0 = (y - 6) * 64; }
    else if (y == 12){ A = g_Xq; W = Wq;  bias = bq;  M = g_cnt[1]; col0 = 0; }
    else if (y == 13){ A = g_Xc; W = Wk;  bias = bk;  M = g_cnt[1]; col0 = 0; }
    else             { A = g_Xc; W = Wv;  bias = bv;  M = g_cnt[1]; col0 = (y - 14) * 64; }
    int row0 = blockIdx.x * 64;
    if (row0 >= M) return;

    extern __shared__ float sm[];
    float* As = sm;              // [64][132]
    float* Ws = sm + 64 * 132;   // [64][132]
    int t = threadIdx.x;
    for (int i4 = t; i4 < 64 * 32; i4 += 256) {
        int r = i4 >> 5, k4 = i4 & 31;
        float4 v = make_float4(0.f, 0.f, 0.f, 0.f);
        if (row0 + r < M)
            v = reinterpret_cast<const float4*>(A + (size_t)(row0 + r) * 128)[k4];
        v.x = tf32r(v.x); v.y = tf32r(v.y); v.z = tf32r(v.z); v.w = tf32r(v.w);
        *reinterpret_cast<float4*>(As + r * 132 + k4 * 4) = v;
    }
    for (int i4 = t; i4 < 64 * 32; i4 += 256) {
        int c = i4 >> 5, k4 = i4 & 31;
        float4 v = reinterpret_cast<const float4*>(W + (size_t)(col0 + c) * 128)[k4];
        v.x = tf32r(v.x); v.y = tf32r(v.y); v.z = tf32r(v.z); v.w = tf32r(v.w);
        *reinterpret_cast<float4*>(Ws + c * 132 + k4 * 4) = v;
    }
    __syncthreads();
    int w = t >> 5, lane = t & 31;
    int g = lane >> 2, tid = lane & 3;
    int mw = w >> 1, nw = w & 1;
    float c[4][4];
#pragma unroll
    for (int nt = 0; nt < 4; nt++)
#pragma unroll
        for (int i = 0; i < 4; i++) c[nt][i] = 0.f;
    const float* r0p = As + (16 * mw + g) * 132;
    const float* r8p = r0p + 8 * 132;
#pragma unroll
    for (int ks = 0; ks < 16; ks++) {
        unsigned a[4];
        a[0] = __float_as_uint(r0p[8 * ks + tid]);
        a[1] = __float_as_uint(r8p[8 * ks + tid]);
        a[2] = __float_as_uint(r0p[8 * ks + tid + 4]);
        a[3] = __float_as_uint(r8p[8 * ks + tid + 4]);
#pragma unroll
        for (int nt = 0; nt < 4; nt++) {
            const float* kr = Ws + (nw * 32 + 8 * nt + g) * 132;
            unsigned b0 = __float_as_uint(kr[8 * ks + tid]);
            unsigned b1 = __float_as_uint(kr[8 * ks + tid + 4]);
            mma_tf32(c[nt], a, b0, b1);
        }
    }
    int ra = row0 + 16 * mw + g;
    int rb = ra + 8;
    if (y < 12) {
        float* C = (y < 6) ? g_GI : g_GH;
#pragma unroll
        for (int nt = 0; nt < 4; nt++) {
            int cb = col0 + nw * 32 + 8 * nt + 2 * tid;
            float2 bz = *reinterpret_cast<const float2*>(bias + cb);
            if (ra < M)
                *reinterpret_cast<float2*>(C + (size_t)ra * 384 + cb) =
                    make_float2(c[nt][0] + bz.x, c[nt][1] + bz.y);
            if (rb < M)
                *reinterpret_cast<float2*>(C + (size_t)rb * 384 + cb) =
                    make_float2(c[nt][2] + bz.x, c[nt][3] + bz.y);
        }
    } else if (y <= 13) {
        __half* dst = (y == 12) ? g_Qh : g_Kh;
        float s = (y == 12) ? 0.125f : 1.0f;
#pragma unroll
        for (int nt = 0; nt < 4; nt++) {
            int cb = nw * 32 + 8 * nt + 2 * tid;
            float2 bz = *reinterpret_cast<const float2*>(bias + cb);
            if (ra < M) {
                __half2 h = __floats2half2_rn((c[nt][0] + bz.x) * s, (c[nt][1] + bz.y) * s);
                *reinterpret_cast<__half2*>(dst + (size_t)ra * 64 + cb) = h;
            }
            if (rb < M) {
                __half2 h = __floats2half2_rn((c[nt][2] + bz.x) * s, (c[nt][3] + bz.y) * s);
                *reinterpret_cast<__half2*>(dst + (size_t)rb * 64 + cb) = h;
            }
        }
    } else {
        // V -> g_VT transposed [d][slot]
#pragma unroll
        for (int nt = 0; nt < 4; nt++) {
            int cb = col0 + nw * 32 + 8 * nt + 2 * tid;
            float2 bz = *reinterpret_cast<const float2*>(bias + cb);
            if (ra < M) {
                g_VT[(size_t)cb * CN + ra]       = __float2half(c[nt][0] + bz.x);
                g_VT[(size_t)(cb + 1) * CN + ra] = __float2half(c[nt][1] + bz.y);
            }
            if (rb < M) {
                g_VT[(size_t)cb * CN + rb]       = __float2half(c[nt][2] + bz.x);
                g_VT[(size_t)(cb + 1) * CN + rb] = __float2half(c[nt][3] + bz.y);
            }
        }
    }
}

// ----------------- k_gruc: GRU gates + scatter h_new + column max ----------
__global__ void k_gruc(const float* __restrict__ hid, float* __restrict__ outH) {
    int n1 = g_cnt[0];
    int t = threadIdx.x;
    int c = t & 127, sub = t >> 7;
    int s0 = blockIdx.x * 8;
    float mx = -FLT_MAX;
#pragma unroll
    for (int k = 0; k < 4; k++) {
        int s = s0 + sub * 4 + k;
        if (s < n1) {
            int row = g_idx1[s];
            const float* gi = g_GI + (size_t)s * 384;
            const float* gh = g_GH + (size_t)s * 384;
            float r  = 1.f / (1.f + __expf(-(gi[c] + gh[c])));
            float z  = 1.f / (1.f + __expf(-(gi[128 + c] + gh[128 + c])));
            float nn = tanhf(gi[256 + c] + r * gh[256 + c]);
            float h  = hid[(size_t)row * 128 + c];
            float o  = (1.f - z) * nn + z * h;
            outH[(size_t)row * 128 + c] = o;
            mx = fmaxf(mx, o);
        }
    }
    __shared__ float red[2][128];
    red[sub][c] = mx;
    __syncthreads();
    if (t < 128) atomicMax(&g_outacc[t], ford(fmaxf(red[0][t], red[1][t])));
}

// ----------------- k_flash: fp16 MMA, cp.async double-buffered K/V ---------
// 4 warps; warp w owns q-rows 16w..16w+15, all 64 keys, all 128 d.
// P lives in registers. Tile loads are unconditional (gmem tails are zero).
// Smem: Q[64][72] + 2x(K[64][72] + VT[128][72]) = 64.5 KB -> 3 CTAs/SM.
#define FLASH_SMEM ((3 * 64 * 72 + 2 * 128 * 72) * 2)
__global__ void __launch_bounds__(128, 3) k_flash() {
    int n23 = g_cnt[1];
    int qb = blockIdx.x / KSPLIT;
    int sp = blockIdx.x % KSPLIT;
    int q0 = qb * 64;
    if (q0 >= n23) return;
    extern __shared__ __half smh[];
    __half* Qs = smh;                              // [64][72]
    // stage s: K at smh + (1+s)*64*72 ; VT at smh + 3*64*72 + s*128*72
    int t = threadIdx.x;
    int w = t >> 5, lane = t & 31;
    int g = lane >> 2, tid = lane & 3;

    int nkb = (n23 + 63) >> 6;
    int chunk = (nkb + KSPLIT - 1) / KSPLIT;
    int kb0 = sp * chunk;
    int kb1 = min(kb0 + chunk, nkb);

    // issue async loads for first K/V tile (stage 0) before staging Q
    {
        int k0 = kb0 << 6;
        __half* Kst = smh + 64 * 72;
        __half* Vst = smh + 3 * 64 * 72;
        for (int i = t; i < 64 * 8; i += 128) {
            int r = i >> 3, c8 = i & 7;
            cp16((unsigned)__cvta_generic_to_shared(Kst + r * 72 + 8 * c8),
                 g_Kh + (size_t)(k0 + r) * AT + 8 * c8);
        }
        for (int i = t; i < 128 * 8; i += 128) {
            int d = i >> 3, j8 = i & 7;
            cp16((unsigned)__cvta_generic_to_shared(Vst + d * 72 + 8 * j8),
                 g_VT + (size_t)d * CN + k0 + 8 * j8);
        }
        asm volatile("cp.async.commit_group;");
    }
    // stage Q tile (overlaps with the async loads above)
    for (int i = t; i < 64 * 8; i += 128) {
        int r = i >> 3, c8 = i & 7;
        *reinterpret_cast<uint4*>(Qs + r * 72 + 8 * c8) =
            *reinterpret_cast<const uint4*>(g_Qh + (size_t)(q0 + r) * AT + 8 * c8);
    }
    __syncthreads();
    // preload Q A-fragments (4 k-chunks of 16)
    unsigned qa[4][4];
    {
        const __half* r0 = Qs + (16 * w + g) * 72;
        const __half* r8 = Qs + (16 * w + g + 8) * 72;
#pragma unroll
        for (int ks = 0; ks < 4; ks++) {
            qa[ks][0] = *reinterpret_cast<const unsigned*>(r0 + 16 * ks + 2 * tid);
            qa[ks][1] = *reinterpret_cast<const unsigned*>(r8 + 16 * ks + 2 * tid);
            qa[ks][2] = *reinterpret_cast<const unsigned*>(r0 + 16 * ks + 2 * tid + 8);
            qa[ks][3] = *reinterpret_cast<const unsigned*>(r8 + 16 * ks + 2 * tid + 8);
        }
    }
    float o[16][4];
#pragma unroll
    for (int nt = 0; nt < 16; nt++)
#pragma unroll
        for (int i = 0; i < 4; i++) o[nt][i] = 0.f;
    float l0 = 0.f, l1 = 0.f;

    for (int kb = kb0; kb < kb1; kb++) {
        int st = (kb - kb0) & 1;
        bool has_next = (kb + 1 < kb1);
        if (has_next) {
            // issue loads for next tile into the other stage
            int k0n = (kb + 1) << 6;
            int sn = st ^ 1;
            __half* Kst = smh + (1 + sn) * 64 * 72;
            __half* Vst = smh + 3 * 64 * 72 + sn * 128 * 72;
            for (int i = t; i < 64 * 8; i += 128) {
                int r = i >> 3, c8 = i & 7;
                cp16((unsigned)__cvta_generic_to_shared(Kst + r * 72 + 8 * c8),
                     g_Kh + (size_t)(k0n + r) * AT + 8 * c8);
            }
            for (int i = t; i < 128 * 8; i += 128) {
                int d = i >> 3, j8 = i & 7;
                cp16((unsigned)__cvta_generic_to_shared(Vst + d * 72 + 8 * j8),
                     g_VT + (size_t)d * CN + k0n + 8 * j8);
            }
            asm volatile("cp.async.commit_group;");
            asm volatile("cp.async.wait_group 1;");
        } else {
            asm volatile("cp.async.wait_group 0;");
        }
        __syncthreads();
        const __half* Ks  = smh + (1 + st) * 64 * 72;
        const __half* VTs = smh + 3 * 64 * 72 + st * 128 * 72;
        int k0 = kb << 6;
        // S = Q K^T : 8 key-tiles x 4 k-chunks
        float c[8][4];
#pragma unroll
        for (int nt = 0; nt < 8; nt++)
#pragma unroll
            for (int i = 0; i < 4; i++) c[nt][i] = 0.f;
#pragma unroll
        for (int nt = 0; nt < 8; nt++) {
            const __half* kr = Ks + (8 * nt + g) * 72;
#pragma unroll
            for (int ks = 0; ks < 4; ks++) {
                unsigned b0 = *reinterpret_cast<const unsigned*>(kr + 16 * ks + 2 * tid);
                unsigned b1 = *reinterpret_cast<const unsigned*>(kr + 16 * ks + 2 * tid + 8);
                mma_f16(c[nt], qa[ks], b0, b1);
            }
        }
        // P = exp(S) in registers (MUFU), packed straight into PV A-fragments
        unsigned pa[4][4];
#pragma unroll
        for (int nt = 0; nt < 8; nt++) {
            int key0 = k0 + 8 * nt + 2 * tid;
            float p0 = (key0     < n23) ? __expf(c[nt][0]) : 0.f;
            float p1 = (key0 + 1 < n23) ? __expf(c[nt][1]) : 0.f;
            float p2 = (key0     < n23) ? __expf(c[nt][2]) : 0.f;
            float p3 = (key0 + 1 < n23) ? __expf(c[nt][3]) : 0.f;
            l0 += p0 + p1;
            l1 += p2 + p3;
            int kc = nt >> 1, h = (nt & 1) * 2;
            pa[kc][h]     = pack_h2(p0, p1);
            pa[kc][h + 1] = pack_h2(p2, p3);
        }
        // O += P V : 16 d-tiles x 4 k-chunks
#pragma unroll
        for (int kc = 0; kc < 4; kc++) {
#pragma unroll
            for (int nt = 0; nt < 16; nt++) {
                const __half* vr = VTs + (8 * nt + g) * 72;
                unsigned b0 = *reinterpret_cast<const unsigned*>(vr + 16 * kc + 2 * tid);
                unsigned b1 = *reinterpret_cast<const unsigned*>(vr + 16 * kc + 2 * tid + 8);
                mma_f16(o[nt], pa[kc], b0, b1);
            }
        }
        __syncthreads();   // all reads of stage st done before its next refill
    }
    // ---- epilogue ----
    l0 += __shfl_xor_sync(0xffffffffu, l0, 1);
    l0 += __shfl_xor_sync(0xffffffffu, l0, 2);
    l1 += __shfl_xor_sync(0xffffffffu, l1, 1);
    l1 += __shfl_xor_sync(0xffffffffu, l1, 2);
    float* lr = reinterpret_cast<float*>(Qs);   // Qs no longer needed
    if (tid == 0) {
        lr[16 * w + g] = l0;
        lr[16 * w + g + 8] = l1;
    }
    __syncthreads();
    if (t < 64 && q0 + t < n23)
        g_L3[sp * CN + q0 + t] = lr[t];
    int r0 = q0 + 16 * w + g;
    int r8 = r0 + 8;
    float* base0 = g_O3 + ((size_t)sp * CN + r0) * 128 + 2 * tid;
    float* base8 = g_O3 + ((size_t)sp * CN + r8) * 128 + 2 * tid;
#pragma unroll
    for (int nt = 0; nt < 16; nt++) {
        if (r0 < n23)
            *reinterpret_cast<float2*>(base0 + 8 * nt) = make_float2(o[nt][0], o[nt][1]);
        if (r8 < n23)
            *reinterpret_cast<float2*>(base8 + 8 * nt) = make_float2(o[nt][2], o[nt][3]);
    }
}

// ----------------- k_combine: sum splits, tanh, scatter, column max --------
__global__ void k_combine(float* __restrict__ outH) {
    int n23 = g_cnt[1];
    int t = threadIdx.x;
    int c = t & 127, sub = t >> 7;
    int s0 = blockIdx.x * 8;
    float mx = -FLT_MAX;
#pragma unroll
    for (int k = 0; k < 4; k++) {
        int sl = s0 + sub * 4 + k;
        if (sl < n23) {
            float lt = 0.f, ov = 0.f;
#pragma unroll
            for (int sp = 0; sp < KSPLIT; sp++) {
                lt += g_L3[sp * CN + sl];
                ov += g_O3[((size_t)sp * CN + sl) * 128 + c];
            }
            float h = tanhf(ov / lt);
            int row = g_idx23[sl] & 0x3FFFFFFF;
            outH[(size_t)row * 128 + c] = h;
            mx = fmaxf(mx, h);
        }
    }
    __shared__ float red[2][128];
    red[sub][c] = mx;
    __syncthreads();
    if (t < 128) atomicMax(&g_outacc[t], ford(fmaxf(red[0][t], red[1][t])));
}

// ----------------- k_final: output vector + reset counters for next run ----
__global__ void k_final(float* __restrict__ out) {
    int t = threadIdx.x;
    out[t] = funord(g_outacc[t]) + g_tf[t];
    if (t == 0) { g_cnt[0] = 0; g_cnt[1] = 0; }
}

// ---------------------------------------------------------------------------
extern "C" void kernel_launch(void* const* d_in, const int* in_sizes, int n_in,
                              void* d_out, int out_size) {
    const float* interval = (const float*)d_in[0];
    const float* co   = (const float*)d_in[1];
    const float* no_  = (const float*)d_in[2];
    const float* un   = (const float*)d_in[3];
    const float* hid  = (const float*)d_in[4];
    const int*   divided = (const int*)d_in[5];
    const float* W_ih = (const float*)d_in[6];
    const float* W_hh = (const float*)d_in[7];
    const float* b_ih = (const float*)d_in[8];
    const float* b_hh = (const float*)d_in[9];
    const float* Wq = (const float*)d_in[10];
    const float* bq = (const float*)d_in[11];
    const float* Wk = (const float*)d_in[12];
    const float* bk = (const float*)d_in[13];
    const float* Wv = (const float*)d_in[14];
    const float* bv = (const float*)d_in[15];
    const float* Wt = (const float*)d_in[16];
    const float* bt = (const float*)d_in[17];
    float* out  = (float*)d_out;
    float* outH = out + HD;   // h_new region: [12288, 128] after the 128-vec

    cudaFuncSetAttribute(k_gemm,  cudaFuncAttributeMaxDynamicSharedMemorySize, GEMM_SMEM);
    cudaFuncSetAttribute(k_flash, cudaFuncAttributeMaxDynamicSharedMemorySize, FLASH_SMEM);

    k_init<<<768, 512>>>(outH, interval, Wt, bt, divided);
    k_gather<<<CN / 2, 256>>>(co, no_, un, hid);
    k_gemm<<<dim3(192, 16), 256, GEMM_SMEM>>>(W_ih, W_hh, b_ih, b_hh,
                                              Wq, bq, Wk, bk, Wv, bv);
    k_flash<<<(CN / 64) * KSPLIT, 128, FLASH_SMEM>>>();
    k_gruc<<<CN / 8, 256>>>(hid, outH);
    k_combine<<<CN / 8, 256>>>(outH);
    k_final<<<1, 128>>>(out);
}

// round 10
// speedup vs baseline: 5.2735x; 1.0386x over previous
#include <cuda_runtime.h>
#include <cuda_fp16.h>
#include <float.h>
#include <math.h>

#define CN 12288          // CODE_NUM
#define GD 128            // GRAPH
#define HD 128            // HIDDEN
#define AT 64             // ATT
#define KSPLIT 4

// ----------------- scratch (device globals; no allocation allowed) ---------
__device__ float g_Xq[CN * GD];     // gathered query-source rows (m23)
__device__ float g_Xc[CN * GD];     // gathered co_embeddings rows (m23)
__device__ float g_X1[CN * GD];     // gathered co_embeddings rows (m1)
__device__ float g_H1[CN * HD];     // gathered hidden rows (m1)
__device__ float g_GI[CN * 3 * HD]; // x @ W_ih^T + b_ih
__device__ float g_GH[CN * 3 * HD]; // h @ W_hh^T + b_hh
__device__ __half g_Qh[CN * AT];    // Q/8, fp16 (slots >= n23 stay zero)
__device__ __half g_Kh[CN * AT];    // K, fp16  (slots >= n23 stay zero)
__device__ __half g_VT[HD * CN];    // V transposed [d][slot], fp16 (tail zero)
__device__ float g_O3[KSPLIT * CN * HD];  // per-split O partials
__device__ float g_L3[KSPLIT * CN];       // per-split l partials
__device__ int   g_idx1[CN];
__device__ int   g_idx23[CN];       // row | (m2 << 30)
__device__ int   g_cnt[2] = {0, 0}; // [0]=n1, [1]=n23 (reset by k_final)
__device__ unsigned g_outacc[HD];   // ordered-uint float max accumulator
__device__ float g_tf[HD];          // time features

__device__ __forceinline__ unsigned ford(float f) {
    unsigned u = __float_as_uint(f);
    return (u & 0x80000000u) ? ~u : (u | 0x80000000u);
}
__device__ __forceinline__ float funord(unsigned u) {
    return (u & 0x80000000u) ? __uint_as_float(u ^ 0x80000000u)
                             : __uint_as_float(~u);
}

// round-to-nearest tf32 (for MMA operand staging)
__device__ __forceinline__ float tf32r(float x) {
    unsigned u;
    asm("cvt.rna.tf32.f32 %0, %1;" : "=r"(u) : "f"(x));
    return __uint_as_float(u);
}

// m16n8k8 tf32 MMA, fp32 accumulate (projection GEMMs)
__device__ __forceinline__ void mma_tf32(float* c, const unsigned* a,
                                         unsigned b0, unsigned b1) {
    asm volatile(
        "mma.sync.aligned.m16n8k8.row.col.f32.tf32.tf32.f32 "
        "{%0,%1,%2,%3}, {%4,%5,%6,%7}, {%8,%9}, {%0,%1,%2,%3};"
        : "+f"(c[0]), "+f"(c[1]), "+f"(c[2]), "+f"(c[3])
        : "r"(a[0]), "r"(a[1]), "r"(a[2]), "r"(a[3]), "r"(b0), "r"(b1));
}

// m16n8k16 fp16 MMA, fp32 accumulate (flash)
__device__ __forceinline__ void mma_f16(float* c, const unsigned* a,
                                        unsigned b0, unsigned b1) {
    asm volatile(
        "mma.sync.aligned.m16n8k16.row.col.f32.f16.f16.f32 "
        "{%0,%1,%2,%3}, {%4,%5,%6,%7}, {%8,%9}, {%0,%1,%2,%3};"
        : "+f"(c[0]), "+f"(c[1]), "+f"(c[2]), "+f"(c[3])
        : "r"(a[0]), "r"(a[1]), "r"(a[2]), "r"(a[3]), "r"(b0), "r"(b1));
}

// ldmatrix x4 (native order; our smem tiles already match B-fragment layout)
__device__ __forceinline__ void ldsm4(unsigned& r0, unsigned& r1,
                                      unsigned& r2, unsigned& r3, unsigned addr) {
    asm volatile("ldmatrix.sync.aligned.m8n8.x4.shared.b16 {%0,%1,%2,%3}, [%4];"
                 : "=r"(r0), "=r"(r1), "=r"(r2), "=r"(r3) : "r"(addr));
}

__device__ __forceinline__ unsigned pack_h2(float a, float b) {
    __half2 h = __floats2half2_rn(a, b);
    return *reinterpret_cast<unsigned*>(&h);
}

// 16B global->shared async copy
__device__ __forceinline__ void cp16(unsigned dst, const void* src) {
    asm volatile("cp.async.cg.shared.global [%0], [%1], 16;"
                 :: "r"(dst), "l"(src));
}

// ----------------- k_init: zero h_new, init accumulators, tf, compact ------
__global__ void k_init(float* __restrict__ outH, const float* __restrict__ interval,
                       const float* __restrict__ Wt, const float* __restrict__ bt,
                       const int* __restrict__ divided) {
    int i = blockIdx.x * 512 + threadIdx.x;            // 768*512 = 393216 float4
    reinterpret_cast<float4*>(outH)[i] = make_float4(0.f, 0.f, 0.f, 0.f);
    if (blockIdx.x == 0) {
        int t = threadIdx.x;
        if (t < HD) {
            float xt = 1.0f / logf(interval[0] + 2.7182818284590452f);
            g_tf[t] = tanhf(xt * Wt[t] + bt[t]);
            g_outacc[t] = ford(-FLT_MAX);
        }
    }
    if (blockIdx.x < 24) {
        int row = blockIdx.x * 512 + threadIdx.x;      // 24*512 = 12288
        int d0 = divided[row * 3 + 0];
        int d1 = divided[row * 3 + 1];
        int d2 = divided[row * 3 + 2];
        if (d0 > 0) {
            int pos = atomicAdd(&g_cnt[0], 1);
            g_idx1[pos] = row;
        }
        if (d1 > 0 || d2 > 0) {
            int pos = atomicAdd(&g_cnt[1], 1);
            g_idx23[pos] = row | ((d1 > 0) ? (1 << 30) : 0);
        }
    }
}

// ----------------- k_gather: compact rows into dense scratch ---------------
__global__ void k_gather(const float* __restrict__ co, const float* __restrict__ no_,
                         const float* __restrict__ un, const float* __restrict__ hid) {
    int s = blockIdx.x * 2 + (threadIdx.x >> 7);
    int lane = threadIdx.x & 127;
    int n23 = g_cnt[1], n1 = g_cnt[0];
    if (s < n23) {
        int e = g_idx23[s];
        int row = e & 0x3FFFFFFF;
        const float* src = (e & (1 << 30)) ? no_ : un;
        g_Xq[s * GD + lane] = src[row * GD + lane];
        g_Xc[s * GD + lane] = co[row * GD + lane];
    }
    if (s < n1) {
        int row = g_idx1[s];
        g_X1[s * GD + lane] = co[row * GD + lane];
        g_H1[s * HD + lane] = hid[row * HD + lane];
    }
}

// ----------------- k_gemm: all projections in one launch -------------------
// y 0..5:  GI col y      (A=X1, W=Wih)  fp32 out
// y 6..11: GH col y-6    (A=H1, W=Whh)  fp32 out
// y 12: Q (A=Xq, W=Wq) -> g_Qh half (x 1/8)
// y 13: K (A=Xc, W=Wk) -> g_Kh half
// y 14,15: V halves (A=Xc, W=Wv) -> g_VT half transposed
#define GEMM_SMEM (2 * 64 * 132 * 4)
__global__ void __launch_bounds__(256, 2) k_gemm(
        const float* __restrict__ Wih, const float* __restrict__ Whh,
        const float* __restrict__ bih, const float* __restrict__ bhh,
        const float* __restrict__ Wq,  const float* __restrict__ bq,
        const float* __restrict__ Wk,  const float* __restrict__ bk,
        const float* __restrict__ Wv,  const float* __restrict__ bv) {
    int y = blockIdx.y;
    const float *A, *W, *bias;
    int M, col0;
    if (y < 6)       { A = g_X1; W = Wih; bias = bih; M = g_cnt[0]; col0 = y * 64; }
    else if (y < 12) { A = g_H1; W = Whh; bias = bhh; M = g_cnt[0]; col0 = (y - 6) * 64; }
    else if (y == 12){ A = g_Xq; W = Wq;  bias = bq;  M = g_cnt[1]; col0 = 0; }
    else if (y == 13){ A = g_Xc; W = Wk;  bias = bk;  M = g_cnt[1]; col0 = 0; }
    else             { A = g_Xc; W = Wv;  bias = bv;  M = g_cnt[1]; col0 = (y - 14) * 64; }
    int row0 = blockIdx.x * 64;
    if (row0 >= M) return;

    extern __shared__ float sm[];
    float* As = sm;              // [64][132]
    float* Ws = sm + 64 * 132;   // [64][132]
    int t = threadIdx.x;
    for (int i4 = t; i4 < 64 * 32; i4 += 256) {
        int r = i4 >> 5, k4 = i4 & 31;
        float4 v = make_float4(0.f, 0.f, 0.f, 0.f);
        if (row0 + r < M)
            v = reinterpret_cast<const float4*>(A + (size_t)(row0 + r) * 128)[k4];
        v.x = tf32r(v.x); v.y = tf32r(v.y); v.z = tf32r(v.z); v.w = tf32r(v.w);
        *reinterpret_cast<float4*>(As + r * 132 + k4 * 4) = v;
    }
    for (int i4 = t; i4 < 64 * 32; i4 += 256) {
        int c = i4 >> 5, k4 = i4 & 31;
        float4 v = reinterpret_cast<const float4*>(W + (size_t)(col0 + c) * 128)[k4];
        v.x = tf32r(v.x); v.y = tf32r(v.y); v.z = tf32r(v.z); v.w = tf32r(v.w);
        *reinterpret_cast<float4*>(Ws + c * 132 + k4 * 4) = v;
    }
    __syncthreads();
    int w = t >> 5, lane = t & 31;
    int g = lane >> 2, tid = lane & 3;
    int mw = w >> 1, nw = w & 1;
    float c[4][4];
#pragma unroll
    for (int nt = 0; nt < 4; nt++)
#pragma unroll
        for (int i = 0; i < 4; i++) c[nt][i] = 0.f;
    const float* r0p = As + (16 * mw + g) * 132;
    const float* r8p = r0p + 8 * 132;
#pragma unroll
    for (int ks = 0; ks < 16; ks++) {
        unsigned a[4];
        a[0] = __float_as_uint(r0p[8 * ks + tid]);
        a[1] = __float_as_uint(r8p[8 * ks + tid]);
        a[2] = __float_as_uint(r0p[8 * ks + tid + 4]);
        a[3] = __float_as_uint(r8p[8 * ks + tid + 4]);
#pragma unroll
        for (int nt = 0; nt < 4; nt++) {
            const float* kr = Ws + (nw * 32 + 8 * nt + g) * 132;
            unsigned b0 = __float_as_uint(kr[8 * ks + tid]);
            unsigned b1 = __float_as_uint(kr[8 * ks + tid + 4]);
            mma_tf32(c[nt], a, b0, b1);
        }
    }
    int ra = row0 + 16 * mw + g;
    int rb = ra + 8;
    if (y < 12) {
        float* C = (y < 6) ? g_GI : g_GH;
#pragma unroll
        for (int nt = 0; nt < 4; nt++) {
            int cb = col0 + nw * 32 + 8 * nt + 2 * tid;
            float2 bz = *reinterpret_cast<const float2*>(bias + cb);
            if (ra < M)
                *reinterpret_cast<float2*>(C + (size_t)ra * 384 + cb) =
                    make_float2(c[nt][0] + bz.x, c[nt][1] + bz.y);
            if (rb < M)
                *reinterpret_cast<float2*>(C + (size_t)rb * 384 + cb) =
                    make_float2(c[nt][2] + bz.x, c[nt][3] + bz.y);
        }
    } else if (y <= 13) {
        __half* dst = (y == 12) ? g_Qh : g_Kh;
        float s = (y == 12) ? 0.125f : 1.0f;
#pragma unroll
        for (int nt = 0; nt < 4; nt++) {
            int cb = nw * 32 + 8 * nt + 2 * tid;
            float2 bz = *reinterpret_cast<const float2*>(bias + cb);
            if (ra < M) {
                __half2 h = __floats2half2_rn((c[nt][0] + bz.x) * s, (c[nt][1] + bz.y) * s);
                *reinterpret_cast<__half2*>(dst + (size_t)ra * 64 + cb) = h;
            }
            if (rb < M) {
                __half2 h = __floats2half2_rn((c[nt][2] + bz.x) * s, (c[nt][3] + bz.y) * s);
                *reinterpret_cast<__half2*>(dst + (size_t)rb * 64 + cb) = h;
            }
        }
    } else {
        // V -> g_VT transposed [d][slot]
#pragma unroll
        for (int nt = 0; nt < 4; nt++) {
            int cb = col0 + nw * 32 + 8 * nt + 2 * tid;
            float2 bz = *reinterpret_cast<const float2*>(bias + cb);
            if (ra < M) {
                g_VT[(size_t)cb * CN + ra]       = __float2half(c[nt][0] + bz.x);
                g_VT[(size_t)(cb + 1) * CN + ra] = __float2half(c[nt][1] + bz.y);
            }
            if (rb < M) {
                g_VT[(size_t)cb * CN + rb]       = __float2half(c[nt][2] + bz.x);
                g_VT[(size_t)(cb + 1) * CN + rb] = __float2half(c[nt][3] + bz.y);
            }
        }
    }
}

// ----------------- k_flash: fp16 MMA + ldmatrix + cp.async double-buffer ---
// 4 warps; warp w owns q-rows 16w..16w+15, all 64 keys, all 128 d.
// B-fragments via ldmatrix.x4 (native order == our smem tile layout).
// Smem: Q[64][72] + 2x(K[64][72] + VT[128][72]) = 64.5 KB -> 3 CTAs/SM.
#define FLASH_SMEM ((3 * 64 * 72 + 2 * 128 * 72) * 2)
__global__ void __launch_bounds__(128, 3) k_flash() {
    int n23 = g_cnt[1];
    int qb = blockIdx.x / KSPLIT;
    int sp = blockIdx.x % KSPLIT;
    int q0 = qb * 64;
    if (q0 >= n23) return;
    extern __shared__ __half smh[];
    __half* Qs = smh;                              // [64][72]
    // stage s: K at smh + (1+s)*64*72 ; VT at smh + 3*64*72 + s*128*72
    int t = threadIdx.x;
    int w = t >> 5, lane = t & 31;
    int g = lane >> 2, tid = lane & 3;
    // per-lane ldmatrix byte offset within a [.][72] tile:
    // row (lane&7), k-offset 8*(lane>>3)
    unsigned lofs = (unsigned)(((lane & 7) * 72 + 8 * (lane >> 3)) * 2);

    int nkb = (n23 + 63) >> 6;
    int chunk = (nkb + KSPLIT - 1) / KSPLIT;
    int kb0 = sp * chunk;
    int kb1 = min(kb0 + chunk, nkb);

    // issue async loads for first K/V tile (stage 0) before staging Q
    {
        int k0 = kb0 << 6;
        __half* Kst = smh + 64 * 72;
        __half* Vst = smh + 3 * 64 * 72;
        for (int i = t; i < 64 * 8; i += 128) {
            int r = i >> 3, c8 = i & 7;
            cp16((unsigned)__cvta_generic_to_shared(Kst + r * 72 + 8 * c8),
                 g_Kh + (size_t)(k0 + r) * AT + 8 * c8);
        }
        for (int i = t; i < 128 * 8; i += 128) {
            int d = i >> 3, j8 = i & 7;
            cp16((unsigned)__cvta_generic_to_shared(Vst + d * 72 + 8 * j8),
                 g_VT + (size_t)d * CN + k0 + 8 * j8);
        }
        asm volatile("cp.async.commit_group;");
    }
    // stage Q tile (overlaps with the async loads above)
    for (int i = t; i < 64 * 8; i += 128) {
        int r = i >> 3, c8 = i & 7;
        *reinterpret_cast<uint4*>(Qs + r * 72 + 8 * c8) =
            *reinterpret_cast<const uint4*>(g_Qh + (size_t)(q0 + r) * AT + 8 * c8);
    }
    __syncthreads();
    // preload Q A-fragments (4 k-chunks of 16)
    unsigned qa[4][4];
    {
        const __half* r0 = Qs + (16 * w + g) * 72;
        const __half* r8 = Qs + (16 * w + g + 8) * 72;
#pragma unroll
        for (int ks = 0; ks < 4; ks++) {
            qa[ks][0] = *reinterpret_cast<const unsigned*>(r0 + 16 * ks + 2 * tid);
            qa[ks][1] = *reinterpret_cast<const unsigned*>(r8 + 16 * ks + 2 * tid);
            qa[ks][2] = *reinterpret_cast<const unsigned*>(r0 + 16 * ks + 2 * tid + 8);
            qa[ks][3] = *reinterpret_cast<const unsigned*>(r8 + 16 * ks + 2 * tid + 8);
        }
    }
    float o[16][4];
#pragma unroll
    for (int nt = 0; nt < 16; nt++)
#pragma unroll
        for (int i = 0; i < 4; i++) o[nt][i] = 0.f;
    float l0 = 0.f, l1 = 0.f;

    for (int kb = kb0; kb < kb1; kb++) {
        int st = (kb - kb0) & 1;
        bool has_next = (kb + 1 < kb1);
        if (has_next) {
            // issue loads for next tile into the other stage
            int k0n = (kb + 1) << 6;
            int sn = st ^ 1;
            __half* Kst = smh + (1 + sn) * 64 * 72;
            __half* Vst = smh + 3 * 64 * 72 + sn * 128 * 72;
            for (int i = t; i < 64 * 8; i += 128) {
                int r = i >> 3, c8 = i & 7;
                cp16((unsigned)__cvta_generic_to_shared(Kst + r * 72 + 8 * c8),
                     g_Kh + (size_t)(k0n + r) * AT + 8 * c8);
            }
            for (int i = t; i < 128 * 8; i += 128) {
                int d = i >> 3, j8 = i & 7;
                cp16((unsigned)__cvta_generic_to_shared(Vst + d * 72 + 8 * j8),
                     g_VT + (size_t)d * CN + k0n + 8 * j8);
            }
            asm volatile("cp.async.commit_group;");
            asm volatile("cp.async.wait_group 1;");
        } else {
            asm volatile("cp.async.wait_group 0;");
        }
        __syncthreads();
        unsigned KsA = (unsigned)__cvta_generic_to_shared(smh + (1 + st) * 64 * 72) + lofs;
        unsigned VtA = (unsigned)__cvta_generic_to_shared(smh + 3 * 64 * 72 + st * 128 * 72) + lofs;
        int k0 = kb << 6;
        // S = Q K^T : 8 key-tiles, B-fragments via 2 ldmatrix.x4 each
        float c[8][4];
#pragma unroll
        for (int nt = 0; nt < 8; nt++)
#pragma unroll
            for (int i = 0; i < 4; i++) c[nt][i] = 0.f;
#pragma unroll
        for (int nt = 0; nt < 8; nt++) {
            unsigned base = KsA + nt * (8 * 72 * 2);
            unsigned b0, b1, b2, b3;
            ldsm4(b0, b1, b2, b3, base);
            mma_f16(c[nt], qa[0], b0, b1);
            mma_f16(c[nt], qa[1], b2, b3);
            ldsm4(b0, b1, b2, b3, base + 64);
            mma_f16(c[nt], qa[2], b0, b1);
            mma_f16(c[nt], qa[3], b2, b3);
        }
        // P = exp(S) in registers (MUFU), packed straight into PV A-fragments
        unsigned pa[4][4];
#pragma unroll
        for (int nt = 0; nt < 8; nt++) {
            int key0 = k0 + 8 * nt + 2 * tid;
            float p0 = (key0     < n23) ? __expf(c[nt][0]) : 0.f;
            float p1 = (key0 + 1 < n23) ? __expf(c[nt][1]) : 0.f;
            float p2 = (key0     < n23) ? __expf(c[nt][2]) : 0.f;
            float p3 = (key0 + 1 < n23) ? __expf(c[nt][3]) : 0.f;
            l0 += p0 + p1;
            l1 += p2 + p3;
            int kc = nt >> 1, h = (nt & 1) * 2;
            pa[kc][h]     = pack_h2(p0, p1);
            pa[kc][h + 1] = pack_h2(p2, p3);
        }
        // O += P V : 16 d-tiles, B-fragments via 2 ldmatrix.x4 each
#pragma unroll
        for (int nt = 0; nt < 16; nt++) {
            unsigned base = VtA + nt * (8 * 72 * 2);
            unsigned b0, b1, b2, b3;
            ldsm4(b0, b1, b2, b3, base);
            mma_f16(o[nt], pa[0], b0, b1);
            mma_f16(o[nt], pa[1], b2, b3);
            ldsm4(b0, b1, b2, b3, base + 64);
            mma_f16(o[nt], pa[2], b0, b1);
            mma_f16(o[nt], pa[3], b2, b3);
        }
        __syncthreads();   // all reads of stage st done before its next refill
    }
    // ---- epilogue ----
    l0 += __shfl_xor_sync(0xffffffffu, l0, 1);
    l0 += __shfl_xor_sync(0xffffffffu, l0, 2);
    l1 += __shfl_xor_sync(0xffffffffu, l1, 1);
    l1 += __shfl_xor_sync(0xffffffffu, l1, 2);
    float* lr = reinterpret_cast<float*>(Qs);   // Qs no longer needed
    if (tid == 0) {
        lr[16 * w + g] = l0;
        lr[16 * w + g + 8] = l1;
    }
    __syncthreads();
    if (t < 64 && q0 + t < n23)
        g_L3[sp * CN + q0 + t] = lr[t];
    int r0 = q0 + 16 * w + g;
    int r8 = r0 + 8;
    float* base0 = g_O3 + ((size_t)sp * CN + r0) * 128 + 2 * tid;
    float* base8 = g_O3 + ((size_t)sp * CN + r8) * 128 + 2 * tid;
#pragma unroll
    for (int nt = 0; nt < 16; nt++) {
        if (r0 < n23)
            *reinterpret_cast<float2*>(base0 + 8 * nt) = make_float2(o[nt][0], o[nt][1]);
        if (r8 < n23)
            *reinterpret_cast<float2*>(base8 + 8 * nt) = make_float2(o[nt][2], o[nt][3]);
    }
}

// ----------------- k_post: fused GRU-gate + split-combine ------------------
// blocks [0, CN/8): combine (m23 slots); blocks [CN/8, 2*CN/8): gruc (m1 slots)
__global__ void k_post(const float* __restrict__ hid, float* __restrict__ outH) {
    int t = threadIdx.x;
    int c = t & 127, sub = t >> 7;
    float mx = -FLT_MAX;
    if (blockIdx.x < CN / 8) {
        int n23 = g_cnt[1];
        int s0 = blockIdx.x * 8;
#pragma unroll
        for (int k = 0; k < 4; k++) {
            int sl = s0 + sub * 4 + k;
            if (sl < n23) {
                float lt = 0.f, ov = 0.f;
#pragma unroll
                for (int sp = 0; sp < KSPLIT; sp++) {
                    lt += g_L3[sp * CN + sl];
                    ov += g_O3[((size_t)sp * CN + sl) * 128 + c];
                }
                float h = tanhf(ov / lt);
                int row = g_idx23[sl] & 0x3FFFFFFF;
                outH[(size_t)row * 128 + c] = h;
                mx = fmaxf(mx, h);
            }
        }
    } else {
        int n1 = g_cnt[0];
        int s0 = (blockIdx.x - CN / 8) * 8;
#pragma unroll
        for (int k = 0; k < 4; k++) {
            int s = s0 + sub * 4 + k;
            if (s < n1) {
                int row = g_idx1[s];
                const float* gi = g_GI + (size_t)s * 384;
                const float* gh = g_GH + (size_t)s * 384;
                float r  = 1.f / (1.f + __expf(-(gi[c] + gh[c])));
                float z  = 1.f / (1.f + __expf(-(gi[128 + c] + gh[128 + c])));
                float nn = tanhf(gi[256 + c] + r * gh[256 + c]);
                float h  = hid[(size_t)row * 128 + c];
                float o  = (1.f - z) * nn + z * h;
                outH[(size_t)row * 128 + c] = o;
                mx = fmaxf(mx, o);
            }
        }
    }
    __shared__ float red[2][128];
    red[sub][c] = mx;
    __syncthreads();
    if (t < 128) atomicMax(&g_outacc[t], ford(fmaxf(red[0][t], red[1][t])));
}

// ----------------- k_final: output vector + reset counters for next run ----
__global__ void k_final(float* __restrict__ out) {
    int t = threadIdx.x;
    out[t] = funord(g_outacc[t]) + g_tf[t];
    if (t == 0) { g_cnt[0] = 0; g_cnt[1] = 0; }
}

// ---------------------------------------------------------------------------
extern "C" void kernel_launch(void* const* d_in, const int* in_sizes, int n_in,
                              void* d_out, int out_size) {
    const float* interval = (const float*)d_in[0];
    const float* co   = (const float*)d_in[1];
    const float* no_  = (const float*)d_in[2];
    const float* un   = (const float*)d_in[3];
    const float* hid  = (const float*)d_in[4];
    const int*   divided = (const int*)d_in[5];
    const float* W_ih = (const float*)d_in[6];
    const float* W_hh = (const float*)d_in[7];
    const float* b_ih = (const float*)d_in[8];
    const float* b_hh = (const float*)d_in[9];
    const float* Wq = (const float*)d_in[10];
    const float* bq = (const float*)d_in[11];
    const float* Wk = (const float*)d_in[12];
    const float* bk = (const float*)d_in[13];
    const float* Wv = (const float*)d_in[14];
    const float* bv = (const float*)d_in[15];
    const float* Wt = (const float*)d_in[16];
    const float* bt = (const float*)d_in[17];
    float* out  = (float*)d_out;
    float* outH = out + HD;   // h_new region: [12288, 128] after the 128-vec

    cudaFuncSetAttribute(k_gemm,  cudaFuncAttributeMaxDynamicSharedMemorySize, GEMM_SMEM);
    cudaFuncSetAttribute(k_flash, cudaFuncAttributeMaxDynamicSharedMemorySize, FLASH_SMEM);

    k_init<<<768, 512>>>(outH, interval, Wt, bt, divided);
    k_gather<<<CN / 2, 256>>>(co, no_, un, hid);
    k_gemm<<<dim3(192, 16), 256, GEMM_SMEM>>>(W_ih, W_hh, b_ih, b_hh,
                                              Wq, bq, Wk, bk, Wv, bv);
    k_flash<<<(CN / 64) * KSPLIT, 128, FLASH_SMEM>>>();
    k_post<<<2 * (CN / 8), 256>>>(hid, outH);
    k_final<<<1, 128>>>(out);
}

// round 11
// speedup vs baseline: 5.6093x; 1.0637x over previous
#include <cuda_runtime.h>
#include <cuda_fp16.h>
#include <float.h>
#include <math.h>

#define CN 12288          // CODE_NUM
#define GD 128            // GRAPH
#define HD 128            // HIDDEN
#define AT 64             // ATT
#define KSPLIT 4

// ----------------- scratch (device globals; no allocation allowed) ---------
__device__ float g_Xq[CN * GD];     // gathered query-source rows (m23)
__device__ float g_Xc[CN * GD];     // gathered co_embeddings rows (m23)
__device__ float g_X1[CN * GD];     // gathered co_embeddings rows (m1)
__device__ float g_H1[CN * HD];     // gathered hidden rows (m1)
__device__ float g_GI[CN * 3 * HD]; // x @ W_ih^T + b_ih
__device__ float g_GH[CN * 3 * HD]; // h @ W_hh^T + b_hh
__device__ __half g_Qh[CN * AT];    // Q/8, fp16 (slots >= n23 stay zero)
__device__ __half g_Kh[CN * AT];    // K, fp16  (slots >= n23 stay zero)
__device__ __half g_VT[HD * CN];    // V transposed [d][slot], fp16 (tail zero)
__device__ float g_O3[KSPLIT * CN * HD];  // per-split O partials
__device__ float g_L3[KSPLIT * CN];       // per-split l partials
__device__ int   g_idx1[CN];
__device__ int   g_idx23[CN];       // row | (m2 << 30)
__device__ int   g_cnt[2] = {0, 0}; // [0]=n1, [1]=n23 (reset by k_final)
__device__ unsigned g_outacc[HD];   // ordered-uint float max accumulator
__device__ float g_tf[HD];          // time features

__device__ __forceinline__ unsigned ford(float f) {
    unsigned u = __float_as_uint(f);
    return (u & 0x80000000u) ? ~u : (u | 0x80000000u);
}
__device__ __forceinline__ float funord(unsigned u) {
    return (u & 0x80000000u) ? __uint_as_float(u ^ 0x80000000u)
                             : __uint_as_float(~u);
}

// round-to-nearest tf32 (for MMA operand staging)
__device__ __forceinline__ float tf32r(float x) {
    unsigned u;
    asm("cvt.rna.tf32.f32 %0, %1;" : "=r"(u) : "f"(x));
    return __uint_as_float(u);
}

// m16n8k8 tf32 MMA, fp32 accumulate (projection GEMMs)
__device__ __forceinline__ void mma_tf32(float* c, const unsigned* a,
                                         unsigned b0, unsigned b1) {
    asm volatile(
        "mma.sync.aligned.m16n8k8.row.col.f32.tf32.tf32.f32 "
        "{%0,%1,%2,%3}, {%4,%5,%6,%7}, {%8,%9}, {%0,%1,%2,%3};"
        : "+f"(c[0]), "+f"(c[1]), "+f"(c[2]), "+f"(c[3])
        : "r"(a[0]), "r"(a[1]), "r"(a[2]), "r"(a[3]), "r"(b0), "r"(b1));
}

// m16n8k16 fp16 MMA, fp32 accumulate (flash)
__device__ __forceinline__ void mma_f16(float* c, const unsigned* a,
                                        unsigned b0, unsigned b1) {
    asm volatile(
        "mma.sync.aligned.m16n8k16.row.col.f32.f16.f16.f32 "
        "{%0,%1,%2,%3}, {%4,%5,%6,%7}, {%8,%9}, {%0,%1,%2,%3};"
        : "+f"(c[0]), "+f"(c[1]), "+f"(c[2]), "+f"(c[3])
        : "r"(a[0]), "r"(a[1]), "r"(a[2]), "r"(a[3]), "r"(b0), "r"(b1));
}

// ldmatrix x4 (native order; our smem tiles already match B-fragment layout)
__device__ __forceinline__ void ldsm4(unsigned& r0, unsigned& r1,
                                      unsigned& r2, unsigned& r3, unsigned addr) {
    asm volatile("ldmatrix.sync.aligned.m8n8.x4.shared.b16 {%0,%1,%2,%3}, [%4];"
                 : "=r"(r0), "=r"(r1), "=r"(r2), "=r"(r3) : "r"(addr));
}

__device__ __forceinline__ unsigned pack_h2(float a, float b) {
    __half2 h = __floats2half2_rn(a, b);
    return *reinterpret_cast<unsigned*>(&h);
}

// 16B global->shared async copy
__device__ __forceinline__ void cp16(unsigned dst, const void* src) {
    asm volatile("cp.async.cg.shared.global [%0], [%1], 16;"
                 :: "r"(dst), "l"(src));
}

// ----------------- k_zero: zero h_new region (runs on side stream) ---------
__global__ void k_zero(float* __restrict__ outH) {
    int i = blockIdx.x * 512 + threadIdx.x;            // 768*512 float4
    reinterpret_cast<float4*>(outH)[i] = make_float4(0.f, 0.f, 0.f, 0.f);
}

// ----------------- k_initA: accumulators, tf, compact ----------------------
__global__ void k_initA(const float* __restrict__ interval,
                        const float* __restrict__ Wt, const float* __restrict__ bt,
                        const int* __restrict__ divided) {
    if (blockIdx.x == 0) {
        int t = threadIdx.x;
        if (t < HD) {
            float xt = 1.0f / logf(interval[0] + 2.7182818284590452f);
            g_tf[t] = tanhf(xt * Wt[t] + bt[t]);
            g_outacc[t] = ford(-FLT_MAX);
        }
    }
    int row = blockIdx.x * 512 + threadIdx.x;          // 24*512 = 12288
    int d0 = divided[row * 3 + 0];
    int d1 = divided[row * 3 + 1];
    int d2 = divided[row * 3 + 2];
    if (d0 > 0) {
        int pos = atomicAdd(&g_cnt[0], 1);
        g_idx1[pos] = row;
    }
    if (d1 > 0 || d2 > 0) {
        int pos = atomicAdd(&g_cnt[1], 1);
        g_idx23[pos] = row | ((d1 > 0) ? (1 << 30) : 0);
    }
}

// ----------------- k_gather: compact rows into dense scratch ---------------
__global__ void k_gather(const float* __restrict__ co, const float* __restrict__ no_,
                         const float* __restrict__ un, const float* __restrict__ hid) {
    int s = blockIdx.x * 2 + (threadIdx.x >> 7);
    int lane = threadIdx.x & 127;
    int n23 = g_cnt[1], n1 = g_cnt[0];
    if (s < n23) {
        int e = g_idx23[s];
        int row = e & 0x3FFFFFFF;
        const float* src = (e & (1 << 30)) ? no_ : un;
        g_Xq[s * GD + lane] = src[row * GD + lane];
        g_Xc[s * GD + lane] = co[row * GD + lane];
    }
    if (s < n1) {
        int row = g_idx1[s];
        g_X1[s * GD + lane] = co[row * GD + lane];
        g_H1[s * HD + lane] = hid[row * HD + lane];
    }
}

// ----------------- shared GEMM core: c[4][4] = A[64,128] @ W[64,128]^T -----
#define GEMM_SMEM (2 * 64 * 132 * 4)
__device__ __forceinline__ void gemm_core(const float* __restrict__ A,
                                          const float* __restrict__ W,
                                          int M, int row0, int col0,
                                          float* sm, float c[4][4]) {
    float* As = sm;              // [64][132]
    float* Ws = sm + 64 * 132;   // [64][132]
    int t = threadIdx.x;
    for (int i4 = t; i4 < 64 * 32; i4 += 256) {
        int r = i4 >> 5, k4 = i4 & 31;
        float4 v = make_float4(0.f, 0.f, 0.f, 0.f);
        if (row0 + r < M)
            v = reinterpret_cast<const float4*>(A + (size_t)(row0 + r) * 128)[k4];
        v.x = tf32r(v.x); v.y = tf32r(v.y); v.z = tf32r(v.z); v.w = tf32r(v.w);
        *reinterpret_cast<float4*>(As + r * 132 + k4 * 4) = v;
    }
    for (int i4 = t; i4 < 64 * 32; i4 += 256) {
        int cc = i4 >> 5, k4 = i4 & 31;
        float4 v = reinterpret_cast<const float4*>(W + (size_t)(col0 + cc) * 128)[k4];
        v.x = tf32r(v.x); v.y = tf32r(v.y); v.z = tf32r(v.z); v.w = tf32r(v.w);
        *reinterpret_cast<float4*>(Ws + cc * 132 + k4 * 4) = v;
    }
    __syncthreads();
    int w = t >> 5, lane = t & 31;
    int g = lane >> 2, tid = lane & 3;
    int mw = w >> 1, nw = w & 1;
#pragma unroll
    for (int nt = 0; nt < 4; nt++)
#pragma unroll
        for (int i = 0; i < 4; i++) c[nt][i] = 0.f;
    const float* r0p = As + (16 * mw + g) * 132;
    const float* r8p = r0p + 8 * 132;
#pragma unroll
    for (int ks = 0; ks < 16; ks++) {
        unsigned a[4];
        a[0] = __float_as_uint(r0p[8 * ks + tid]);
        a[1] = __float_as_uint(r8p[8 * ks + tid]);
        a[2] = __float_as_uint(r0p[8 * ks + tid + 4]);
        a[3] = __float_as_uint(r8p[8 * ks + tid + 4]);
#pragma unroll
        for (int nt = 0; nt < 4; nt++) {
            const float* kr = Ws + (nw * 32 + 8 * nt + g) * 132;
            unsigned b0 = __float_as_uint(kr[8 * ks + tid]);
            unsigned b1 = __float_as_uint(kr[8 * ks + tid + 4]);
            mma_tf32(c[nt], a, b0, b1);
        }
    }
}

// GI/GH: y 0..5 -> GI col y; y 6..11 -> GH col y-6  (runs on side stream)
__global__ void __launch_bounds__(256, 2) k_gemm_g(
        const float* __restrict__ Wih, const float* __restrict__ Whh,
        const float* __restrict__ bih, const float* __restrict__ bhh) {
    int y = blockIdx.y;
    const float* A = (y < 6) ? g_X1 : g_H1;
    const float* W = (y < 6) ? Wih : Whh;
    const float* bias = (y < 6) ? bih : bhh;
    float* C = (y < 6) ? g_GI : g_GH;
    int M = g_cnt[0];
    int col0 = (y % 6) * 64;
    int row0 = blockIdx.x * 64;
    if (row0 >= M) return;
    extern __shared__ float sm[];
    float c[4][4];
    gemm_core(A, W, M, row0, col0, sm, c);
    int t = threadIdx.x, w = t >> 5, lane = t & 31;
    int g = lane >> 2, tid = lane & 3;
    int mw = w >> 1, nw = w & 1;
    int ra = row0 + 16 * mw + g, rb = ra + 8;
#pragma unroll
    for (int nt = 0; nt < 4; nt++) {
        int cb = col0 + nw * 32 + 8 * nt + 2 * tid;
        float2 bz = *reinterpret_cast<const float2*>(bias + cb);
        if (ra < M)
            *reinterpret_cast<float2*>(C + (size_t)ra * 384 + cb) =
                make_float2(c[nt][0] + bz.x, c[nt][1] + bz.y);
        if (rb < M)
            *reinterpret_cast<float2*>(C + (size_t)rb * 384 + cb) =
                make_float2(c[nt][2] + bz.x, c[nt][3] + bz.y);
    }
}

// QKV: y=0 Q, y=1 K, y=2,3 V halves (fp16 outputs)
__global__ void __launch_bounds__(256, 2) k_gemm_qkv(
        const float* __restrict__ Wq,  const float* __restrict__ bq,
        const float* __restrict__ Wk,  const float* __restrict__ bk,
        const float* __restrict__ Wv,  const float* __restrict__ bv) {
    int y = blockIdx.y;
    const float *A, *W, *bias; int col0;
    if (y == 0)      { A = g_Xq; W = Wq; bias = bq; col0 = 0; }
    else if (y == 1) { A = g_Xc; W = Wk; bias = bk; col0 = 0; }
    else             { A = g_Xc; W = Wv; bias = bv; col0 = (y - 2) * 64; }
    int M = g_cnt[1];
    int row0 = blockIdx.x * 64;
    if (row0 >= M) return;
    extern __shared__ float sm[];
    float c[4][4];
    gemm_core(A, W, M, row0, col0, sm, c);
    int t = threadIdx.x, w = t >> 5, lane = t & 31;
    int g = lane >> 2, tid = lane & 3;
    int mw = w >> 1, nw = w & 1;
    int ra = row0 + 16 * mw + g, rb = ra + 8;
    if (y <= 1) {
        __half* dst = (y == 0) ? g_Qh : g_Kh;
        float s = (y == 0) ? 0.125f : 1.0f;
#pragma unroll
        for (int nt = 0; nt < 4; nt++) {
            int cb = nw * 32 + 8 * nt + 2 * tid;
            float2 bz = *reinterpret_cast<const float2*>(bias + cb);
            if (ra < M) {
                __half2 h = __floats2half2_rn((c[nt][0] + bz.x) * s, (c[nt][1] + bz.y) * s);
                *reinterpret_cast<__half2*>(dst + (size_t)ra * 64 + cb) = h;
            }
            if (rb < M) {
                __half2 h = __floats2half2_rn((c[nt][2] + bz.x) * s, (c[nt][3] + bz.y) * s);
                *reinterpret_cast<__half2*>(dst + (size_t)rb * 64 + cb) = h;
            }
        }
    } else {
#pragma unroll
        for (int nt = 0; nt < 4; nt++) {
            int cb = col0 + nw * 32 + 8 * nt + 2 * tid;
            float2 bz = *reinterpret_cast<const float2*>(bias + cb);
            if (ra < M) {
                g_VT[(size_t)cb * CN + ra]       = __float2half(c[nt][0] + bz.x);
                g_VT[(size_t)(cb + 1) * CN + ra] = __float2half(c[nt][1] + bz.y);
            }
            if (rb < M) {
                g_VT[(size_t)cb * CN + rb]       = __float2half(c[nt][2] + bz.x);
                g_VT[(size_t)(cb + 1) * CN + rb] = __float2half(c[nt][3] + bz.y);
            }
        }
    }
}

// ----------------- k_flash: fp16 MMA + ldmatrix + cp.async, no masking -----
// Tail keys have K rows = 0 -> S = 0 -> exp = 1 exactly; V rows = 0 so O is
// unaffected; l over-counts by exactly (#invalid keys), subtracted in epilogue.
#define FLASH_SMEM ((3 * 64 * 72 + 2 * 128 * 72) * 2)
__global__ void __launch_bounds__(128, 3) k_flash() {
    int n23 = g_cnt[1];
    int qb = blockIdx.x / KSPLIT;
    int sp = blockIdx.x % KSPLIT;
    int q0 = qb * 64;
    if (q0 >= n23) return;
    extern __shared__ __half smh[];
    __half* Qs = smh;                              // [64][72]
    int t = threadIdx.x;
    int w = t >> 5, lane = t & 31;
    int g = lane >> 2, tid = lane & 3;
    unsigned lofs = (unsigned)(((lane & 7) * 72 + 8 * (lane >> 3)) * 2);

    int nkb = (n23 + 63) >> 6;
    int chunk = (nkb + KSPLIT - 1) / KSPLIT;
    int kb0 = sp * chunk;
    int kb1 = min(kb0 + chunk, nkb);

    // issue async loads for first K/V tile (stage 0) before staging Q
    {
        int k0 = kb0 << 6;
        __half* Kst = smh + 64 * 72;
        __half* Vst = smh + 3 * 64 * 72;
        for (int i = t; i < 64 * 8; i += 128) {
            int r = i >> 3, c8 = i & 7;
            cp16((unsigned)__cvta_generic_to_shared(Kst + r * 72 + 8 * c8),
                 g_Kh + (size_t)(k0 + r) * AT + 8 * c8);
        }
        for (int i = t; i < 128 * 8; i += 128) {
            int d = i >> 3, j8 = i & 7;
            cp16((unsigned)__cvta_generic_to_shared(Vst + d * 72 + 8 * j8),
                 g_VT + (size_t)d * CN + k0 + 8 * j8);
        }
        asm volatile("cp.async.commit_group;");
    }
    // stage Q tile (overlaps with the async loads above)
    for (int i = t; i < 64 * 8; i += 128) {
        int r = i >> 3, c8 = i & 7;
        *reinterpret_cast<uint4*>(Qs + r * 72 + 8 * c8) =
            *reinterpret_cast<const uint4*>(g_Qh + (size_t)(q0 + r) * AT + 8 * c8);
    }
    __syncthreads();
    // preload Q A-fragments (4 k-chunks of 16)
    unsigned qa[4][4];
    {
        const __half* r0 = Qs + (16 * w + g) * 72;
        const __half* r8 = Qs + (16 * w + g + 8) * 72;
#pragma unroll
        for (int ks = 0; ks < 4; ks++) {
            qa[ks][0] = *reinterpret_cast<const unsigned*>(r0 + 16 * ks + 2 * tid);
            qa[ks][1] = *reinterpret_cast<const unsigned*>(r8 + 16 * ks + 2 * tid);
            qa[ks][2] = *reinterpret_cast<const unsigned*>(r0 + 16 * ks + 2 * tid + 8);
            qa[ks][3] = *reinterpret_cast<const unsigned*>(r8 + 16 * ks + 2 * tid + 8);
        }
    }
    float o[16][4];
#pragma unroll
    for (int nt = 0; nt < 16; nt++)
#pragma unroll
        for (int i = 0; i < 4; i++) o[nt][i] = 0.f;
    float l0 = 0.f, l1 = 0.f;

    for (int kb = kb0; kb < kb1; kb++) {
        int st = (kb - kb0) & 1;
        bool has_next = (kb + 1 < kb1);
        if (has_next) {
            int k0n = (kb + 1) << 6;
            int sn = st ^ 1;
            __half* Kst = smh + (1 + sn) * 64 * 72;
            __half* Vst = smh + 3 * 64 * 72 + sn * 128 * 72;
            for (int i = t; i < 64 * 8; i += 128) {
                int r = i >> 3, c8 = i & 7;
                cp16((unsigned)__cvta_generic_to_shared(Kst + r * 72 + 8 * c8),
                     g_Kh + (size_t)(k0n + r) * AT + 8 * c8);
            }
            for (int i = t; i < 128 * 8; i += 128) {
                int d = i >> 3, j8 = i & 7;
                cp16((unsigned)__cvta_generic_to_shared(Vst + d * 72 + 8 * j8),
                     g_VT + (size_t)d * CN + k0n + 8 * j8);
            }
            asm volatile("cp.async.commit_group;");
            asm volatile("cp.async.wait_group 1;");
        } else {
            asm volatile("cp.async.wait_group 0;");
        }
        __syncthreads();
        unsigned KsA = (unsigned)__cvta_generic_to_shared(smh + (1 + st) * 64 * 72) + lofs;
        unsigned VtA = (unsigned)__cvta_generic_to_shared(smh + 3 * 64 * 72 + st * 128 * 72) + lofs;
        // S = Q K^T : 8 key-tiles, B-fragments via 2 ldmatrix.x4 each
        float c[8][4];
#pragma unroll
        for (int nt = 0; nt < 8; nt++)
#pragma unroll
            for (int i = 0; i < 4; i++) c[nt][i] = 0.f;
#pragma unroll
        for (int nt = 0; nt < 8; nt++) {
            unsigned base = KsA + nt * (8 * 72 * 2);
            unsigned b0, b1, b2, b3;
            ldsm4(b0, b1, b2, b3, base);
            mma_f16(c[nt], qa[0], b0, b1);
            mma_f16(c[nt], qa[1], b2, b3);
            ldsm4(b0, b1, b2, b3, base + 64);
            mma_f16(c[nt], qa[2], b0, b1);
            mma_f16(c[nt], qa[3], b2, b3);
        }
        // P = exp(S), unmasked (invalid keys give exactly 1; corrected later)
        unsigned pa[4][4];
#pragma unroll
        for (int nt = 0; nt < 8; nt++) {
            float p0 = __expf(c[nt][0]);
            float p1 = __expf(c[nt][1]);
            float p2 = __expf(c[nt][2]);
            float p3 = __expf(c[nt][3]);
            l0 += p0 + p1;
            l1 += p2 + p3;
            int kc = nt >> 1, h = (nt & 1) * 2;
            pa[kc][h]     = pack_h2(p0, p1);
            pa[kc][h + 1] = pack_h2(p2, p3);
        }
        // O += P V : 16 d-tiles, B-fragments via 2 ldmatrix.x4 each
#pragma unroll
        for (int nt = 0; nt < 16; nt++) {
            unsigned base = VtA + nt * (8 * 72 * 2);
            unsigned b0, b1, b2, b3;
            ldsm4(b0, b1, b2, b3, base);
            mma_f16(o[nt], pa[0], b0, b1);
            mma_f16(o[nt], pa[1], b2, b3);
            ldsm4(b0, b1, b2, b3, base + 64);
            mma_f16(o[nt], pa[2], b0, b1);
            mma_f16(o[nt], pa[3], b2, b3);
        }
        __syncthreads();   // all reads of stage st done before its next refill
    }
    // ---- epilogue ----
    // exact l correction: invalid keys processed by this split
    int inv = kb1 * 64 - max(n23, kb0 * 64);
    if (inv < 0) inv = 0;
    l0 += __shfl_xor_sync(0xffffffffu, l0, 1);
    l0 += __shfl_xor_sync(0xffffffffu, l0, 2);
    l1 += __shfl_xor_sync(0xffffffffu, l1, 1);
    l1 += __shfl_xor_sync(0xffffffffu, l1, 2);
    float* lr = reinterpret_cast<float*>(Qs);   // Qs no longer needed
    if (tid == 0) {
        lr[16 * w + g] = l0 - (float)inv;
        lr[16 * w + g + 8] = l1 - (float)inv;
    }
    __syncthreads();
    if (t < 64 && q0 + t < n23)
        g_L3[sp * CN + q0 + t] = lr[t];
    int r0 = q0 + 16 * w + g;
    int r8 = r0 + 8;
    float* base0 = g_O3 + ((size_t)sp * CN + r0) * 128 + 2 * tid;
    float* base8 = g_O3 + ((size_t)sp * CN + r8) * 128 + 2 * tid;
#pragma unroll
    for (int nt = 0; nt < 16; nt++) {
        if (r0 < n23)
            *reinterpret_cast<float2*>(base0 + 8 * nt) = make_float2(o[nt][0], o[nt][1]);
        if (r8 < n23)
            *reinterpret_cast<float2*>(base8 + 8 * nt) = make_float2(o[nt][2], o[nt][3]);
    }
}

// ----------------- k_post: fused GRU-gate + split-combine ------------------
__global__ void k_post(const float* __restrict__ hid, float* __restrict__ outH) {
    int t = threadIdx.x;
    int c = t & 127, sub = t >> 7;
    float mx = -FLT_MAX;
    if (blockIdx.x < CN / 8) {
        int n23 = g_cnt[1];
        int s0 = blockIdx.x * 8;
#pragma unroll
        for (int k = 0; k < 4; k++) {
            int sl = s0 + sub * 4 + k;
            if (sl < n23) {
                float lt = 0.f, ov = 0.f;
#pragma unroll
                for (int sp = 0; sp < KSPLIT; sp++) {
                    lt += g_L3[sp * CN + sl];
                    ov += g_O3[((size_t)sp * CN + sl) * 128 + c];
                }
                float h = tanhf(ov / lt);
                int row = g_idx23[sl] & 0x3FFFFFFF;
                outH[(size_t)row * 128 + c] = h;
                mx = fmaxf(mx, h);
            }
        }
    } else {
        int n1 = g_cnt[0];
        int s0 = (blockIdx.x - CN / 8) * 8;
#pragma unroll
        for (int k = 0; k < 4; k++) {
            int s = s0 + sub * 4 + k;
            if (s < n1) {
                int row = g_idx1[s];
                const float* gi = g_GI + (size_t)s * 384;
                const float* gh = g_GH + (size_t)s * 384;
                float r  = 1.f / (1.f + __expf(-(gi[c] + gh[c])));
                float z  = 1.f / (1.f + __expf(-(gi[128 + c] + gh[128 + c])));
                float nn = tanhf(gi[256 + c] + r * gh[256 + c]);
                float h  = hid[(size_t)row * 128 + c];
                float o  = (1.f - z) * nn + z * h;
                outH[(size_t)row * 128 + c] = o;
                mx = fmaxf(mx, o);
            }
        }
    }
    __shared__ float red[2][128];
    red[sub][c] = mx;
    __syncthreads();
    if (t < 128) atomicMax(&g_outacc[t], ford(fmaxf(red[0][t], red[1][t])));
}

// ----------------- k_final: output vector + reset counters for next run ----
__global__ void k_final(float* __restrict__ out) {
    int t = threadIdx.x;
    out[t] = funord(g_outacc[t]) + g_tf[t];
    if (t == 0) { g_cnt[0] = 0; g_cnt[1] = 0; }
}

// ---------------------------------------------------------------------------
extern "C" void kernel_launch(void* const* d_in, const int* in_sizes, int n_in,
                              void* d_out, int out_size) {
    const float* interval = (const float*)d_in[0];
    const float* co   = (const float*)d_in[1];
    const float* no_  = (const float*)d_in[2];
    const float* un   = (const float*)d_in[3];
    const float* hid  = (const float*)d_in[4];
    const int*   divided = (const int*)d_in[5];
    const float* W_ih = (const float*)d_in[6];
    const float* W_hh = (const float*)d_in[7];
    const float* b_ih = (const float*)d_in[8];
    const float* b_hh = (const float*)d_in[9];
    const float* Wq = (const float*)d_in[10];
    const float* bq = (const float*)d_in[11];
    const float* Wk = (const float*)d_in[12];
    const float* bk = (const float*)d_in[13];
    const float* Wv = (const float*)d_in[14];
    const float* bv = (const float*)d_in[15];
    const float* Wt = (const float*)d_in[16];
    const float* bt = (const float*)d_in[17];
    float* out  = (float*)d_out;
    float* outH = out + HD;   // h_new region: [12288, 128] after the 128-vec

    // side stream + fork/join events (created once; identical work every call)
    static cudaStream_t s2 = nullptr;
    static cudaEvent_t e0 = nullptr, e1 = nullptr, e2 = nullptr;
    if (s2 == nullptr) {
        cudaStreamCreateWithFlags(&s2, cudaStreamNonBlocking);
        cudaEventCreateWithFlags(&e0, cudaEventDisableTiming);
        cudaEventCreateWithFlags(&e1, cudaEventDisableTiming);
        cudaEventCreateWithFlags(&e2, cudaEventDisableTiming);
    }

    cudaFuncSetAttribute(k_gemm_g,   cudaFuncAttributeMaxDynamicSharedMemorySize, GEMM_SMEM);
    cudaFuncSetAttribute(k_gemm_qkv, cudaFuncAttributeMaxDynamicSharedMemorySize, GEMM_SMEM);
    cudaFuncSetAttribute(k_flash,    cudaFuncAttributeMaxDynamicSharedMemorySize, FLASH_SMEM);

    // fork: side stream zeroes outH while main stream compacts/gathers
    cudaEventRecord(e0, 0);
    cudaStreamWaitEvent(s2, e0, 0);
    k_zero<<<768, 512, 0, s2>>>(outH);

    k_initA<<<24, 512>>>(interval, Wt, bt, divided);
    k_gather<<<CN / 2, 256>>>(co, no_, un, hid);
    cudaEventRecord(e1, 0);

    // side stream: GI/GH GEMM overlaps with qkv GEMM + flash on main stream
    cudaStreamWaitEvent(s2, e1, 0);
    k_gemm_g<<<dim3(192, 12), 256, GEMM_SMEM, s2>>>(W_ih, W_hh, b_ih, b_hh);
    cudaEventRecord(e2, s2);

    k_gemm_qkv<<<dim3(192, 4), 256, GEMM_SMEM>>>(Wq, bq, Wk, bk, Wv, bv);
    k_flash<<<(CN / 64) * KSPLIT, 128, FLASH_SMEM>>>();

    // join: post needs flash (main), GI/GH + zero (side)
    cudaStreamWaitEvent(0, e2, 0);
    k_post<<<2 * (CN / 8), 256>>>(hid, outH);
    k_final<<<1, 128>>>(out);
}

// round 12
// speedup vs baseline: 5.9635x; 1.0632x over previous
#include <cuda_runtime.h>
#include <cuda_fp16.h>
#include <float.h>
#include <math.h>

#define CN 12288          // CODE_NUM
#define GD 128            // GRAPH
#define HD 128            // HIDDEN
#define AT 64             // ATT
#define KSPLIT 4

// ----------------- scratch (device globals; no allocation allowed) ---------
__device__ float g_Xq[CN * GD];     // gathered query-source rows (m23)
__device__ float g_Xc[CN * GD];     // gathered co_embeddings rows (m23)
__device__ float g_X1[CN * GD];     // gathered co_embeddings rows (m1)
__device__ float g_H1[CN * HD];     // gathered hidden rows (m1)
__device__ float g_GI[CN * 3 * HD]; // x @ W_ih^T + b_ih
__device__ float g_GH[CN * 3 * HD]; // h @ W_hh^T + b_hh
__device__ __half g_Qh[CN * AT];    // Q * 0.125*log2e, fp16 (tail zero)
__device__ __half g_Kh[CN * AT];    // K, fp16  (tail zero)
__device__ __half g_VT[HD * CN];    // V transposed [d][slot], fp16 (tail zero)
__device__ float g_O3[KSPLIT * CN * HD];  // per-split O partials
__device__ float g_L3[KSPLIT * CN];       // per-split l partials
__device__ int   g_idx1[CN];
__device__ int   g_idx23[CN];       // row | (m2 << 30)
__device__ int   g_cnt[2] = {0, 0}; // [0]=n1, [1]=n23 (reset by k_final)
__device__ unsigned g_outacc[HD];   // ordered-uint float max accumulator
__device__ float g_tf[HD];          // time features

__device__ __forceinline__ unsigned ford(float f) {
    unsigned u = __float_as_uint(f);
    return (u & 0x80000000u) ? ~u : (u | 0x80000000u);
}
__device__ __forceinline__ float funord(unsigned u) {
    return (u & 0x80000000u) ? __uint_as_float(u ^ 0x80000000u)
                             : __uint_as_float(~u);
}

// round-to-nearest tf32 (for MMA operand staging)
__device__ __forceinline__ float tf32r(float x) {
    unsigned u;
    asm("cvt.rna.tf32.f32 %0, %1;" : "=r"(u) : "f"(x));
    return __uint_as_float(u);
}

// m16n8k8 tf32 MMA, fp32 accumulate (projection GEMMs)
__device__ __forceinline__ void mma_tf32(float* c, const unsigned* a,
                                         unsigned b0, unsigned b1) {
    asm volatile(
        "mma.sync.aligned.m16n8k8.row.col.f32.tf32.tf32.f32 "
        "{%0,%1,%2,%3}, {%4,%5,%6,%7}, {%8,%9}, {%0,%1,%2,%3};"
        : "+f"(c[0]), "+f"(c[1]), "+f"(c[2]), "+f"(c[3])
        : "r"(a[0]), "r"(a[1]), "r"(a[2]), "r"(a[3]), "r"(b0), "r"(b1));
}

// m16n8k16 fp16 MMA, fp32 accumulate (flash)
__device__ __forceinline__ void mma_f16(float* c, const unsigned* a,
                                        unsigned b0, unsigned b1) {
    asm volatile(
        "mma.sync.aligned.m16n8k16.row.col.f32.f16.f16.f32 "
        "{%0,%1,%2,%3}, {%4,%5,%6,%7}, {%8,%9}, {%0,%1,%2,%3};"
        : "+f"(c[0]), "+f"(c[1]), "+f"(c[2]), "+f"(c[3])
        : "r"(a[0]), "r"(a[1]), "r"(a[2]), "r"(a[3]), "r"(b0), "r"(b1));
}

// ldmatrix x4 (native order; our smem tiles already match B-fragment layout)
__device__ __forceinline__ void ldsm4(unsigned& r0, unsigned& r1,
                                      unsigned& r2, unsigned& r3, unsigned addr) {
    asm volatile("ldmatrix.sync.aligned.m8n8.x4.shared.b16 {%0,%1,%2,%3}, [%4];"
                 : "=r"(r0), "=r"(r1), "=r"(r2), "=r"(r3) : "r"(addr));
}

__device__ __forceinline__ unsigned pack_h2(float a, float b) {
    __half2 h = __floats2half2_rn(a, b);
    return *reinterpret_cast<unsigned*>(&h);
}

// raw exp2 (log2e is pre-folded into Q): 1 MUFU, no multiply
__device__ __forceinline__ float ex2(float x) {
    float r;
    asm("ex2.approx.f32 %0, %1;" : "=f"(r) : "f"(x));
    return r;
}

// 16B global->shared async copy
__device__ __forceinline__ void cp16(unsigned dst, const void* src) {
    asm volatile("cp.async.cg.shared.global [%0], [%1], 16;"
                 :: "r"(dst), "l"(src));
}

// ----------------- k_zero: zero h_new region (side stream) -----------------
__global__ void k_zero(float* __restrict__ outH) {
    int i = blockIdx.x * 512 + threadIdx.x;            // 768*512 float4
    reinterpret_cast<float4*>(outH)[i] = make_float4(0.f, 0.f, 0.f, 0.f);
}

// ----------------- k_initA: accumulators, tf, compact ----------------------
__global__ void k_initA(const float* __restrict__ interval,
                        const float* __restrict__ Wt, const float* __restrict__ bt,
                        const int* __restrict__ divided) {
    if (blockIdx.x == 0) {
        int t = threadIdx.x;
        if (t < HD) {
            float xt = 1.0f / logf(interval[0] + 2.7182818284590452f);
            g_tf[t] = tanhf(xt * Wt[t] + bt[t]);
            g_outacc[t] = ford(-FLT_MAX);
        }
    }
    int row = blockIdx.x * 512 + threadIdx.x;          // 24*512 = 12288
    int d0 = divided[row * 3 + 0];
    int d1 = divided[row * 3 + 1];
    int d2 = divided[row * 3 + 2];
    if (d0 > 0) {
        int pos = atomicAdd(&g_cnt[0], 1);
        g_idx1[pos] = row;
    }
    if (d1 > 0 || d2 > 0) {
        int pos = atomicAdd(&g_cnt[1], 1);
        g_idx23[pos] = row | ((d1 > 0) ? (1 << 30) : 0);
    }
}

// ----------------- k_gather23: m23 rows (main stream) ----------------------
__global__ void k_gather23(const float* __restrict__ co, const float* __restrict__ no_,
                           const float* __restrict__ un) {
    int s = blockIdx.x * 2 + (threadIdx.x >> 7);
    int lane = threadIdx.x & 127;
    if (s < g_cnt[1]) {
        int e = g_idx23[s];
        int row = e & 0x3FFFFFFF;
        const float* src = (e & (1 << 30)) ? no_ : un;
        g_Xq[s * GD + lane] = src[row * GD + lane];
        g_Xc[s * GD + lane] = co[row * GD + lane];
    }
}

// ----------------- k_gather1: m1 rows (side stream) ------------------------
__global__ void k_gather1(const float* __restrict__ co, const float* __restrict__ hid) {
    int s = blockIdx.x * 2 + (threadIdx.x >> 7);
    int lane = threadIdx.x & 127;
    if (s < g_cnt[0]) {
        int row = g_idx1[s];
        g_X1[s * GD + lane] = co[row * GD + lane];
        g_H1[s * HD + lane] = hid[row * HD + lane];
    }
}

// ----------------- shared GEMM core: c[4][4] = A[64,128] @ W[64,128]^T -----
#define GEMM_SMEM (2 * 64 * 132 * 4)
__device__ __forceinline__ void gemm_core(const float* __restrict__ A,
                                          const float* __restrict__ W,
                                          int M, int row0, int col0,
                                          float* sm, float c[4][4]) {
    float* As = sm;              // [64][132]
    float* Ws = sm + 64 * 132;   // [64][132]
    int t = threadIdx.x;
    for (int i4 = t; i4 < 64 * 32; i4 += 256) {
        int r = i4 >> 5, k4 = i4 & 31;
        float4 v = make_float4(0.f, 0.f, 0.f, 0.f);
        if (row0 + r < M)
            v = reinterpret_cast<const float4*>(A + (size_t)(row0 + r) * 128)[k4];
        v.x = tf32r(v.x); v.y = tf32r(v.y); v.z = tf32r(v.z); v.w = tf32r(v.w);
        *reinterpret_cast<float4*>(As + r * 132 + k4 * 4) = v;
    }
    for (int i4 = t; i4 < 64 * 32; i4 += 256) {
        int cc = i4 >> 5, k4 = i4 & 31;
        float4 v = reinterpret_cast<const float4*>(W + (size_t)(col0 + cc) * 128)[k4];
        v.x = tf32r(v.x); v.y = tf32r(v.y); v.z = tf32r(v.z); v.w = tf32r(v.w);
        *reinterpret_cast<float4*>(Ws + cc * 132 + k4 * 4) = v;
    }
    __syncthreads();
    int w = t >> 5, lane = t & 31;
    int g = lane >> 2, tid = lane & 3;
    int mw = w >> 1, nw = w & 1;
#pragma unroll
    for (int nt = 0; nt < 4; nt++)
#pragma unroll
        for (int i = 0; i < 4; i++) c[nt][i] = 0.f;
    const float* r0p = As + (16 * mw + g) * 132;
    const float* r8p = r0p + 8 * 132;
#pragma unroll
    for (int ks = 0; ks < 16; ks++) {
        unsigned a[4];
        a[0] = __float_as_uint(r0p[8 * ks + tid]);
        a[1] = __float_as_uint(r8p[8 * ks + tid]);
        a[2] = __float_as_uint(r0p[8 * ks + tid + 4]);
        a[3] = __float_as_uint(r8p[8 * ks + tid + 4]);
#pragma unroll
        for (int nt = 0; nt < 4; nt++) {
            const float* kr = Ws + (nw * 32 + 8 * nt + g) * 132;
            unsigned b0 = __float_as_uint(kr[8 * ks + tid]);
            unsigned b1 = __float_as_uint(kr[8 * ks + tid + 4]);
            mma_tf32(c[nt], a, b0, b1);
        }
    }
}

// GI/GH: y 0..5 -> GI col y; y 6..11 -> GH col y-6  (side stream)
__global__ void __launch_bounds__(256, 2) k_gemm_g(
        const float* __restrict__ Wih, const float* __restrict__ Whh,
        const float* __restrict__ bih, const float* __restrict__ bhh) {
    int y = blockIdx.y;
    const float* A = (y < 6) ? g_X1 : g_H1;
    const float* W = (y < 6) ? Wih : Whh;
    const float* bias = (y < 6) ? bih : bhh;
    float* C = (y < 6) ? g_GI : g_GH;
    int M = g_cnt[0];
    int col0 = (y % 6) * 64;
    int row0 = blockIdx.x * 64;
    if (row0 >= M) return;
    extern __shared__ float sm[];
    float c[4][4];
    gemm_core(A, W, M, row0, col0, sm, c);
    int t = threadIdx.x, w = t >> 5, lane = t & 31;
    int g = lane >> 2, tid = lane & 3;
    int mw = w >> 1, nw = w & 1;
    int ra = row0 + 16 * mw + g, rb = ra + 8;
#pragma unroll
    for (int nt = 0; nt < 4; nt++) {
        int cb = col0 + nw * 32 + 8 * nt + 2 * tid;
        float2 bz = *reinterpret_cast<const float2*>(bias + cb);
        if (ra < M)
            *reinterpret_cast<float2*>(C + (size_t)ra * 384 + cb) =
                make_float2(c[nt][0] + bz.x, c[nt][1] + bz.y);
        if (rb < M)
            *reinterpret_cast<float2*>(C + (size_t)rb * 384 + cb) =
                make_float2(c[nt][2] + bz.x, c[nt][3] + bz.y);
    }
}

// QKV: y=0 Q (x 0.125*log2e), y=1 K, y=2,3 V halves (fp16 outputs)
__global__ void __launch_bounds__(256, 2) k_gemm_qkv(
        const float* __restrict__ Wq,  const float* __restrict__ bq,
        const float* __restrict__ Wk,  const float* __restrict__ bk,
        const float* __restrict__ Wv,  const float* __restrict__ bv) {
    int y = blockIdx.y;
    const float *A, *W, *bias; int col0;
    if (y == 0)      { A = g_Xq; W = Wq; bias = bq; col0 = 0; }
    else if (y == 1) { A = g_Xc; W = Wk; bias = bk; col0 = 0; }
    else             { A = g_Xc; W = Wv; bias = bv; col0 = (y - 2) * 64; }
    int M = g_cnt[1];
    int row0 = blockIdx.x * 64;
    if (row0 >= M) return;
    extern __shared__ float sm[];
    float c[4][4];
    gemm_core(A, W, M, row0, col0, sm, c);
    int t = threadIdx.x, w = t >> 5, lane = t & 31;
    int g = lane >> 2, tid = lane & 3;
    int mw = w >> 1, nw = w & 1;
    int ra = row0 + 16 * mw + g, rb = ra + 8;
    if (y <= 1) {
        __half* dst = (y == 0) ? g_Qh : g_Kh;
        float s = (y == 0) ? 0.18033688011112042f : 1.0f;   // 0.125 * log2(e)
#pragma unroll
        for (int nt = 0; nt < 4; nt++) {
            int cb = nw * 32 + 8 * nt + 2 * tid;
            float2 bz = *reinterpret_cast<const float2*>(bias + cb);
            if (ra < M) {
                __half2 h = __floats2half2_rn((c[nt][0] + bz.x) * s, (c[nt][1] + bz.y) * s);
                *reinterpret_cast<__half2*>(dst + (size_t)ra * 64 + cb) = h;
            }
            if (rb < M) {
                __half2 h = __floats2half2_rn((c[nt][2] + bz.x) * s, (c[nt][3] + bz.y) * s);
                *reinterpret_cast<__half2*>(dst + (size_t)rb * 64 + cb) = h;
            }
        }
    } else {
#pragma unroll
        for (int nt = 0; nt < 4; nt++) {
            int cb = col0 + nw * 32 + 8 * nt + 2 * tid;
            float2 bz = *reinterpret_cast<const float2*>(bias + cb);
            if (ra < M) {
                g_VT[(size_t)cb * CN + ra]       = __float2half(c[nt][0] + bz.x);
                g_VT[(size_t)(cb + 1) * CN + ra] = __float2half(c[nt][1] + bz.y);
            }
            if (rb < M) {
                g_VT[(size_t)cb * CN + rb]       = __float2half(c[nt][2] + bz.x);
                g_VT[(size_t)(cb + 1) * CN + rb] = __float2half(c[nt][3] + bz.y);
            }
        }
    }
}

// ----------------- k_flash: fp16 MMA + ldmatrix + cp.async, no masking -----
// Tail keys: K rows = 0 -> S' = 0 -> ex2 = 1 exactly; V rows = 0 so O is
// unaffected; l over-counts by exactly (#invalid keys), subtracted in epilogue.
#define FLASH_SMEM ((3 * 64 * 72 + 2 * 128 * 72) * 2)
__global__ void __launch_bounds__(128, 3) k_flash() {
    int n23 = g_cnt[1];
    int qb = blockIdx.x / KSPLIT;
    int sp = blockIdx.x % KSPLIT;
    int q0 = qb * 64;
    if (q0 >= n23) return;
    extern __shared__ __half smh[];
    __half* Qs = smh;                              // [64][72]
    int t = threadIdx.x;
    int w = t >> 5, lane = t & 31;
    int g = lane >> 2, tid = lane & 3;
    unsigned lofs = (unsigned)(((lane & 7) * 72 + 8 * (lane >> 3)) * 2);

    int nkb = (n23 + 63) >> 6;
    int chunk = (nkb + KSPLIT - 1) / KSPLIT;
    int kb0 = sp * chunk;
    int kb1 = min(kb0 + chunk, nkb);

    // issue async loads for first K/V tile (stage 0) before staging Q
    {
        int k0 = kb0 << 6;
        __half* Kst = smh + 64 * 72;
        __half* Vst = smh + 3 * 64 * 72;
        for (int i = t; i < 64 * 8; i += 128) {
            int r = i >> 3, c8 = i & 7;
            cp16((unsigned)__cvta_generic_to_shared(Kst + r * 72 + 8 * c8),
                 g_Kh + (size_t)(k0 + r) * AT + 8 * c8);
        }
        for (int i = t; i < 128 * 8; i += 128) {
            int d = i >> 3, j8 = i & 7;
            cp16((unsigned)__cvta_generic_to_shared(Vst + d * 72 + 8 * j8),
                 g_VT + (size_t)d * CN + k0 + 8 * j8);
        }
        asm volatile("cp.async.commit_group;");
    }
    // stage Q tile (overlaps with the async loads above)
    for (int i = t; i < 64 * 8; i += 128) {
        int r = i >> 3, c8 = i & 7;
        *reinterpret_cast<uint4*>(Qs + r * 72 + 8 * c8) =
            *reinterpret_cast<const uint4*>(g_Qh + (size_t)(q0 + r) * AT + 8 * c8);
    }
    __syncthreads();
    // preload Q A-fragments (4 k-chunks of 16)
    unsigned qa[4][4];
    {
        const __half* r0 = Qs + (16 * w + g) * 72;
        const __half* r8 = Qs + (16 * w + g + 8) * 72;
#pragma unroll
        for (int ks = 0; ks < 4; ks++) {
            qa[ks][0] = *reinterpret_cast<const unsigned*>(r0 + 16 * ks + 2 * tid);
            qa[ks][1] = *reinterpret_cast<const unsigned*>(r8 + 16 * ks + 2 * tid);
            qa[ks][2] = *reinterpret_cast<const unsigned*>(r0 + 16 * ks + 2 * tid + 8);
            qa[ks][3] = *reinterpret_cast<const unsigned*>(r8 + 16 * ks + 2 * tid + 8);
        }
    }
    float o[16][4];
#pragma unroll
    for (int nt = 0; nt < 16; nt++)
#pragma unroll
        for (int i = 0; i < 4; i++) o[nt][i] = 0.f;
    float l0 = 0.f, l1 = 0.f;

    for (int kb = kb0; kb < kb1; kb++) {
        int st = (kb - kb0) & 1;
        bool has_next = (kb + 1 < kb1);
        if (has_next) {
            int k0n = (kb + 1) << 6;
            int sn = st ^ 1;
            __half* Kst = smh + (1 + sn) * 64 * 72;
            __half* Vst = smh + 3 * 64 * 72 + sn * 128 * 72;
            for (int i = t; i < 64 * 8; i += 128) {
                int r = i >> 3, c8 = i & 7;
                cp16((unsigned)__cvta_generic_to_shared(Kst + r * 72 + 8 * c8),
                     g_Kh + (size_t)(k0n + r) * AT + 8 * c8);
            }
            for (int i = t; i < 128 * 8; i += 128) {
                int d = i >> 3, j8 = i & 7;
                cp16((unsigned)__cvta_generic_to_shared(Vst + d * 72 + 8 * j8),
                     g_VT + (size_t)d * CN + k0n + 8 * j8);
            }
            asm volatile("cp.async.commit_group;");
            asm volatile("cp.async.wait_group 1;");
        } else {
            asm volatile("cp.async.wait_group 0;");
        }
        __syncthreads();
        unsigned KsA = (unsigned)__cvta_generic_to_shared(smh + (1 + st) * 64 * 72) + lofs;
        unsigned VtA = (unsigned)__cvta_generic_to_shared(smh + 3 * 64 * 72 + st * 128 * 72) + lofs;
        // S = Q K^T : 8 key-tiles, B-fragments via 2 ldmatrix.x4 each
        float c[8][4];
#pragma unroll
        for (int nt = 0; nt < 8; nt++)
#pragma unroll
            for (int i = 0; i < 4; i++) c[nt][i] = 0.f;
#pragma unroll
        for (int nt = 0; nt < 8; nt++) {
            unsigned base = KsA + nt * (8 * 72 * 2);
            unsigned b0, b1, b2, b3;
            ldsm4(b0, b1, b2, b3, base);
            mma_f16(c[nt], qa[0], b0, b1);
            mma_f16(c[nt], qa[1], b2, b3);
            ldsm4(b0, b1, b2, b3, base + 64);
            mma_f16(c[nt], qa[2], b0, b1);
            mma_f16(c[nt], qa[3], b2, b3);
        }
        // P = 2^S' (log2e pre-folded), unmasked; invalid keys give exactly 1
        unsigned pa[4][4];
#pragma unroll
        for (int nt = 0; nt < 8; nt++) {
            float p0 = ex2(c[nt][0]);
            float p1 = ex2(c[nt][1]);
            float p2 = ex2(c[nt][2]);
            float p3 = ex2(c[nt][3]);
            l0 += p0 + p1;
            l1 += p2 + p3;
            int kc = nt >> 1, h = (nt & 1) * 2;
            pa[kc][h]     = pack_h2(p0, p1);
            pa[kc][h + 1] = pack_h2(p2, p3);
        }
        // O += P V : 16 d-tiles, B-fragments via 2 ldmatrix.x4 each
#pragma unroll
        for (int nt = 0; nt < 16; nt++) {
            unsigned base = VtA + nt * (8 * 72 * 2);
            unsigned b0, b1, b2, b3;
            ldsm4(b0, b1, b2, b3, base);
            mma_f16(o[nt], pa[0], b0, b1);
            mma_f16(o[nt], pa[1], b2, b3);
            ldsm4(b0, b1, b2, b3, base + 64);
            mma_f16(o[nt], pa[2], b0, b1);
            mma_f16(o[nt], pa[3], b2, b3);
        }
        __syncthreads();   // all reads of stage st done before its next refill
    }
    // ---- epilogue ----
    int inv = kb1 * 64 - max(n23, kb0 * 64);
    if (inv < 0) inv = 0;
    l0 += __shfl_xor_sync(0xffffffffu, l0, 1);
    l0 += __shfl_xor_sync(0xffffffffu, l0, 2);
    l1 += __shfl_xor_sync(0xffffffffu, l1, 1);
    l1 += __shfl_xor_sync(0xffffffffu, l1, 2);
    float* lr = reinterpret_cast<float*>(Qs);   // Qs no longer needed
    if (tid == 0) {
        lr[16 * w + g] = l0 - (float)inv;
        lr[16 * w + g + 8] = l1 - (float)inv;
    }
    __syncthreads();
    if (t < 64 && q0 + t < n23)
        g_L3[sp * CN + q0 + t] = lr[t];
    int r0 = q0 + 16 * w + g;
    int r8 = r0 + 8;
    float* base0 = g_O3 + ((size_t)sp * CN + r0) * 128 + 2 * tid;
    float* base8 = g_O3 + ((size_t)sp * CN + r8) * 128 + 2 * tid;
#pragma unroll
    for (int nt = 0; nt < 16; nt++) {
        if (r0 < n23)
            *reinterpret_cast<float2*>(base0 + 8 * nt) = make_float2(o[nt][0], o[nt][1]);
        if (r8 < n23)
            *reinterpret_cast<float2*>(base8 + 8 * nt) = make_float2(o[nt][2], o[nt][3]);
    }
}

// ----------------- k_combine: split-combine + scatter + max (main) ---------
__global__ void k_combine(float* __restrict__ outH) {
    int t = threadIdx.x;
    int c = t & 127, sub = t >> 7;
    float mx = -FLT_MAX;
    int n23 = g_cnt[1];
    int s0 = blockIdx.x * 8;
#pragma unroll
    for (int k = 0; k < 4; k++) {
        int sl = s0 + sub * 4 + k;
        if (sl < n23) {
            float lt = 0.f, ov = 0.f;
#pragma unroll
            for (int sp = 0; sp < KSPLIT; sp++) {
                lt += g_L3[sp * CN + sl];
                ov += g_O3[((size_t)sp * CN + sl) * 128 + c];
            }
            float h = tanhf(ov / lt);
            int row = g_idx23[sl] & 0x3FFFFFFF;
            outH[(size_t)row * 128 + c] = h;
            mx = fmaxf(mx, h);
        }
    }
    __shared__ float red[2][128];
    red[sub][c] = mx;
    __syncthreads();
    if (t < 128) atomicMax(&g_outacc[t], ford(fmaxf(red[0][t], red[1][t])));
}

// ----------------- k_gruc: GRU gates + scatter + max (side) ----------------
__global__ void k_gruc(const float* __restrict__ hid, float* __restrict__ outH) {
    int t = threadIdx.x;
    int c = t & 127, sub = t >> 7;
    float mx = -FLT_MAX;
    int n1 = g_cnt[0];
    int s0 = blockIdx.x * 8;
#pragma unroll
    for (int k = 0; k < 4; k++) {
        int s = s0 + sub * 4 + k;
        if (s < n1) {
            int row = g_idx1[s];
            const float* gi = g_GI + (size_t)s * 384;
            const float* gh = g_GH + (size_t)s * 384;
            float r  = 1.f / (1.f + __expf(-(gi[c] + gh[c])));
            float z  = 1.f / (1.f + __expf(-(gi[128 + c] + gh[128 + c])));
            float nn = tanhf(gi[256 + c] + r * gh[256 + c]);
            float h  = hid[(size_t)row * 128 + c];
            float o  = (1.f - z) * nn + z * h;
            outH[(size_t)row * 128 + c] = o;
            mx = fmaxf(mx, o);
        }
    }
    __shared__ float red[2][128];
    red[sub][c] = mx;
    __syncthreads();
    if (t < 128) atomicMax(&g_outacc[t], ford(fmaxf(red[0][t], red[1][t])));
}

// ----------------- k_final: output vector + reset counters for next run ----
__global__ void k_final(float* __restrict__ out) {
    int t = threadIdx.x;
    out[t] = funord(g_outacc[t]) + g_tf[t];
    if (t == 0) { g_cnt[0] = 0; g_cnt[1] = 0; }
}

// ---------------------------------------------------------------------------
extern "C" void kernel_launch(void* const* d_in, const int* in_sizes, int n_in,
                              void* d_out, int out_size) {
    const float* interval = (const float*)d_in[0];
    const float* co   = (const float*)d_in[1];
    const float* no_  = (const float*)d_in[2];
    const float* un   = (const float*)d_in[3];
    const float* hid  = (const float*)d_in[4];
    const int*   divided = (const int*)d_in[5];
    const float* W_ih = (const float*)d_in[6];
    const float* W_hh = (const float*)d_in[7];
    const float* b_ih = (const float*)d_in[8];
    const float* b_hh = (const float*)d_in[9];
    const float* Wq = (const float*)d_in[10];
    const float* bq = (const float*)d_in[11];
    const float* Wk = (const float*)d_in[12];
    const float* bk = (const float*)d_in[13];
    const float* Wv = (const float*)d_in[14];
    const float* bv = (const float*)d_in[15];
    const float* Wt = (const float*)d_in[16];
    const float* bt = (const float*)d_in[17];
    float* out  = (float*)d_out;
    float* outH = out + HD;   // h_new region: [12288, 128] after the 128-vec

    // side stream + fork/join events (created once; identical work every call)
    static cudaStream_t s2 = nullptr;
    static cudaEvent_t e0 = nullptr, e1 = nullptr, e2 = nullptr, e3 = nullptr;
    if (s2 == nullptr) {
        cudaStreamCreateWithFlags(&s2, cudaStreamNonBlocking);
        cudaEventCreateWithFlags(&e0, cudaEventDisableTiming);
        cudaEventCreateWithFlags(&e1, cudaEventDisableTiming);
        cudaEventCreateWithFlags(&e2, cudaEventDisableTiming);
        cudaEventCreateWithFlags(&e3, cudaEventDisableTiming);
    }

    cudaFuncSetAttribute(k_gemm_g,   cudaFuncAttributeMaxDynamicSharedMemorySize, GEMM_SMEM);
    cudaFuncSetAttribute(k_gemm_qkv, cudaFuncAttributeMaxDynamicSharedMemorySize, GEMM_SMEM);
    cudaFuncSetAttribute(k_flash,    cudaFuncAttributeMaxDynamicSharedMemorySize, FLASH_SMEM);

    // fork at top: side stream zeroes outH immediately
    cudaEventRecord(e0, 0);
    cudaStreamWaitEvent(s2, e0, 0);
    k_zero<<<768, 512, 0, s2>>>(outH);

    // main: compact, then m23 pipeline
    k_initA<<<24, 512>>>(interval, Wt, bt, divided);
    cudaEventRecord(e1, 0);

    // side: after compact -> m1 gather, GI/GH GEMM, GRU (all hidden by flash)
    cudaStreamWaitEvent(s2, e1, 0);
    k_gather1<<<CN / 2, 256, 0, s2>>>(co, hid);
    k_gemm_g<<<dim3(192, 12), 256, GEMM_SMEM, s2>>>(W_ih, W_hh, b_ih, b_hh);
    cudaEventRecord(e2, s2);         // zero + m1-gemm done (combine may write outH)
    k_gruc<<<CN / 8, 256, 0, s2>>>(hid, outH);
    cudaEventRecord(e3, s2);         // gruc done (final may read outacc)

    k_gather23<<<CN / 2, 256>>>(co, no_, un);
    k_gemm_qkv<<<dim3(192, 4), 256, GEMM_SMEM>>>(Wq, bq, Wk, bk, Wv, bv);
    k_flash<<<(CN / 64) * KSPLIT, 128, FLASH_SMEM>>>();

    cudaStreamWaitEvent(0, e2, 0);   // outH zero complete before combine writes
    k_combine<<<CN / 8, 256>>>(outH);
    cudaStreamWaitEvent(0, e3, 0);
    k_final<<<1, 128>>>(out);
}

// round 13
// speedup vs baseline: 6.2718x; 1.0517x over previous
#include <cuda_runtime.h>
#include <cuda_fp16.h>
#include <float.h>
#include <math.h>

#define CN 12288          // CODE_NUM
#define GD 128            // GRAPH
#define HD 128            // HIDDEN
#define AT 64             // ATT
#define KSPLIT 4

// ----------------- scratch (device globals; no allocation allowed) ---------
__device__ float g_GI[CN * 3 * HD]; // x @ W_ih^T + b_ih
__device__ float g_GH[CN * 3 * HD]; // h @ W_hh^T + b_hh
__device__ __half g_Qh[CN * AT];    // Q * 0.125*log2e, fp16 (tail zero)
__device__ __half g_Kh[CN * AT];    // K, fp16  (tail zero)
__device__ __half g_VT[HD * CN];    // V transposed [d][slot], fp16 (tail zero)
__device__ float g_O3[KSPLIT * CN * HD];  // per-split O partials
__device__ float g_L3[KSPLIT * CN];       // per-split l partials
__device__ int   g_idx1[CN];
__device__ int   g_idx23[CN];       // row | (m2 << 30)
__device__ int   g_cnt[2] = {0, 0}; // [0]=n1, [1]=n23 (reset by k_final)
__device__ unsigned g_outacc[HD];   // ordered-uint float max accumulator
__device__ float g_tf[HD];          // time features

__device__ __forceinline__ unsigned ford(float f) {
    unsigned u = __float_as_uint(f);
    return (u & 0x80000000u) ? ~u : (u | 0x80000000u);
}
__device__ __forceinline__ float funord(unsigned u) {
    return (u & 0x80000000u) ? __uint_as_float(u ^ 0x80000000u)
                             : __uint_as_float(~u);
}

// round-to-nearest tf32 (for MMA operand staging)
__device__ __forceinline__ float tf32r(float x) {
    unsigned u;
    asm("cvt.rna.tf32.f32 %0, %1;" : "=r"(u) : "f"(x));
    return __uint_as_float(u);
}

// m16n8k8 tf32 MMA, fp32 accumulate (projection GEMMs)
__device__ __forceinline__ void mma_tf32(float* c, const unsigned* a,
                                         unsigned b0, unsigned b1) {
    asm volatile(
        "mma.sync.aligned.m16n8k8.row.col.f32.tf32.tf32.f32 "
        "{%0,%1,%2,%3}, {%4,%5,%6,%7}, {%8,%9}, {%0,%1,%2,%3};"
        : "+f"(c[0]), "+f"(c[1]), "+f"(c[2]), "+f"(c[3])
        : "r"(a[0]), "r"(a[1]), "r"(a[2]), "r"(a[3]), "r"(b0), "r"(b1));
}

// m16n8k16 fp16 MMA, fp32 accumulate (flash)
__device__ __forceinline__ void mma_f16(float* c, const unsigned* a,
                                        unsigned b0, unsigned b1) {
    asm volatile(
        "mma.sync.aligned.m16n8k16.row.col.f32.f16.f16.f32 "
        "{%0,%1,%2,%3}, {%4,%5,%6,%7}, {%8,%9}, {%0,%1,%2,%3};"
        : "+f"(c[0]), "+f"(c[1]), "+f"(c[2]), "+f"(c[3])
        : "r"(a[0]), "r"(a[1]), "r"(a[2]), "r"(a[3]), "r"(b0), "r"(b1));
}

// ldmatrix x4 (native order; our smem tiles already match B-fragment layout)
__device__ __forceinline__ void ldsm4(unsigned& r0, unsigned& r1,
                                      unsigned& r2, unsigned& r3, unsigned addr) {
    asm volatile("ldmatrix.sync.aligned.m8n8.x4.shared.b16 {%0,%1,%2,%3}, [%4];"
                 : "=r"(r0), "=r"(r1), "=r"(r2), "=r"(r3) : "r"(addr));
}

__device__ __forceinline__ unsigned pack_h2(float a, float b) {
    __half2 h = __floats2half2_rn(a, b);
    return *reinterpret_cast<unsigned*>(&h);
}

// raw exp2 (log2e is pre-folded into Q): 1 MUFU, no multiply
__device__ __forceinline__ float ex2(float x) {
    float r;
    asm("ex2.approx.f32 %0, %1;" : "=f"(r) : "f"(x));
    return r;
}

// 16B global->shared async copy
__device__ __forceinline__ void cp16(unsigned dst, const void* src) {
    asm volatile("cp.async.cg.shared.global [%0], [%1], 16;"
                 :: "r"(dst), "l"(src));
}

// ----------------- k_zero: zero h_new region (side stream) -----------------
__global__ void k_zero(float* __restrict__ outH) {
    int i = blockIdx.x * 512 + threadIdx.x;            // 768*512 float4
    reinterpret_cast<float4*>(outH)[i] = make_float4(0.f, 0.f, 0.f, 0.f);
}

// ----------------- k_initA: accumulators, tf, compact ----------------------
__global__ void k_initA(const float* __restrict__ interval,
                        const float* __restrict__ Wt, const float* __restrict__ bt,
                        const int* __restrict__ divided) {
    if (blockIdx.x == 0) {
        int t = threadIdx.x;
        if (t < HD) {
            float xt = 1.0f / logf(interval[0] + 2.7182818284590452f);
            g_tf[t] = tanhf(xt * Wt[t] + bt[t]);
            g_outacc[t] = ford(-FLT_MAX);
        }
    }
    int row = blockIdx.x * 512 + threadIdx.x;          // 24*512 = 12288
    int d0 = divided[row * 3 + 0];
    int d1 = divided[row * 3 + 1];
    int d2 = divided[row * 3 + 2];
    if (d0 > 0) {
        int pos = atomicAdd(&g_cnt[0], 1);
        g_idx1[pos] = row;
    }
    if (d1 > 0 || d2 > 0) {
        int pos = atomicAdd(&g_cnt[1], 1);
        g_idx23[pos] = row | ((d1 > 0) ? (1 << 30) : 0);
    }
}

// ----------------- shared GEMM mma part (after smem staging) ---------------
#define GEMM_SMEM (2 * 64 * 132 * 4)
__device__ __forceinline__ void gemm_mma(const float* sm, float c[4][4]) {
    const float* As = sm;              // [64][132]
    const float* Ws = sm + 64 * 132;   // [64][132]
    int t = threadIdx.x;
    int w = t >> 5, lane = t & 31;
    int g = lane >> 2, tid = lane & 3;
    int mw = w >> 1, nw = w & 1;
#pragma unroll
    for (int nt = 0; nt < 4; nt++)
#pragma unroll
        for (int i = 0; i < 4; i++) c[nt][i] = 0.f;
    const float* r0p = As + (16 * mw + g) * 132;
    const float* r8p = r0p + 8 * 132;
#pragma unroll
    for (int ks = 0; ks < 16; ks++) {
        unsigned a[4];
        a[0] = __float_as_uint(r0p[8 * ks + tid]);
        a[1] = __float_as_uint(r8p[8 * ks + tid]);
        a[2] = __float_as_uint(r0p[8 * ks + tid + 4]);
        a[3] = __float_as_uint(r8p[8 * ks + tid + 4]);
#pragma unroll
        for (int nt = 0; nt < 4; nt++) {
            const float* kr = Ws + (nw * 32 + 8 * nt + g) * 132;
            unsigned b0 = __float_as_uint(kr[8 * ks + tid]);
            unsigned b1 = __float_as_uint(kr[8 * ks + tid + 4]);
            mma_tf32(c[nt], a, b0, b1);
        }
    }
}

// W staging helper (direct, tf32-rounded)
__device__ __forceinline__ void stage_W(float* Ws, const float* __restrict__ W,
                                        int col0) {
    int t = threadIdx.x;
    for (int i4 = t; i4 < 64 * 32; i4 += 256) {
        int cc = i4 >> 5, k4 = i4 & 31;
        float4 v = reinterpret_cast<const float4*>(W + (size_t)(col0 + cc) * 128)[k4];
        v.x = tf32r(v.x); v.y = tf32r(v.y); v.z = tf32r(v.z); v.w = tf32r(v.w);
        *reinterpret_cast<float4*>(Ws + cc * 132 + k4 * 4) = v;
    }
}

// GI/GH with fused m1 gather: y 0..5 -> GI (A=co[idx1]); y 6..11 -> GH (A=hid[idx1])
__global__ void __launch_bounds__(256, 2) k_gemm_g(
        const float* __restrict__ co,  const float* __restrict__ hid,
        const float* __restrict__ Wih, const float* __restrict__ Whh,
        const float* __restrict__ bih, const float* __restrict__ bhh) {
    int y = blockIdx.y;
    const float* A = (y < 6) ? co : hid;
    const float* W = (y < 6) ? Wih : Whh;
    const float* bias = (y < 6) ? bih : bhh;
    float* C = (y < 6) ? g_GI : g_GH;
    int M = g_cnt[0];
    int col0 = (y % 6) * 64;
    int row0 = blockIdx.x * 64;
    if (row0 >= M) return;
    extern __shared__ float sm[];
    int t = threadIdx.x;
    for (int i4 = t; i4 < 64 * 32; i4 += 256) {
        int r = i4 >> 5, k4 = i4 & 31;
        float4 v = make_float4(0.f, 0.f, 0.f, 0.f);
        int s = row0 + r;
        if (s < M) {
            int row = g_idx1[s];
            v = reinterpret_cast<const float4*>(A + (size_t)row * 128)[k4];
        }
        v.x = tf32r(v.x); v.y = tf32r(v.y); v.z = tf32r(v.z); v.w = tf32r(v.w);
        *reinterpret_cast<float4*>(sm + r * 132 + k4 * 4) = v;
    }
    stage_W(sm + 64 * 132, W, col0);
    __syncthreads();
    float c[4][4];
    gemm_mma(sm, c);
    int w = t >> 5, lane = t & 31;
    int g = lane >> 2, tid = lane & 3;
    int mw = w >> 1, nw = w & 1;
    int ra = row0 + 16 * mw + g, rb = ra + 8;
#pragma unroll
    for (int nt = 0; nt < 4; nt++) {
        int cb = col0 + nw * 32 + 8 * nt + 2 * tid;
        float2 bz = *reinterpret_cast<const float2*>(bias + cb);
        if (ra < M)
            *reinterpret_cast<float2*>(C + (size_t)ra * 384 + cb) =
                make_float2(c[nt][0] + bz.x, c[nt][1] + bz.y);
        if (rb < M)
            *reinterpret_cast<float2*>(C + (size_t)rb * 384 + cb) =
                make_float2(c[nt][2] + bz.x, c[nt][3] + bz.y);
    }
}

// QKV with fused m23 gather: y=0 Q (A = no_/un per m2 bit, x 0.125*log2e),
// y=1 K (A=co), y=2,3 V halves (A=co; fp16 transposed output)
__global__ void __launch_bounds__(256, 2) k_gemm_qkv(
        const float* __restrict__ co,  const float* __restrict__ no_,
        const float* __restrict__ un,
        const float* __restrict__ Wq,  const float* __restrict__ bq,
        const float* __restrict__ Wk,  const float* __restrict__ bk,
        const float* __restrict__ Wv,  const float* __restrict__ bv) {
    int y = blockIdx.y;
    const float *W, *bias; int col0;
    if (y == 0)      { W = Wq; bias = bq; col0 = 0; }
    else if (y == 1) { W = Wk; bias = bk; col0 = 0; }
    else             { W = Wv; bias = bv; col0 = (y - 2) * 64; }
    int M = g_cnt[1];
    int row0 = blockIdx.x * 64;
    if (row0 >= M) return;
    extern __shared__ float sm[];
    int t = threadIdx.x;
    for (int i4 = t; i4 < 64 * 32; i4 += 256) {
        int r = i4 >> 5, k4 = i4 & 31;
        float4 v = make_float4(0.f, 0.f, 0.f, 0.f);
        int s = row0 + r;
        if (s < M) {
            int e = g_idx23[s];
            int row = e & 0x3FFFFFFF;
            const float* A = (y == 0) ? ((e & (1 << 30)) ? no_ : un) : co;
            v = reinterpret_cast<const float4*>(A + (size_t)row * 128)[k4];
        }
        v.x = tf32r(v.x); v.y = tf32r(v.y); v.z = tf32r(v.z); v.w = tf32r(v.w);
        *reinterpret_cast<float4*>(sm + r * 132 + k4 * 4) = v;
    }
    stage_W(sm + 64 * 132, W, col0);
    __syncthreads();
    float c[4][4];
    gemm_mma(sm, c);
    int w = t >> 5, lane = t & 31;
    int g = lane >> 2, tid = lane & 3;
    int mw = w >> 1, nw = w & 1;
    int ra = row0 + 16 * mw + g, rb = ra + 8;
    if (y <= 1) {
        __half* dst = (y == 0) ? g_Qh : g_Kh;
        float s = (y == 0) ? 0.18033688011112042f : 1.0f;   // 0.125 * log2(e)
#pragma unroll
        for (int nt = 0; nt < 4; nt++) {
            int cb = nw * 32 + 8 * nt + 2 * tid;
            float2 bz = *reinterpret_cast<const float2*>(bias + cb);
            if (ra < M) {
                __half2 h = __floats2half2_rn((c[nt][0] + bz.x) * s, (c[nt][1] + bz.y) * s);
                *reinterpret_cast<__half2*>(dst + (size_t)ra * 64 + cb) = h;
            }
            if (rb < M) {
                __half2 h = __floats2half2_rn((c[nt][2] + bz.x) * s, (c[nt][3] + bz.y) * s);
                *reinterpret_cast<__half2*>(dst + (size_t)rb * 64 + cb) = h;
            }
        }
    } else {
#pragma unroll
        for (int nt = 0; nt < 4; nt++) {
            int cb = col0 + nw * 32 + 8 * nt + 2 * tid;
            float2 bz = *reinterpret_cast<const float2*>(bias + cb);
            if (ra < M) {
                g_VT[(size_t)cb * CN + ra]       = __float2half(c[nt][0] + bz.x);
                g_VT[(size_t)(cb + 1) * CN + ra] = __float2half(c[nt][1] + bz.y);
            }
            if (rb < M) {
                g_VT[(size_t)cb * CN + rb]       = __float2half(c[nt][2] + bz.x);
                g_VT[(size_t)(cb + 1) * CN + rb] = __float2half(c[nt][3] + bz.y);
            }
        }
    }
}

// ----------------- k_flash: fp16 MMA + ldmatrix + cp.async, no masking -----
// Tail keys: K rows = 0 -> S' = 0 -> ex2 = 1 exactly; V rows = 0 so O is
// unaffected; l over-counts by exactly (#invalid keys), subtracted in epilogue.
#define FLASH_SMEM ((3 * 64 * 72 + 2 * 128 * 72) * 2)
__global__ void __launch_bounds__(128, 3) k_flash() {
    int n23 = g_cnt[1];
    int qb = blockIdx.x / KSPLIT;
    int sp = blockIdx.x % KSPLIT;
    int q0 = qb * 64;
    if (q0 >= n23) return;
    extern __shared__ __half smh[];
    __half* Qs = smh;                              // [64][72]
    int t = threadIdx.x;
    int w = t >> 5, lane = t & 31;
    int g = lane >> 2, tid = lane & 3;
    unsigned lofs = (unsigned)(((lane & 7) * 72 + 8 * (lane >> 3)) * 2);

    int nkb = (n23 + 63) >> 6;
    int chunk = (nkb + KSPLIT - 1) / KSPLIT;
    int kb0 = sp * chunk;
    int kb1 = min(kb0 + chunk, nkb);

    // issue async loads for first K/V tile (stage 0) before staging Q
    {
        int k0 = kb0 << 6;
        __half* Kst = smh + 64 * 72;
        __half* Vst = smh + 3 * 64 * 72;
        for (int i = t; i < 64 * 8; i += 128) {
            int r = i >> 3, c8 = i & 7;
            cp16((unsigned)__cvta_generic_to_shared(Kst + r * 72 + 8 * c8),
                 g_Kh + (size_t)(k0 + r) * AT + 8 * c8);
        }
        for (int i = t; i < 128 * 8; i += 128) {
            int d = i >> 3, j8 = i & 7;
            cp16((unsigned)__cvta_generic_to_shared(Vst + d * 72 + 8 * j8),
                 g_VT + (size_t)d * CN + k0 + 8 * j8);
        }
        asm volatile("cp.async.commit_group;");
    }
    // stage Q tile (overlaps with the async loads above)
    for (int i = t; i < 64 * 8; i += 128) {
        int r = i >> 3, c8 = i & 7;
        *reinterpret_cast<uint4*>(Qs + r * 72 + 8 * c8) =
            *reinterpret_cast<const uint4*>(g_Qh + (size_t)(q0 + r) * AT + 8 * c8);
    }
    __syncthreads();
    // preload Q A-fragments (4 k-chunks of 16)
    unsigned qa[4][4];
    {
        const __half* r0 = Qs + (16 * w + g) * 72;
        const __half* r8 = Qs + (16 * w + g + 8) * 72;
#pragma unroll
        for (int ks = 0; ks < 4; ks++) {
            qa[ks][0] = *reinterpret_cast<const unsigned*>(r0 + 16 * ks + 2 * tid);
            qa[ks][1] = *reinterpret_cast<const unsigned*>(r8 + 16 * ks + 2 * tid);
            qa[ks][2] = *reinterpret_cast<const unsigned*>(r0 + 16 * ks + 2 * tid + 8);
            qa[ks][3] = *reinterpret_cast<const unsigned*>(r8 + 16 * ks + 2 * tid + 8);
        }
    }
    float o[16][4];
#pragma unroll
    for (int nt = 0; nt < 16; nt++)
#pragma unroll
        for (int i = 0; i < 4; i++) o[nt][i] = 0.f;
    float l0 = 0.f, l1 = 0.f;

    for (int kb = kb0; kb < kb1; kb++) {
        int st = (kb - kb0) & 1;
        bool has_next = (kb + 1 < kb1);
        if (has_next) {
            int k0n = (kb + 1) << 6;
            int sn = st ^ 1;
            __half* Kst = smh + (1 + sn) * 64 * 72;
            __half* Vst = smh + 3 * 64 * 72 + sn * 128 * 72;
            for (int i = t; i < 64 * 8; i += 128) {
                int r = i >> 3, c8 = i & 7;
                cp16((unsigned)__cvta_generic_to_shared(Kst + r * 72 + 8 * c8),
                     g_Kh + (size_t)(k0n + r) * AT + 8 * c8);
            }
            for (int i = t; i < 128 * 8; i += 128) {
                int d = i >> 3, j8 = i & 7;
                cp16((unsigned)__cvta_generic_to_shared(Vst + d * 72 + 8 * j8),
                     g_VT + (size_t)d * CN + k0n + 8 * j8);
            }
            asm volatile("cp.async.commit_group;");
            asm volatile("cp.async.wait_group 1;");
        } else {
            asm volatile("cp.async.wait_group 0;");
        }
        __syncthreads();
        unsigned KsA = (unsigned)__cvta_generic_to_shared(smh + (1 + st) * 64 * 72) + lofs;
        unsigned VtA = (unsigned)__cvta_generic_to_shared(smh + 3 * 64 * 72 + st * 128 * 72) + lofs;
        // S = Q K^T : 8 key-tiles, B-fragments via 2 ldmatrix.x4 each
        float c[8][4];
#pragma unroll
        for (int nt = 0; nt < 8; nt++)
#pragma unroll
            for (int i = 0; i < 4; i++) c[nt][i] = 0.f;
#pragma unroll
        for (int nt = 0; nt < 8; nt++) {
            unsigned base = KsA + nt * (8 * 72 * 2);
            unsigned b0, b1, b2, b3;
            ldsm4(b0, b1, b2, b3, base);
            mma_f16(c[nt], qa[0], b0, b1);
            mma_f16(c[nt], qa[1], b2, b3);
            ldsm4(b0, b1, b2, b3, base + 64);
            mma_f16(c[nt], qa[2], b0, b1);
            mma_f16(c[nt], qa[3], b2, b3);
        }
        // P = 2^S' (log2e pre-folded), unmasked; invalid keys give exactly 1
        unsigned pa[4][4];
#pragma unroll
        for (int nt = 0; nt < 8; nt++) {
            float p0 = ex2(c[nt][0]);
            float p1 = ex2(c[nt][1]);
            float p2 = ex2(c[nt][2]);
            float p3 = ex2(c[nt][3]);
            l0 += p0 + p1;
            l1 += p2 + p3;
            int kc = nt >> 1, h = (nt & 1) * 2;
            pa[kc][h]     = pack_h2(p0, p1);
            pa[kc][h + 1] = pack_h2(p2, p3);
        }
        // O += P V : 16 d-tiles, B-fragments via 2 ldmatrix.x4 each
#pragma unroll
        for (int nt = 0; nt < 16; nt++) {
            unsigned base = VtA + nt * (8 * 72 * 2);
            unsigned b0, b1, b2, b3;
            ldsm4(b0, b1, b2, b3, base);
            mma_f16(o[nt], pa[0], b0, b1);
            mma_f16(o[nt], pa[1], b2, b3);
            ldsm4(b0, b1, b2, b3, base + 64);
            mma_f16(o[nt], pa[2], b0, b1);
            mma_f16(o[nt], pa[3], b2, b3);
        }
        __syncthreads();   // all reads of stage st done before its next refill
    }
    // ---- epilogue ----
    int inv = kb1 * 64 - max(n23, kb0 * 64);
    if (inv < 0) inv = 0;
    l0 += __shfl_xor_sync(0xffffffffu, l0, 1);
    l0 += __shfl_xor_sync(0xffffffffu, l0, 2);
    l1 += __shfl_xor_sync(0xffffffffu, l1, 1);
    l1 += __shfl_xor_sync(0xffffffffu, l1, 2);
    float* lr = reinterpret_cast<float*>(Qs);   // Qs no longer needed
    if (tid == 0) {
        lr[16 * w + g] = l0 - (float)inv;
        lr[16 * w + g + 8] = l1 - (float)inv;
    }
    __syncthreads();
    if (t < 64 && q0 + t < n23)
        g_L3[sp * CN + q0 + t] = lr[t];
    int r0 = q0 + 16 * w + g;
    int r8 = r0 + 8;
    float* base0 = g_O3 + ((size_t)sp * CN + r0) * 128 + 2 * tid;
    float* base8 = g_O3 + ((size_t)sp * CN + r8) * 128 + 2 * tid;
#pragma unroll
    for (int nt = 0; nt < 16; nt++) {
        if (r0 < n23)
            *reinterpret_cast<float2*>(base0 + 8 * nt) = make_float2(o[nt][0], o[nt][1]);
        if (r8 < n23)
            *reinterpret_cast<float2*>(base8 + 8 * nt) = make_float2(o[nt][2], o[nt][3]);
    }
}

// ----------------- k_combine: split-combine + scatter + max (main) ---------
__global__ void k_combine(float* __restrict__ outH) {
    int t = threadIdx.x;
    int c = t & 127, sub = t >> 7;
    float mx = -FLT_MAX;
    int n23 = g_cnt[1];
    int s0 = blockIdx.x * 8;
#pragma unroll
    for (int k = 0; k < 4; k++) {
        int sl = s0 + sub * 4 + k;
        if (sl < n23) {
            float lt = 0.f, ov = 0.f;
#pragma unroll
            for (int sp = 0; sp < KSPLIT; sp++) {
                lt += g_L3[sp * CN + sl];
                ov += g_O3[((size_t)sp * CN + sl) * 128 + c];
            }
            float h = tanhf(ov / lt);
            int row = g_idx23[sl] & 0x3FFFFFFF;
            outH[(size_t)row * 128 + c] = h;
            mx = fmaxf(mx, h);
        }
    }
    __shared__ float red[2][128];
    red[sub][c] = mx;
    __syncthreads();
    if (t < 128) atomicMax(&g_outacc[t], ford(fmaxf(red[0][t], red[1][t])));
}

// ----------------- k_gruc: GRU gates + scatter + max (side) ----------------
__global__ void k_gruc(const float* __restrict__ hid, float* __restrict__ outH) {
    int t = threadIdx.x;
    int c = t & 127, sub = t >> 7;
    float mx = -FLT_MAX;
    int n1 = g_cnt[0];
    int s0 = blockIdx.x * 8;
#pragma unroll
    for (int k = 0; k < 4; k++) {
        int s = s0 + sub * 4 + k;
        if (s < n1) {
            int row = g_idx1[s];
            const float* gi = g_GI + (size_t)s * 384;
            const float* gh = g_GH + (size_t)s * 384;
            float r  = 1.f / (1.f + __expf(-(gi[c] + gh[c])));
            float z  = 1.f / (1.f + __expf(-(gi[128 + c] + gh[128 + c])));
            float nn = tanhf(gi[256 + c] + r * gh[256 + c]);
            float h  = hid[(size_t)row * 128 + c];
            float o  = (1.f - z) * nn + z * h;
            outH[(size_t)row * 128 + c] = o;
            mx = fmaxf(mx, o);
        }
    }
    __shared__ float red[2][128];
    red[sub][c] = mx;
    __syncthreads();
    if (t < 128) atomicMax(&g_outacc[t], ford(fmaxf(red[0][t], red[1][t])));
}

// ----------------- k_final: output vector + reset counters for next run ----
__global__ void k_final(float* __restrict__ out) {
    int t = threadIdx.x;
    out[t] = funord(g_outacc[t]) + g_tf[t];
    if (t == 0) { g_cnt[0] = 0; g_cnt[1] = 0; }
}

// ---------------------------------------------------------------------------
extern "C" void kernel_launch(void* const* d_in, const int* in_sizes, int n_in,
                              void* d_out, int out_size) {
    const float* interval = (const float*)d_in[0];
    const float* co   = (const float*)d_in[1];
    const float* no_  = (const float*)d_in[2];
    const float* un   = (const float*)d_in[3];
    const float* hid  = (const float*)d_in[4];
    const int*   divided = (const int*)d_in[5];
    const float* W_ih = (const float*)d_in[6];
    const float* W_hh = (const float*)d_in[7];
    const float* b_ih = (const float*)d_in[8];
    const float* b_hh = (const float*)d_in[9];
    const float* Wq = (const float*)d_in[10];
    const float* bq = (const float*)d_in[11];
    const float* Wk = (const float*)d_in[12];
    const float* bk = (const float*)d_in[13];
    const float* Wv = (const float*)d_in[14];
    const float* bv = (const float*)d_in[15];
    const float* Wt = (const float*)d_in[16];
    const float* bt = (const float*)d_in[17];
    float* out  = (float*)d_out;
    float* outH = out + HD;   // h_new region: [12288, 128] after the 128-vec

    // side stream + fork/join events (created once; identical work every call)
    static cudaStream_t s2 = nullptr;
    static cudaEvent_t e0 = nullptr, e1 = nullptr, e2 = nullptr, e3 = nullptr;
    if (s2 == nullptr) {
        cudaStreamCreateWithFlags(&s2, cudaStreamNonBlocking);
        cudaEventCreateWithFlags(&e0, cudaEventDisableTiming);
        cudaEventCreateWithFlags(&e1, cudaEventDisableTiming);
        cudaEventCreateWithFlags(&e2, cudaEventDisableTiming);
        cudaEventCreateWithFlags(&e3, cudaEventDisableTiming);
    }

    cudaFuncSetAttribute(k_gemm_g,   cudaFuncAttributeMaxDynamicSharedMemorySize, GEMM_SMEM);
    cudaFuncSetAttribute(k_gemm_qkv, cudaFuncAttributeMaxDynamicSharedMemorySize, GEMM_SMEM);
    cudaFuncSetAttribute(k_flash,    cudaFuncAttributeMaxDynamicSharedMemorySize, FLASH_SMEM);

    // fork at top: side stream zeroes outH immediately
    cudaEventRecord(e0, 0);
    cudaStreamWaitEvent(s2, e0, 0);
    k_zero<<<768, 512, 0, s2>>>(outH);

    // main: compact, then m23 pipeline (gathers fused into GEMM staging)
    k_initA<<<24, 512>>>(interval, Wt, bt, divided);
    cudaEventRecord(e1, 0);

    // side: after compact -> GI/GH GEMM (fused m1 gather), GRU
    cudaStreamWaitEvent(s2, e1, 0);
    k_gemm_g<<<dim3(192, 12), 256, GEMM_SMEM, s2>>>(co, hid, W_ih, W_hh, b_ih, b_hh);
    cudaEventRecord(e2, s2);         // zero + m1-gemm done (combine may write outH)
    k_gruc<<<CN / 8, 256, 0, s2>>>(hid, outH);
    cudaEventRecord(e3, s2);         // gruc done (final may read outacc)

    k_gemm_qkv<<<dim3(192, 4), 256, GEMM_SMEM>>>(co, no_, un,
                                                 Wq, bq, Wk, bk, Wv, bv);
    k_flash<<<(CN / 64) * KSPLIT, 128, FLASH_SMEM>>>();

    cudaStreamWaitEvent(0, e2, 0);   // outH zero complete before combine writes
    k_combine<<<CN / 8, 256>>>(outH);
    cudaStreamWaitEvent(0, e3, 0);
    k_final<<<1, 128>>>(out);
}